// round 3
// baseline (speedup 1.0000x reference)
#include <cuda_runtime.h>
#include <cuda_bf16.h>
#include <cstdint>

// ---------------------------------------------------------------------------
// ChebGcnDecoder: FC(128->512 relu) -> FC(512->110592) -> reshape (B,864,128)
//  -> 4x [ChebConv(K=3) + lrelu + repeat2] -> ChebConv -> perm -> slice 6890
//
// Layout: features stored (node, batch, channel) row-major so every GEMM is
// (n*128 x ci) @ (ci x co) row-major, propagation moves contiguous rows, and
// repeat(2,axis=1) is fused into all consumers as a node>>1 read-index.
// GEMMs run on tensor cores: bf16 hi/lo split (3x mma) ~ fp32 precision.
// ---------------------------------------------------------------------------

#define LRELU_S 0.2f

// Scratch (static __device__ arrays; no allocation allowed)
__device__ float g_T[84934656];      // [T0 | T1 | T2] regions, per-layer strided
__device__ float g_outA[14155776];   // ping-pong layer outputs
__device__ float g_outB[14155776];
__device__ float g_h1[65536];        // FC1 output 128x512
__device__ int   g_cnt[6912];
__device__ float g_dinv[6912];
__device__ int   g_off[6913];
__device__ int   g_cur[6912];
__device__ int   g_csrc[41472];
__device__ float g_cw[41472];
__device__ int   g_is64;

// ---------------------------------------------------------------------------
__device__ __forceinline__ int read_idx(const void* p, int i) {
    if (g_is64) return (int)((const long long*)p)[i];
    return ((const int*)p)[i];
}

// Detect int64 vs int32 index buffers: for LE int64 values in [0,6912) every
// odd 32-bit word is 0; genuine int32 node-id data has nonzero odd words.
__global__ void detect_kernel(const int* w, int nwords) {
    __shared__ int any;
    if (threadIdx.x == 0) any = 0;
    __syncthreads();
    int a = 0;
    for (int i = 1 + 2 * (int)threadIdx.x; i < nwords; i += 2 * blockDim.x) a |= w[i];
    if (a) atomicOr(&any, 1);
    __syncthreads();
    if (threadIdx.x == 0) g_is64 = any ? 0 : 1;
}

__global__ void zero_cnt_kernel(int n) {
    int i = blockIdx.x * blockDim.x + threadIdx.x;
    if (i < n) g_cnt[i] = 0;
}

__global__ void count_kernel(const void* edges, int e) {
    int i = blockIdx.x * blockDim.x + threadIdx.x;
    if (i < e) atomicAdd(&g_cnt[read_idx(edges, e + i)], 1);
}

__global__ void dinv_kernel(int n) {
    int i = blockIdx.x * blockDim.x + threadIdx.x;
    if (i < n) g_dinv[i] = (g_cnt[i] > 0) ? rsqrtf((float)g_cnt[i]) : 0.0f;
}

// One-block exclusive scan over up to 6912 counts -> g_off (n+1), g_cur copy.
__global__ void scan_kernel(int n) {
    __shared__ int partial[1024];
    int tid = threadIdx.x;
    int C = (n + 1023) / 1024;   // <= 7
    int start = tid * C;
    int local[8];
    int s = 0;
    for (int i = 0; i < C; i++) {
        int idx = start + i;
        int v = (idx < n) ? g_cnt[idx] : 0;
        local[i] = s;
        s += v;
    }
    partial[tid] = s;
    __syncthreads();
    for (int d = 1; d < 1024; d <<= 1) {
        int t = (tid >= d) ? partial[tid - d] : 0;
        __syncthreads();
        if (tid >= d) partial[tid] += t;
        __syncthreads();
    }
    int base = (tid > 0) ? partial[tid - 1] : 0;
    for (int i = 0; i < C; i++) {
        int idx = start + i;
        if (idx < n) {
            int o = base + local[i];
            g_off[idx] = o;
            g_cur[idx] = o;
        }
    }
    if (tid == 1023) g_off[n] = partial[1023];
}

__global__ void fill_kernel(const void* edges, int e) {
    int i = blockIdx.x * blockDim.x + threadIdx.x;
    if (i < e) {
        int s = read_idx(edges, i);
        int d = read_idx(edges, e + i);
        int p = atomicAdd(&g_cur[d], 1);
        g_csrc[p] = s;
        g_cw[p] = -g_dinv[s] * g_dinv[d];
    }
}

// out[v] = scale * sum_{in-edges} w * in[src>>shin]  - (sub ? sub[v>>shsub] : 0)
// float4 rows; R4 = B*ci/4. grid = (R4/256, n).
__global__ void prop_kernel(float4* __restrict__ out, const float4* __restrict__ in,
                            const float4* __restrict__ sub, float scale, int R4,
                            int shin, int shsub) {
    int v = blockIdx.y;
    int j = blockIdx.x * blockDim.x + threadIdx.x;
    float4 acc = make_float4(0.f, 0.f, 0.f, 0.f);
    int s = g_off[v], t = g_off[v + 1];
    for (int q = s; q < t; q++) {
        float w = g_cw[q];
        float4 x = in[(size_t)(g_csrc[q] >> shin) * R4 + j];
        acc.x += w * x.x; acc.y += w * x.y; acc.z += w * x.z; acc.w += w * x.w;
    }
    float4 r = make_float4(scale * acc.x, scale * acc.y, scale * acc.z, scale * acc.w);
    if (sub) {
        float4 u = sub[(size_t)(v >> shsub) * R4 + j];
        r.x -= u.x; r.y -= u.y; r.z -= u.z; r.w -= u.w;
    }
    out[(size_t)v * R4 + j] = r;
}

// ---------------------------------------------------------------------------
// Tensor-core GEMM (bf16 hi/lo split, fp32 accumulate; ~fp32 precision).
// C(MxN) = [A_0|A_1|A_2] (M x K, K = nblk*ci) @ W (K x N) + bias
// A_0 read through node-halving map: row m -> node v=m>>7, batch b=m&127,
//   addr A0[(((v>>shiftA)<<7)|b)*ci + off]. A_1/A_2 at A12 + (p-1)*S + m*ci.
// mode: 0 bias, 1 bias+relu, 2 bias+lrelu, 3 bias + FC2-transpose write into
// (node,batch,channel) layout (m=batch, n = node*128+channel).
// Requires M % 128 == 0. K arbitrary (zero-padded tiles).
// ---------------------------------------------------------------------------
#define GBM 128
#define GBN 64
#define GBK 32

#define MMA_BF16(c, a, b)                                                     \
    asm volatile(                                                             \
        "mma.sync.aligned.m16n8k16.row.col.f32.bf16.bf16.f32 "                \
        "{%0,%1,%2,%3}, {%4,%5,%6,%7}, {%8,%9}, {%0,%1,%2,%3};\n"             \
        : "+f"((c)[0]), "+f"((c)[1]), "+f"((c)[2]), "+f"((c)[3])              \
        : "r"((a)[0]), "r"((a)[1]), "r"((a)[2]), "r"((a)[3]),                 \
          "r"((b)[0]), "r"((b)[1]))

__device__ __forceinline__ void write_c(float v, int m, int n, int N,
                                        const float* bias, float* out, int mode) {
    if (n >= N) return;
    v += bias[n];
    if (mode == 1) v = v > 0.f ? v : 0.f;
    else if (mode == 2) v = v >= 0.f ? v : LRELU_S * v;
    if (mode == 3) out[(size_t)((n >> 7) * 128 + m) * 128 + (n & 127)] = v;
    else out[(size_t)m * (size_t)N + n] = v;
}

__global__ __launch_bounds__(256)
void gemm_mma(const float* __restrict__ A0, const float* __restrict__ A12,
              long long S, int ci_log2, int shiftA,
              const float* __restrict__ W, const float* __restrict__ bias,
              float* __restrict__ out, int M, int N, int K, int mode) {
    __shared__ __nv_bfloat16 Ah[GBM][GBK + 2], Al[GBM][GBK + 2];
    __shared__ __nv_bfloat16 Bh[GBN][GBK + 2], Bl[GBN][GBK + 2];
    int tid = threadIdx.x;
    int warp = tid >> 5, lane = tid & 31;
    int wm = warp >> 1, wn = warp & 1;        // 4 x 2 warp grid, 32x32 tiles
    int g = lane >> 2, t = lane & 3;
    int m0 = blockIdx.y * GBM, n0 = blockIdx.x * GBN;
    int ci = 1 << ci_log2;

    float acc[2][4][4];
#pragma unroll
    for (int i = 0; i < 2; i++)
#pragma unroll
        for (int j = 0; j < 4; j++)
#pragma unroll
            for (int q = 0; q < 4; q++) acc[i][j][q] = 0.f;

    for (int k0 = 0; k0 < K; k0 += GBK) {
        // Load A tile (128x32 fp32), split to bf16 hi/lo
#pragma unroll
        for (int r = 0; r < 16; r++) {
            int idx = tid + r * 256;
            int m = idx >> 5, k = idx & 31;
            int kg = k0 + k;
            float a = 0.f;
            if (kg < K) {
                int p = kg >> ci_log2;
                int off = kg & (ci - 1);
                int mg = m0 + m;
                if (p == 0) {
                    int v = mg >> 7, b = mg & 127;
                    a = A0[(size_t)(((v >> shiftA) << 7) | b) * ci + off];
                } else {
                    a = A12[(size_t)(p - 1) * S + (size_t)mg * ci + off];
                }
            }
            __nv_bfloat16 hi = __float2bfloat16(a);
            Ah[m][k] = hi;
            Al[m][k] = __float2bfloat16(a - __bfloat162float(hi));
        }
        // Load W tile (32x64 fp32) transposed into [n][k], split hi/lo
#pragma unroll
        for (int r = 0; r < 8; r++) {
            int idx = tid + r * 256;
            int k = idx >> 6, n = idx & 63;
            int kg = k0 + k;
            float w = 0.f;
            if (kg < K && n0 + n < N) w = W[(size_t)kg * N + (n0 + n)];
            __nv_bfloat16 hi = __float2bfloat16(w);
            Bh[n][k] = hi;
            Bl[n][k] = __float2bfloat16(w - __bfloat162float(hi));
        }
        __syncthreads();

#pragma unroll
        for (int kk = 0; kk < GBK; kk += 16) {
            uint32_t ah[2][4], al[2][4], bh[4][2], bl[4][2];
#pragma unroll
            for (int mt = 0; mt < 2; mt++) {
                int r0 = wm * 32 + mt * 16 + g;
                ah[mt][0] = *(const uint32_t*)&Ah[r0][kk + 2 * t];
                ah[mt][1] = *(const uint32_t*)&Ah[r0 + 8][kk + 2 * t];
                ah[mt][2] = *(const uint32_t*)&Ah[r0][kk + 2 * t + 8];
                ah[mt][3] = *(const uint32_t*)&Ah[r0 + 8][kk + 2 * t + 8];
                al[mt][0] = *(const uint32_t*)&Al[r0][kk + 2 * t];
                al[mt][1] = *(const uint32_t*)&Al[r0 + 8][kk + 2 * t];
                al[mt][2] = *(const uint32_t*)&Al[r0][kk + 2 * t + 8];
                al[mt][3] = *(const uint32_t*)&Al[r0 + 8][kk + 2 * t + 8];
            }
#pragma unroll
            for (int nt = 0; nt < 4; nt++) {
                int c0 = wn * 32 + nt * 8 + g;
                bh[nt][0] = *(const uint32_t*)&Bh[c0][kk + 2 * t];
                bh[nt][1] = *(const uint32_t*)&Bh[c0][kk + 2 * t + 8];
                bl[nt][0] = *(const uint32_t*)&Bl[c0][kk + 2 * t];
                bl[nt][1] = *(const uint32_t*)&Bl[c0][kk + 2 * t + 8];
            }
#pragma unroll
            for (int mt = 0; mt < 2; mt++)
#pragma unroll
                for (int nt = 0; nt < 4; nt++) {
                    MMA_BF16(acc[mt][nt], ah[mt], bh[nt]);
                    MMA_BF16(acc[mt][nt], ah[mt], bl[nt]);
                    MMA_BF16(acc[mt][nt], al[mt], bh[nt]);
                }
        }
        __syncthreads();
    }

#pragma unroll
    for (int mt = 0; mt < 2; mt++)
#pragma unroll
        for (int nt = 0; nt < 4; nt++) {
            int mrow = m0 + wm * 32 + mt * 16 + g;
            int ncol = n0 + wn * 32 + nt * 8 + 2 * t;
            write_c(acc[mt][nt][0], mrow,     ncol,     N, bias, out, mode);
            write_c(acc[mt][nt][1], mrow,     ncol + 1, N, bias, out, mode);
            write_c(acc[mt][nt][2], mrow + 8, ncol,     N, bias, out, mode);
            write_c(acc[mt][nt][3], mrow + 8, ncol + 1, N, bias, out, mode);
        }
}

// out[b][u][k] = h[(perm[u]*128 + b)*3 + k], u < 6890
__global__ void final_kernel(float* __restrict__ out, const float* __restrict__ h,
                             const void* __restrict__ perm) {
    int i = blockIdx.x * blockDim.x + threadIdx.x;
    const int TOT = 128 * 6890 * 3;
    if (i < TOT) {
        int b = i / (6890 * 3);
        int r = i - b * (6890 * 3);
        int u = r / 3;
        int k = r - u * 3;
        int v = read_idx(perm, u);
        out[i] = h[(size_t)(v * 128 + b) * 3 + k];
    }
}

// ---------------------------------------------------------------------------
extern "C" void kernel_launch(void* const* d_in, const int* in_sizes, int n_in,
                              void* d_out, int out_size) {
    const float* x   = (const float*)d_in[0];
    const float* fw1 = (const float*)d_in[1];
    const float* fb1 = (const float*)d_in[2];
    const float* fw2 = (const float*)d_in[3];
    const float* fb2 = (const float*)d_in[4];
    const float* W[5];
    const float* bb[5];
    for (int i = 0; i < 5; i++) {
        W[i]  = (const float*)d_in[5 + 2 * i];
        bb[i] = (const float*)d_in[6 + 2 * i];
    }
    const void* edges[4];
    for (int i = 0; i < 4; i++) edges[i] = d_in[15 + i];
    const void* perm = d_in[19];
    float* out = (float*)d_out;

    float *T, *OA, *OB, *H1;
    cudaGetSymbolAddress((void**)&T,  g_T);
    cudaGetSymbolAddress((void**)&OA, g_outA);
    cudaGetSymbolAddress((void**)&OB, g_outB);
    cudaGetSymbolAddress((void**)&H1, g_h1);

    // dtype sniff for index arrays
    detect_kernel<<<1, 256>>>((const int*)edges[0], 5184);

    // FC1: (128x128)@(128x512)+b, relu
    gemm_mma<<<dim3(512 / GBN, 1), 256>>>(x, nullptr, 0, 7, 0, fw1, fb1, H1,
                                          128, 512, 128, 1);
    // FC2: (128x512)@(512x110592)+b, transposed write -> T0 region as (v,b,c)
    gemm_mma<<<dim3(110592 / GBN, 1), 256>>>(H1, nullptr, 0, 9, 0, fw2, fb2, T,
                                             128, 110592, 512, 3);

    const int ns[5]   = {864, 1728, 3456, 6912, 6912};
    const int cis[5]  = {128, 128, 64, 32, 16};
    const int cil2[5] = {7, 7, 6, 5, 4};
    const int cos_[5] = {128, 64, 32, 16, 3};
    const int eidx[5] = {0, 1, 2, 3, 3};
    const int egn[4]  = {864, 1728, 3456, 6912};

    float* prevOut = T;   // layer0 reads T0 written by FC2
    for (int l = 0; l < 5; l++) {
        int n  = ns[l];
        int ci = cis[l];
        int co = cos_[l];
        int R  = 128 * ci;
        int R4 = R / 4;
        size_t Ssz = (size_t)n * R;
        int M = n * 128;
        int K = 3 * ci;
        int sh = (l == 0 || l == 4) ? 0 : 1;  // repeat(2) fused as node>>1

        if (l < 4) {  // layer 4 reuses layer 3's CSR (same edge set)
            const void* eg = edges[eidx[l]];
            int e = 6 * egn[eidx[l]];
            zero_cnt_kernel<<<(n + 255) / 256, 256>>>(n);
            count_kernel<<<(e + 255) / 256, 256>>>(eg, e);
            dinv_kernel<<<(n + 255) / 256, 256>>>(n);
            scan_kernel<<<1, 1024>>>(n);
            fill_kernel<<<(e + 255) / 256, 256>>>(eg, e);
        }

        float4* T1 = (float4*)(T + Ssz);
        float4* T2 = (float4*)(T + 2 * Ssz);
        // Tx1 = prop(Tx0);  Tx2 = 2*prop(Tx1) - Tx0   (Tx0 = prevOut via >>sh)
        prop_kernel<<<dim3(R4 / 256, n), 256>>>(T1, (const float4*)prevOut,
                                                nullptr, 1.0f, R4, sh, 0);
        prop_kernel<<<dim3(R4 / 256, n), 256>>>(T2, (const float4*)T1,
                                                (const float4*)prevOut, 2.0f,
                                                R4, 0, sh);

        float* ob = (l % 2 == 0) ? OA : OB;
        int mode = (l < 4) ? 2 : 0;
        gemm_mma<<<dim3((co + GBN - 1) / GBN, M / GBM), 256>>>(
            prevOut, T + Ssz, (long long)Ssz, cil2[l], sh, W[l], bb[l], ob,
            M, co, K, mode);
        prevOut = ob;
    }

    const int TOT = 128 * 6890 * 3;
    final_kernel<<<(TOT + 255) / 256, 256>>>(out, prevOut, perm);
}

// round 5
// speedup vs baseline: 3.5707x; 3.5707x over previous
#include <cuda_runtime.h>
#include <cstdint>

// ---------------------------------------------------------------------------
// ChebGcnDecoder, commuted form:
//   out_l = U0 + P*U1 + 2*P*(P*U2) + b
//   U0 = Tx0@(W0-W2), U1 = Tx0@W1, U2 = Tx0@W2    (single GEMM, Wc = ci x 3co)
// then two gather-props on co channels. repeat(2,axis=1) fused as node>>1 in
// the GEMM A-read. Layout everywhere: (node, batch, channel) row-major.
// ---------------------------------------------------------------------------

#define LRELU_S 0.2f

// Scratch (static __device__ arrays; no allocation allowed)
__device__ float g_T[42467328];      // U0|U1|U2, stride M*co (<= 14,155,776)
__device__ float g_outA[14155776];   // FC2 out / per-layer outputs
__device__ float g_outB[14155776];   // V = P*U2
__device__ float g_h1[65536];        // FC1 output 128x512
__device__ float g_wcat[49152];      // combined weights (ci x 3co), max 128x384
__device__ int   g_cnt[6912];
__device__ float g_dinv[6912];
__device__ int   g_off[6913];
__device__ int   g_cur[6912];
__device__ int   g_csrc[41472];
__device__ float g_cw[41472];
__device__ int   g_is64;

// ---------------------------------------------------------------------------
__device__ __forceinline__ int read_idx(const void* p, int i) {
    if (g_is64) return (int)((const long long*)p)[i];
    return ((const int*)p)[i];
}

// int64 vs int32 sniff: LE int64 values in [0,6912) have all odd words zero.
__global__ void detect_kernel(const int* w, int nwords) {
    __shared__ int any;
    if (threadIdx.x == 0) any = 0;
    __syncthreads();
    int a = 0;
    for (int i = 1 + 2 * (int)threadIdx.x; i < nwords; i += 2 * blockDim.x) a |= w[i];
    if (a) atomicOr(&any, 1);
    __syncthreads();
    if (threadIdx.x == 0) g_is64 = any ? 0 : 1;
}

__global__ void zero_cnt_kernel(int n) {
    int i = blockIdx.x * blockDim.x + threadIdx.x;
    if (i < n) g_cnt[i] = 0;
}

__global__ void count_kernel(const void* edges, int e) {
    int i = blockIdx.x * blockDim.x + threadIdx.x;
    if (i < e) atomicAdd(&g_cnt[read_idx(edges, e + i)], 1);
}

__global__ void dinv_kernel(int n) {
    int i = blockIdx.x * blockDim.x + threadIdx.x;
    if (i < n) g_dinv[i] = (g_cnt[i] > 0) ? rsqrtf((float)g_cnt[i]) : 0.0f;
}

__global__ void scan_kernel(int n) {
    __shared__ int partial[1024];
    int tid = threadIdx.x;
    int C = (n + 1023) / 1024;   // <= 7
    int start = tid * C;
    int local[8];
    int s = 0;
    for (int i = 0; i < C; i++) {
        int idx = start + i;
        int v = (idx < n) ? g_cnt[idx] : 0;
        local[i] = s;
        s += v;
    }
    partial[tid] = s;
    __syncthreads();
    for (int d = 1; d < 1024; d <<= 1) {
        int t = (tid >= d) ? partial[tid - d] : 0;
        __syncthreads();
        if (tid >= d) partial[tid] += t;
        __syncthreads();
    }
    int base = (tid > 0) ? partial[tid - 1] : 0;
    for (int i = 0; i < C; i++) {
        int idx = start + i;
        if (idx < n) {
            int o = base + local[i];
            g_off[idx] = o;
            g_cur[idx] = o;
        }
    }
    if (tid == 1023) g_off[n] = partial[1023];
}

__global__ void fill_kernel(const void* edges, int e) {
    int i = blockIdx.x * blockDim.x + threadIdx.x;
    if (i < e) {
        int s = read_idx(edges, i);
        int d = read_idx(edges, e + i);
        int p = atomicAdd(&g_cur[d], 1);
        g_csrc[p] = s;
        g_cw[p] = -g_dinv[s] * g_dinv[d];
    }
}

// Combined weights: Wc (ci x 3co) = [W0-W2 | W1 | W2], W input is (3, ci, co).
// NOTE: plain W2 here; the factor 2 on the P^2 term is applied in propF/propF3.
__global__ void wprep_kernel(const float* __restrict__ W, float* __restrict__ Wc,
                             int ci, int co) {
    int i = blockIdx.x * blockDim.x + threadIdx.x;
    int N = 3 * co;
    if (i >= ci * N) return;
    int k = i / N, n = i - k * N;
    int cico = ci * co;
    float v;
    if (n < co)            v = W[k * co + n] - W[2 * cico + k * co + n];
    else if (n < 2 * co)   v = W[cico + k * co + (n - co)];
    else                   v = W[2 * cico + k * co + (n - 2 * co)];
    Wc[i] = v;
}

// ---------------------------------------------------------------------------
// SIMT fp32 GEMM, templated tile.  C(MxN) = A(MxK) @ W(KxN) [+bias][act]
// A row m maps to physical row (((m>>7)>>sh)<<7)|(m&127)  (fused repeat(2)).
// MODE: 1 bias+relu, 2 bias + FC2-transpose write to (node,batch,ch),
//       3 no bias, split write into U0|U1|U2 (t = n/co) at out + t*ustr.
// Requires M % BM == 0 and K % 16 == 0.
// ---------------------------------------------------------------------------
template<int BM, int BN, int TM, int TN, int MODE>
__global__ __launch_bounds__(256)
void gemm_k(const float* __restrict__ A, const float* __restrict__ W,
            const float* __restrict__ bias, float* __restrict__ out,
            int M, int N, int K, int sh, int co, long long ustr) {
    __shared__ float As[16][BM + 4];
    __shared__ float Ws[16][BN + 4];
    const int tid = threadIdx.x;
    const int tx = tid & 15, ty = tid >> 4;
    const int m0 = blockIdx.y * BM, n0 = blockIdx.x * BN;

    float acc[TM][TN];
#pragma unroll
    for (int i = 0; i < TM; i++)
#pragma unroll
        for (int j = 0; j < TN; j++) acc[i][j] = 0.0f;

    for (int k0 = 0; k0 < K; k0 += 16) {
        // A tile (BM x 16), vector loads, transposed store
#pragma unroll
        for (int r = 0; r < BM / 64; r++) {
            int lid = tid + r * 256;
            int row = lid >> 2;
            int kq = (lid & 3) << 2;
            int mg = m0 + row;
            int mg2 = ((((mg >> 7) >> sh) << 7)) | (mg & 127);
            float4 a = *(const float4*)(A + (size_t)mg2 * K + (k0 + kq));
            As[kq + 0][row] = a.x;
            As[kq + 1][row] = a.y;
            As[kq + 2][row] = a.z;
            As[kq + 3][row] = a.w;
        }
        // W tile (16 x BN)
#pragma unroll
        for (int r = 0; r < BN / 64; r++) {
            int lid = tid + r * 256;
            int k = lid / (BN / 4);
            int n4 = (lid % (BN / 4)) * 4;
            int gc = n0 + n4;
            float4 w;
            if (((N & 3) == 0) && gc + 4 <= N) {
                w = *(const float4*)(W + (size_t)(k0 + k) * N + gc);
            } else {
                w.x = (gc + 0 < N) ? W[(size_t)(k0 + k) * N + gc + 0] : 0.f;
                w.y = (gc + 1 < N) ? W[(size_t)(k0 + k) * N + gc + 1] : 0.f;
                w.z = (gc + 2 < N) ? W[(size_t)(k0 + k) * N + gc + 2] : 0.f;
                w.w = (gc + 3 < N) ? W[(size_t)(k0 + k) * N + gc + 3] : 0.f;
            }
            *(float4*)&Ws[k][n4] = w;
        }
        __syncthreads();

#pragma unroll
        for (int k = 0; k < 16; k++) {
            float a[TM], w[TN];
#pragma unroll
            for (int i = 0; i < TM / 4; i++)
                *(float4*)&a[4 * i] = *(const float4*)&As[k][ty * TM + 4 * i];
#pragma unroll
            for (int j = 0; j < TN / 4; j++)
                *(float4*)&w[4 * j] = *(const float4*)&Ws[k][tx * TN + 4 * j];
#pragma unroll
            for (int i = 0; i < TM; i++)
#pragma unroll
                for (int j = 0; j < TN; j++) acc[i][j] += a[i] * w[j];
        }
        __syncthreads();
    }

#pragma unroll
    for (int i = 0; i < TM; i++) {
        int m = m0 + ty * TM + i;
#pragma unroll
        for (int j = 0; j < TN; j++) {
            int n = n0 + tx * TN + j;
            if (n >= N) continue;
            float v = acc[i][j];
            if (MODE == 1) {
                v += bias[n];
                v = v > 0.f ? v : 0.f;
                out[(size_t)m * N + n] = v;
            } else if (MODE == 2) {
                v += bias[n];
                out[(size_t)((n >> 7) * 128 + m) * 128 + (n & 127)] = v;
            } else {  // MODE 3
                int t = (n >= 2 * co) ? 2 : ((n >= co) ? 1 : 0);
                out[(size_t)t * (size_t)ustr + (size_t)m * co + (n - t * co)] = v;
            }
        }
    }
}

// V = P * U2   (gather by CSR).  R4 = 128*co/4 float4 per node row.
__global__ void propV_kernel(float4* __restrict__ V, const float4* __restrict__ U2,
                             int R4) {
    int v = blockIdx.y;
    int j = blockIdx.x * blockDim.x + threadIdx.x;
    float4 acc = make_float4(0.f, 0.f, 0.f, 0.f);
    int s = g_off[v], t = g_off[v + 1];
    for (int q = s; q < t; q++) {
        float w = g_cw[q];
        float4 x = U2[(size_t)g_csrc[q] * R4 + j];
        acc.x += w * x.x; acc.y += w * x.y; acc.z += w * x.z; acc.w += w * x.w;
    }
    V[(size_t)v * R4 + j] = acc;
}

// out = lrelu( U0[v] + sum_e w*(U1[src] + 2*V[src]) + bias )    (co pow2 >= 16)
__global__ void propF_kernel(float4* __restrict__ out, const float4* __restrict__ U0,
                             const float4* __restrict__ U1, const float4* __restrict__ V,
                             const float* __restrict__ bias, int R4, int comask) {
    int v = blockIdx.y;
    int j = blockIdx.x * blockDim.x + threadIdx.x;
    float4 acc = U0[(size_t)v * R4 + j];
    int s = g_off[v], t = g_off[v + 1];
    for (int q = s; q < t; q++) {
        float w = g_cw[q];
        size_t o = (size_t)g_csrc[q] * R4 + j;
        float4 a = U1[o];
        float4 b = V[o];
        acc.x += w * (a.x + 2.f * b.x);
        acc.y += w * (a.y + 2.f * b.y);
        acc.z += w * (a.z + 2.f * b.z);
        acc.w += w * (a.w + 2.f * b.w);
    }
    int c0 = (4 * j) & comask;
    float4 bb = *(const float4*)&bias[c0];
    acc.x += bb.x; acc.y += bb.y; acc.z += bb.z; acc.w += bb.w;
    acc.x = acc.x >= 0.f ? acc.x : LRELU_S * acc.x;
    acc.y = acc.y >= 0.f ? acc.y : LRELU_S * acc.y;
    acc.z = acc.z >= 0.f ? acc.z : LRELU_S * acc.z;
    acc.w = acc.w >= 0.f ? acc.w : LRELU_S * acc.w;
    out[(size_t)v * R4 + j] = acc;
}

// Last layer: co=3, scalar, bias, no activation. R = 384 floats per node.
__global__ void propF3_kernel(float* __restrict__ out, const float* __restrict__ U0,
                              const float* __restrict__ U1, const float* __restrict__ V,
                              const float* __restrict__ bias) {
    int v = blockIdx.y;
    int p = blockIdx.x * blockDim.x + threadIdx.x;   // < 384
    float acc = U0[(size_t)v * 384 + p];
    int s = g_off[v], t = g_off[v + 1];
    for (int q = s; q < t; q++) {
        size_t o = (size_t)g_csrc[q] * 384 + p;
        acc += g_cw[q] * (U1[o] + 2.f * V[o]);
    }
    out[(size_t)v * 384 + p] = acc + bias[p % 3];
}

// out[b][u][k] = h[(perm[u]*128 + b)*3 + k], u < 6890
__global__ void final_kernel(float* __restrict__ out, const float* __restrict__ h,
                             const void* __restrict__ perm) {
    int i = blockIdx.x * blockDim.x + threadIdx.x;
    const int TOT = 128 * 6890 * 3;
    if (i < TOT) {
        int b = i / (6890 * 3);
        int r = i - b * (6890 * 3);
        int u = r / 3;
        int k = r - u * 3;
        int v = read_idx(perm, u);
        out[i] = h[(size_t)(v * 128 + b) * 3 + k];
    }
}

// ---------------------------------------------------------------------------
extern "C" void kernel_launch(void* const* d_in, const int* in_sizes, int n_in,
                              void* d_out, int out_size) {
    const float* x   = (const float*)d_in[0];
    const float* fw1 = (const float*)d_in[1];
    const float* fb1 = (const float*)d_in[2];
    const float* fw2 = (const float*)d_in[3];
    const float* fb2 = (const float*)d_in[4];
    const float* W[5];
    const float* bb[5];
    for (int i = 0; i < 5; i++) {
        W[i]  = (const float*)d_in[5 + 2 * i];
        bb[i] = (const float*)d_in[6 + 2 * i];
    }
    const void* edges[4];
    for (int i = 0; i < 4; i++) edges[i] = d_in[15 + i];
    const void* perm = d_in[19];
    float* out = (float*)d_out;

    float *T, *OA, *OB, *H1, *WC;
    cudaGetSymbolAddress((void**)&T,  g_T);
    cudaGetSymbolAddress((void**)&OA, g_outA);
    cudaGetSymbolAddress((void**)&OB, g_outB);
    cudaGetSymbolAddress((void**)&H1, g_h1);
    cudaGetSymbolAddress((void**)&WC, g_wcat);

    const int ns[5]   = {864, 1728, 3456, 6912, 6912};
    const int cis[5]  = {128, 128, 64, 32, 16};
    const int cos_[5] = {128, 64, 32, 16, 3};
    const int eidx[5] = {0, 1, 2, 3, 3};
    const int egn[4]  = {864, 1728, 3456, 6912};

    // 1: dtype sniff
    detect_kernel<<<1, 256>>>((const int*)edges[0], 5184);
    // 2: FC1 (128x128)@(128x512)+b, relu
    gemm_k<128, 128, 8, 8, 1><<<dim3(4, 1), 256>>>(x, fw1, fb1, H1,
                                                   128, 512, 128, 0, 0, 0);
    // 3: FC2 (128x512)@(512x110592)+b, transposed write -> OA as (node,batch,ch)
    gemm_k<128, 128, 8, 8, 2><<<dim3(110592 / 128, 1), 256>>>(
        H1, fw2, fb2, OA, 128, 110592, 512, 0, 0, 0);

    for (int l = 0; l < 5; l++) {
        int n  = ns[l];
        int ci = cis[l];
        int co = cos_[l];
        int M  = n * 128;
        int N  = 3 * co;
        int sh = (l == 0 || l == 4) ? 0 : 1;   // repeat(2) fused as node>>1
        int R4 = 32 * co;                       // float4 per node row
        long long US = (long long)M * co;       // per-layer U-block stride

        // combined weights for this layer
        wprep_kernel<<<(ci * N + 255) / 256, 256>>>(W[l], WC, ci, co);

        if (l == 0) {
            // keep the big ChebConv GEMM at launch slot #6 for ncu
            zero_cnt_kernel<<<(n + 255) / 256, 256>>>(n);                       // 5
            gemm_k<128, 128, 8, 8, 3><<<dim3((N + 127) / 128, M / 128), 256>>>( // 6
                OA, WC, nullptr, T, M, N, ci, sh, co, US);
            int e = 6 * egn[0];
            count_kernel<<<(e + 255) / 256, 256>>>(edges[0], e);
            dinv_kernel<<<(n + 255) / 256, 256>>>(n);
            scan_kernel<<<1, 1024>>>(n);
            fill_kernel<<<(e + 255) / 256, 256>>>(edges[0], e);
        } else {
            if (l < 4) {   // layer 4 reuses layer 3's CSR
                const void* eg = edges[eidx[l]];
                int e = 6 * egn[eidx[l]];
                zero_cnt_kernel<<<(n + 255) / 256, 256>>>(n);
                count_kernel<<<(e + 255) / 256, 256>>>(eg, e);
                dinv_kernel<<<(n + 255) / 256, 256>>>(n);
                scan_kernel<<<1, 1024>>>(n);
                fill_kernel<<<(e + 255) / 256, 256>>>(eg, e);
            }
            gemm_k<256, 64, 16, 4, 3><<<dim3((N + 63) / 64, M / 256), 256>>>(
                OA, WC, nullptr, T, M, N, ci, sh, co, US);
        }

        // V = P*U2
        propV_kernel<<<dim3(R4 >= 256 ? R4 / 256 : 1, n), R4 < 256 ? R4 : 256>>>(
            (float4*)OB, (const float4*)(T + 2 * US), R4);
        // out = [lrelu](U0 + P*U1 + 2*P*V + b)
        if (l < 4) {
            propF_kernel<<<dim3(R4 / 256, n), 256>>>(
                (float4*)OA, (const float4*)T, (const float4*)(T + US),
                (const float4*)OB, bb[l], R4, co - 1);
        } else {
            propF3_kernel<<<dim3(3, n), 128>>>(OA, T, T + US, OB, bb[4]);
        }
    }

    const int TOT = 128 * 6890 * 3;
    final_kernel<<<(TOT + 255) / 256, 256>>>(out, OA, perm);
}

// round 6
// speedup vs baseline: 4.3057x; 1.2058x over previous
#include <cuda_runtime.h>
#include <cstdint>

// ---------------------------------------------------------------------------
// ChebGcnDecoder, commuted form:
//   out_l = U0 + P*U1 + 2*P*(P*U2) + b
//   U0 = Tx0@(W0-W2), U1 = Tx0@W1, U2 = Tx0@W2    (single GEMM, Wc = ci x 3co)
// For layers 1-3 the GEMM input rows are pairwise-duplicated (repeat(2,axis=1))
// so the GEMM runs on the UN-repeated input (M/2 rows) and the props gather
// U'[src>>1]. Layout: (node, batch, channel) row-major everywhere.
// ---------------------------------------------------------------------------

#define LRELU_S 0.2f

// Scratch (static __device__ arrays; no allocation allowed)
__device__ float g_T[42467328];      // U0|U1|U2, stride Mg*co (<= 14,155,776)
__device__ float g_outA[14155776];   // FC2 out / per-layer outputs
__device__ float g_outB[14155776];   // V = P*U2
__device__ float g_h1[65536];        // FC1 output 128x512
__device__ float g_wcat[49152];      // combined weights (ci x 3co), max 128x384
__device__ int   g_cnt[6912];
__device__ float g_dinv[6912];
__device__ int   g_off[6913];
__device__ int   g_cur[6912];
__device__ int   g_csrc[41472];
__device__ float g_cw[41472];
__device__ int   g_is64;

// ---------------------------------------------------------------------------
__device__ __forceinline__ int read_idx(const void* p, int i) {
    if (g_is64) return (int)((const long long*)p)[i];
    return ((const int*)p)[i];
}

// int64 vs int32 sniff: LE int64 values in [0,6912) have all odd words zero.
__global__ void detect_kernel(const int* w, int nwords) {
    __shared__ int any;
    if (threadIdx.x == 0) any = 0;
    __syncthreads();
    int a = 0;
    for (int i = 1 + 2 * (int)threadIdx.x; i < nwords; i += 2 * blockDim.x) a |= w[i];
    if (a) atomicOr(&any, 1);
    __syncthreads();
    if (threadIdx.x == 0) g_is64 = any ? 0 : 1;
}

__global__ void zero_cnt_kernel(int n) {
    int i = blockIdx.x * blockDim.x + threadIdx.x;
    if (i < n) g_cnt[i] = 0;
}

__global__ void count_kernel(const void* edges, int e) {
    int i = blockIdx.x * blockDim.x + threadIdx.x;
    if (i < e) atomicAdd(&g_cnt[read_idx(edges, e + i)], 1);
}

__global__ void dinv_kernel(int n) {
    int i = blockIdx.x * blockDim.x + threadIdx.x;
    if (i < n) g_dinv[i] = (g_cnt[i] > 0) ? rsqrtf((float)g_cnt[i]) : 0.0f;
}

__global__ void scan_kernel(int n) {
    __shared__ int partial[1024];
    int tid = threadIdx.x;
    int C = (n + 1023) / 1024;   // <= 7
    int start = tid * C;
    int local[8];
    int s = 0;
    for (int i = 0; i < C; i++) {
        int idx = start + i;
        int v = (idx < n) ? g_cnt[idx] : 0;
        local[i] = s;
        s += v;
    }
    partial[tid] = s;
    __syncthreads();
    for (int d = 1; d < 1024; d <<= 1) {
        int t = (tid >= d) ? partial[tid - d] : 0;
        __syncthreads();
        if (tid >= d) partial[tid] += t;
        __syncthreads();
    }
    int base = (tid > 0) ? partial[tid - 1] : 0;
    for (int i = 0; i < C; i++) {
        int idx = start + i;
        if (idx < n) {
            int o = base + local[i];
            g_off[idx] = o;
            g_cur[idx] = o;
        }
    }
    if (tid == 1023) g_off[n] = partial[1023];
}

__global__ void fill_kernel(const void* edges, int e) {
    int i = blockIdx.x * blockDim.x + threadIdx.x;
    if (i < e) {
        int s = read_idx(edges, i);
        int d = read_idx(edges, e + i);
        int p = atomicAdd(&g_cur[d], 1);
        g_csrc[p] = s;
        g_cw[p] = -g_dinv[s] * g_dinv[d];
    }
}

// Combined weights: Wc (ci x 3co) = [W0-W2 | W1 | W2], W input is (3, ci, co).
// Plain W2 here; the factor 2 on the P^2 term is applied in propF/propF3.
__global__ void wprep_kernel(const float* __restrict__ W, float* __restrict__ Wc,
                             int ci, int co) {
    int i = blockIdx.x * blockDim.x + threadIdx.x;
    int N = 3 * co;
    if (i >= ci * N) return;
    int k = i / N, n = i - k * N;
    int cico = ci * co;
    float v;
    if (n < co)            v = W[k * co + n] - W[2 * cico + k * co + n];
    else if (n < 2 * co)   v = W[cico + k * co + (n - co)];
    else                   v = W[2 * cico + k * co + (n - 2 * co)];
    Wc[i] = v;
}

// ---------------------------------------------------------------------------
// SIMT fp32 GEMM, templated tile.  C(MxN) = A(MxK) @ W(KxN) [+bias][act]
// MODE: 1 bias+relu, 2 bias + FC2-transpose write to (node,batch,ch),
//       3 no bias, split write into U0|U1|U2 (t = n/co) at out + t*ustr.
// Requires M % BM == 0 and K % 16 == 0.
// ---------------------------------------------------------------------------
template<int BM, int BN, int TM, int TN, int MODE>
__global__ __launch_bounds__(256)
void gemm_k(const float* __restrict__ A, const float* __restrict__ W,
            const float* __restrict__ bias, float* __restrict__ out,
            int M, int N, int K, int co, long long ustr) {
    __shared__ float As[16][BM + 4];
    __shared__ float Ws[16][BN + 4];
    const int tid = threadIdx.x;
    const int tx = tid & 15, ty = tid >> 4;
    const int m0 = blockIdx.y * BM, n0 = blockIdx.x * BN;

    float acc[TM][TN];
#pragma unroll
    for (int i = 0; i < TM; i++)
#pragma unroll
        for (int j = 0; j < TN; j++) acc[i][j] = 0.0f;

    for (int k0 = 0; k0 < K; k0 += 16) {
        // A tile (BM x 16), vector loads, transposed store
#pragma unroll
        for (int r = 0; r < BM / 64; r++) {
            int lid = tid + r * 256;
            int row = lid >> 2;
            int kq = (lid & 3) << 2;
            int mg = m0 + row;
            float4 a = *(const float4*)(A + (size_t)mg * K + (k0 + kq));
            As[kq + 0][row] = a.x;
            As[kq + 1][row] = a.y;
            As[kq + 2][row] = a.z;
            As[kq + 3][row] = a.w;
        }
        // W tile (16 x BN)
#pragma unroll
        for (int r = 0; r < BN / 64; r++) {
            int lid = tid + r * 256;
            int k = lid / (BN / 4);
            int n4 = (lid % (BN / 4)) * 4;
            int gc = n0 + n4;
            float4 w;
            if (((N & 3) == 0) && gc + 4 <= N) {
                w = *(const float4*)(W + (size_t)(k0 + k) * N + gc);
            } else {
                w.x = (gc + 0 < N) ? W[(size_t)(k0 + k) * N + gc + 0] : 0.f;
                w.y = (gc + 1 < N) ? W[(size_t)(k0 + k) * N + gc + 1] : 0.f;
                w.z = (gc + 2 < N) ? W[(size_t)(k0 + k) * N + gc + 2] : 0.f;
                w.w = (gc + 3 < N) ? W[(size_t)(k0 + k) * N + gc + 3] : 0.f;
            }
            *(float4*)&Ws[k][n4] = w;
        }
        __syncthreads();

#pragma unroll
        for (int k = 0; k < 16; k++) {
            float a[TM], w[TN];
#pragma unroll
            for (int i = 0; i < TM / 4; i++)
                *(float4*)&a[4 * i] = *(const float4*)&As[k][ty * TM + 4 * i];
#pragma unroll
            for (int j = 0; j < TN / 4; j++)
                *(float4*)&w[4 * j] = *(const float4*)&Ws[k][tx * TN + 4 * j];
#pragma unroll
            for (int i = 0; i < TM; i++)
#pragma unroll
                for (int j = 0; j < TN; j++) acc[i][j] += a[i] * w[j];
        }
        __syncthreads();
    }

#pragma unroll
    for (int i = 0; i < TM; i++) {
        int m = m0 + ty * TM + i;
#pragma unroll
        for (int j = 0; j < TN; j++) {
            int n = n0 + tx * TN + j;
            if (n >= N) continue;
            float v = acc[i][j];
            if (MODE == 1) {
                v += bias[n];
                v = v > 0.f ? v : 0.f;
                out[(size_t)m * N + n] = v;
            } else if (MODE == 2) {
                v += bias[n];
                out[(size_t)((n >> 7) * 128 + m) * 128 + (n & 127)] = v;
            } else {  // MODE 3
                int t = (n >= 2 * co) ? 2 : ((n >= co) ? 1 : 0);
                out[(size_t)t * (size_t)ustr + (size_t)m * co + (n - t * co)] = v;
            }
        }
    }
}

// V = P * U2'.  U2' indexed by src>>shU (half-size for layers 1-3).
// R4 = 128*co/4 float4 per node row.
__global__ void propV_kernel(float4* __restrict__ V, const float4* __restrict__ U2,
                             int R4, int shU) {
    int v = blockIdx.y;
    int j = blockIdx.x * blockDim.x + threadIdx.x;
    float4 acc = make_float4(0.f, 0.f, 0.f, 0.f);
    int s = g_off[v], t = g_off[v + 1];
    for (int q = s; q < t; q++) {
        float w = g_cw[q];
        float4 x = U2[(size_t)(g_csrc[q] >> shU) * R4 + j];
        acc.x += w * x.x; acc.y += w * x.y; acc.z += w * x.z; acc.w += w * x.w;
    }
    V[(size_t)v * R4 + j] = acc;
}

// out = lrelu( U0'[v>>shU] + sum_e w*(U1'[src>>shU] + 2*V[src]) + bias )
__global__ void propF_kernel(float4* __restrict__ out, const float4* __restrict__ U0,
                             const float4* __restrict__ U1, const float4* __restrict__ V,
                             const float* __restrict__ bias, int R4, int comask, int shU) {
    int v = blockIdx.y;
    int j = blockIdx.x * blockDim.x + threadIdx.x;
    float4 acc = U0[(size_t)(v >> shU) * R4 + j];
    int s = g_off[v], t = g_off[v + 1];
    for (int q = s; q < t; q++) {
        float w = g_cw[q];
        int src = g_csrc[q];
        float4 a = U1[(size_t)(src >> shU) * R4 + j];
        float4 b = V[(size_t)src * R4 + j];
        acc.x += w * (a.x + 2.f * b.x);
        acc.y += w * (a.y + 2.f * b.y);
        acc.z += w * (a.z + 2.f * b.z);
        acc.w += w * (a.w + 2.f * b.w);
    }
    int c0 = (4 * j) & comask;
    float4 bb = *(const float4*)&bias[c0];
    acc.x += bb.x; acc.y += bb.y; acc.z += bb.z; acc.w += bb.w;
    acc.x = acc.x >= 0.f ? acc.x : LRELU_S * acc.x;
    acc.y = acc.y >= 0.f ? acc.y : LRELU_S * acc.y;
    acc.z = acc.z >= 0.f ? acc.z : LRELU_S * acc.z;
    acc.w = acc.w >= 0.f ? acc.w : LRELU_S * acc.w;
    out[(size_t)v * R4 + j] = acc;
}

// Last layer: co=3, scalar, bias, no activation. R = 384 floats per node.
__global__ void propF3_kernel(float* __restrict__ out, const float* __restrict__ U0,
                              const float* __restrict__ U1, const float* __restrict__ V,
                              const float* __restrict__ bias) {
    int v = blockIdx.y;
    int p = blockIdx.x * blockDim.x + threadIdx.x;   // < 384
    float acc = U0[(size_t)v * 384 + p];
    int s = g_off[v], t = g_off[v + 1];
    for (int q = s; q < t; q++) {
        size_t o = (size_t)g_csrc[q] * 384 + p;
        acc += g_cw[q] * (U1[o] + 2.f * V[o]);
    }
    out[(size_t)v * 384 + p] = acc + bias[p % 3];
}

// out[b][u][k] = h[(perm[u]*128 + b)*3 + k], u < 6890
__global__ void final_kernel(float* __restrict__ out, const float* __restrict__ h,
                             const void* __restrict__ perm) {
    int i = blockIdx.x * blockDim.x + threadIdx.x;
    const int TOT = 128 * 6890 * 3;
    if (i < TOT) {
        int b = i / (6890 * 3);
        int r = i - b * (6890 * 3);
        int u = r / 3;
        int k = r - u * 3;
        int v = read_idx(perm, u);
        out[i] = h[(size_t)(v * 128 + b) * 3 + k];
    }
}

// ---------------------------------------------------------------------------
extern "C" void kernel_launch(void* const* d_in, const int* in_sizes, int n_in,
                              void* d_out, int out_size) {
    const float* x   = (const float*)d_in[0];
    const float* fw1 = (const float*)d_in[1];
    const float* fb1 = (const float*)d_in[2];
    const float* fw2 = (const float*)d_in[3];
    const float* fb2 = (const float*)d_in[4];
    const float* W[5];
    const float* bb[5];
    for (int i = 0; i < 5; i++) {
        W[i]  = (const float*)d_in[5 + 2 * i];
        bb[i] = (const float*)d_in[6 + 2 * i];
    }
    const void* edges[4];
    for (int i = 0; i < 4; i++) edges[i] = d_in[15 + i];
    const void* perm = d_in[19];
    float* out = (float*)d_out;

    float *T, *OA, *OB, *H1, *WC;
    cudaGetSymbolAddress((void**)&T,  g_T);
    cudaGetSymbolAddress((void**)&OA, g_outA);
    cudaGetSymbolAddress((void**)&OB, g_outB);
    cudaGetSymbolAddress((void**)&H1, g_h1);
    cudaGetSymbolAddress((void**)&WC, g_wcat);

    const int ns[5]   = {864, 1728, 3456, 6912, 6912};
    const int cis[5]  = {128, 128, 64, 32, 16};
    const int cos_[5] = {128, 64, 32, 16, 3};
    const int eidx[5] = {0, 1, 2, 3, 3};
    const int egn[4]  = {864, 1728, 3456, 6912};

    // Launch order tuned so the captured ncu launch (index 3) is gemm_l0.
    // 0: FC1 (128x128)@(128x512)+b, relu
    gemm_k<128, 128, 8, 8, 1><<<dim3(4, 1), 256>>>(x, fw1, fb1, H1,
                                                   128, 512, 128, 0, 0);
    // 1: FC2 (128x512)@(512x110592)+b, transposed write -> OA as (node,batch,ch)
    gemm_k<128, 128, 8, 8, 2><<<dim3(110592 / 128, 1), 256>>>(
        H1, fw2, fb2, OA, 128, 110592, 512, 0, 0);
    // 2: combined weights for layer 0
    wprep_kernel<<<(128 * 384 + 255) / 256, 256>>>(W[0], WC, 128, 128);
    // 3: layer-0 ChebConv GEMM (10.9 GF) — ncu capture target
    {
        long long US = 110592LL * 128;
        gemm_k<128, 128, 8, 8, 3><<<dim3(3, 110592 / 128), 256>>>(
            OA, WC, nullptr, T, 110592, 384, 128, 128, US);
    }
    // 4: dtype sniff for index buffers
    detect_kernel<<<1, 256>>>((const int*)edges[0], 5184);

    for (int l = 0; l < 5; l++) {
        int n  = ns[l];
        int ci = cis[l];
        int co = cos_[l];
        int N  = 3 * co;
        // layers 1-3: GEMM on un-repeated input (half the nodes); props do >>1
        int ng = (l == 0 || l == 4) ? n : n / 2;
        int Mg = ng * 128;
        int shU = (l == 0 || l == 4) ? 0 : 1;
        int R4 = 32 * co;
        long long US = (long long)Mg * co;

        if (l > 0) {
            wprep_kernel<<<(ci * N + 255) / 256, 256>>>(W[l], WC, ci, co);
            gemm_k<256, 64, 16, 4, 3><<<dim3((N + 63) / 64, Mg / 256), 256>>>(
                OA, WC, nullptr, T, Mg, N, ci, co, US);
        }

        {   // CSR build (layer 4 reuses layer 3's)
            if (l < 4) {
                const void* eg = edges[eidx[l]];
                int e = 6 * egn[eidx[l]];
                zero_cnt_kernel<<<(n + 255) / 256, 256>>>(n);
                count_kernel<<<(e + 255) / 256, 256>>>(eg, e);
                dinv_kernel<<<(n + 255) / 256, 256>>>(n);
                scan_kernel<<<1, 1024>>>(n);
                fill_kernel<<<(e + 255) / 256, 256>>>(eg, e);
            }
        }

        // V = P*U2'
        propV_kernel<<<dim3(R4 >= 256 ? R4 / 256 : 1, n), R4 < 256 ? R4 : 256>>>(
            (float4*)OB, (const float4*)(T + 2 * US), R4, shU);
        // out = [lrelu](U0' + P*U1' + 2*P*V + b)
        if (l < 4) {
            propF_kernel<<<dim3(R4 / 256, n), 256>>>(
                (float4*)OA, (const float4*)T, (const float4*)(T + US),
                (const float4*)OB, bb[l], R4, co - 1, shU);
        } else {
            propF3_kernel<<<dim3(3, n), 128>>>(OA, T, T + US, OB, bb[4]);
        }
    }

    const int TOT = 128 * 6890 * 3;
    final_kernel<<<(TOT + 255) / 256, 256>>>(out, OA, perm);
}

// round 8
// speedup vs baseline: 4.9411x; 1.1476x over previous
#include <cuda_runtime.h>
#include <cuda_bf16.h>
#include <cstdint>

// ---------------------------------------------------------------------------
// ChebGcnDecoder, commuted form (see R5/R6). Big GEMMs (FC2, L0-L2) run on
// tensor cores via legacy mma.sync m16n8k16 bf16 hi/lo 3-split (fp32 accum,
// ~fp32 precision), operands fetched with ldmatrix from SW128-swizzled SMEM.
// (tcgen05 is unavailable: harness PTX targets compute_103 without 'a'.)
// Small GEMMs (FC1, L3, L4) stay on the measured 28.5 TF/s SIMT fp32 path.
// ---------------------------------------------------------------------------

#define LRELU_S 0.2f

__device__ float g_T[42467328];      // U0|U1|U2, stride Mg*co
__device__ float g_outA[14155776];   // FC2 out / per-layer outputs
__device__ float g_outB[14155776];   // V = P*U2
__device__ float g_h1[65536];        // FC1 output 128x512
__device__ float g_wcat[49152];      // combined weights (ci x 3co)
__device__ int   g_cnt[6912];
__device__ float g_dinv[6912];
__device__ int   g_off[6913];
__device__ int   g_cur[6912];
__device__ int   g_csrc[41472];
__device__ float g_cw[41472];
__device__ int   g_is64;

// ---------------------------------------------------------------------------
__device__ __forceinline__ int read_idx(const void* p, int i) {
    if (g_is64) return (int)((const long long*)p)[i];
    return ((const int*)p)[i];
}

__global__ void detect_kernel(const int* w, int nwords) {
    __shared__ int any;
    if (threadIdx.x == 0) any = 0;
    __syncthreads();
    int a = 0;
    for (int i = 1 + 2 * (int)threadIdx.x; i < nwords; i += 2 * blockDim.x) a |= w[i];
    if (a) atomicOr(&any, 1);
    __syncthreads();
    if (threadIdx.x == 0) g_is64 = any ? 0 : 1;
}

__global__ void zero_cnt_kernel(int n) {
    int i = blockIdx.x * blockDim.x + threadIdx.x;
    if (i < n) g_cnt[i] = 0;
}
__global__ void count_kernel(const void* edges, int e) {
    int i = blockIdx.x * blockDim.x + threadIdx.x;
    if (i < e) atomicAdd(&g_cnt[read_idx(edges, e + i)], 1);
}
__global__ void dinv_kernel(int n) {
    int i = blockIdx.x * blockDim.x + threadIdx.x;
    if (i < n) g_dinv[i] = (g_cnt[i] > 0) ? rsqrtf((float)g_cnt[i]) : 0.0f;
}
__global__ void scan_kernel(int n) {
    __shared__ int partial[1024];
    int tid = threadIdx.x;
    int C = (n + 1023) / 1024;
    int start = tid * C;
    int local[8];
    int s = 0;
    for (int i = 0; i < C; i++) {
        int idx = start + i;
        int v = (idx < n) ? g_cnt[idx] : 0;
        local[i] = s;
        s += v;
    }
    partial[tid] = s;
    __syncthreads();
    for (int d = 1; d < 1024; d <<= 1) {
        int t = (tid >= d) ? partial[tid - d] : 0;
        __syncthreads();
        if (tid >= d) partial[tid] += t;
        __syncthreads();
    }
    int base = (tid > 0) ? partial[tid - 1] : 0;
    for (int i = 0; i < C; i++) {
        int idx = start + i;
        if (idx < n) {
            int o = base + local[i];
            g_off[idx] = o;
            g_cur[idx] = o;
        }
    }
    if (tid == 1023) g_off[n] = partial[1023];
}
__global__ void fill_kernel(const void* edges, int e) {
    int i = blockIdx.x * blockDim.x + threadIdx.x;
    if (i < e) {
        int s = read_idx(edges, i);
        int d = read_idx(edges, e + i);
        int p = atomicAdd(&g_cur[d], 1);
        g_csrc[p] = s;
        g_cw[p] = -g_dinv[s] * g_dinv[d];
    }
}

// Wc (ci x 3co) = [W0-W2 | W1 | W2]; factor 2 on P^2 applied in propF/propF3.
__global__ void wprep_kernel(const float* __restrict__ W, float* __restrict__ Wc,
                             int ci, int co) {
    int i = blockIdx.x * blockDim.x + threadIdx.x;
    int N = 3 * co;
    if (i >= ci * N) return;
    int k = i / N, n = i - k * N;
    int cico = ci * co;
    float v;
    if (n < co)            v = W[k * co + n] - W[2 * cico + k * co + n];
    else if (n < 2 * co)   v = W[cico + k * co + (n - co)];
    else                   v = W[2 * cico + k * co + (n - 2 * co)];
    Wc[i] = v;
}

// ---------------------------------------------------------------------------
// Shared epilogue write
// MODE: 1 bias+relu row-major; 2 bias + FC2-transpose to (node,batch,ch);
//       3 no bias, split write into U0|U1|U2 (t = n/co) at out + t*ustr.
// ---------------------------------------------------------------------------
template<int MODE>
__device__ __forceinline__ void write_c(float v, int m, int n, int N,
                                        const float* bias, float* out,
                                        int co, long long ustr) {
    if (n >= N) return;
    if (MODE == 1) {
        v += bias[n];
        v = v > 0.f ? v : 0.f;
        out[(size_t)m * N + n] = v;
    } else if (MODE == 2) {
        v += bias[n];
        out[(size_t)((n >> 7) * 128 + m) * 128 + (n & 127)] = v;
    } else {
        int t = n / co;
        out[(size_t)t * (size_t)ustr + (size_t)m * co + (n - t * co)] = v;
    }
}

// ---------------------------------------------------------------------------
// Tensor-core GEMM via mma.sync bf16 hi/lo 3-split + ldmatrix.
// C(MxN) = A(MxK)@W(KxN). BM=128, BN=64, BK=64. Requires M%128==0, K%64==0.
// SMEM: SW128 layout, 128B rows: Ah[128]|Al[128]|Bh[64]|Bl[64] = 48KB.
// ---------------------------------------------------------------------------
__device__ __forceinline__ uint32_t smem_u32(const void* p) {
    uint32_t a;
    asm("{ .reg .u64 t; cvta.to.shared.u64 t, %1; cvt.u32.u64 %0, t; }"
        : "=r"(a) : "l"(p));
    return a;
}

#define LDSM_X4(r0, r1, r2, r3, a)                                            \
    asm volatile("ldmatrix.sync.aligned.m8n8.x4.shared.b16 {%0,%1,%2,%3}, [%4];" \
        : "=r"(r0), "=r"(r1), "=r"(r2), "=r"(r3) : "r"(a))

#define MMA4(c, a, b0, b1)                                                    \
    asm volatile(                                                             \
        "mma.sync.aligned.m16n8k16.row.col.f32.bf16.bf16.f32 "                \
        "{%0,%1,%2,%3}, {%4,%5,%6,%7}, {%8,%9}, {%0,%1,%2,%3};\n"             \
        : "+f"((c)[0]), "+f"((c)[1]), "+f"((c)[2]), "+f"((c)[3])              \
        : "r"((a)[0]), "r"((a)[1]), "r"((a)[2]), "r"((a)[3]),                 \
          "r"(b0), "r"(b1))

template<int MODE>
__global__ __launch_bounds__(256)
void gemm_mma(const float* __restrict__ A, const float* __restrict__ W,
              const float* __restrict__ bias, float* __restrict__ out,
              int M, int N, int K, int co, long long ustr) {
    __shared__ __align__(128) uint8_t sm[49152];
    char* smp = (char*)sm;
    const uint32_t sb = smem_u32(sm);
    const uint32_t oAh = 0, oAl = 16384, oBh = 32768, oBl = 40960;

    const int tid = threadIdx.x, lane = tid & 31, warp = tid >> 5;
    const int wm = warp & 3, wn = warp >> 2;       // 4M x 2N warps, 32x32 tiles
    const int m0 = blockIdx.y * 128, n0 = blockIdx.x * 64;

    float acc[2][4][4];
#pragma unroll
    for (int i = 0; i < 2; i++)
#pragma unroll
        for (int j = 0; j < 4; j++)
#pragma unroll
            for (int q = 0; q < 4; q++) acc[i][j][q] = 0.f;

    // ldmatrix lane addressing (constant across stages except col offset)
    const uint32_t lq = lane >> 3, lr = lane & 7;
    const uint32_t qk = (lq >> 1) << 4;            // 0 or 16 bytes
    uint32_t aoff[2], asw[2], boff[2], bsw[2];
#pragma unroll
    for (int mt = 0; mt < 2; mt++) {
        int row = wm * 32 + mt * 16 + ((lq & 1) << 3) + lr;
        aoff[mt] = (uint32_t)row * 128;
        asw[mt] = (uint32_t)((row & 7) << 4);
    }
#pragma unroll
    for (int nt = 0; nt < 2; nt++) {
        int row = wn * 32 + nt * 16 + ((lq & 1) << 3) + lr;
        boff[nt] = (uint32_t)row * 128;
        bsw[nt] = (uint32_t)((row & 7) << 4);
    }

    const int arow = tid >> 1, ahalf = tid & 1;
    const uint32_t arstore = (uint32_t)arow * 128;
    const uint32_t arswst = (uint32_t)((arow & 7) << 4);

    const int nstages = K >> 6;
    for (int s = 0; s < nstages; s++) {
        int k0 = s << 6;
        // ---- A tile: 128 rows x 64 cols fp32 -> bf16 hi/lo, SW128 ----
        {
            const float* ap = A + (size_t)(m0 + arow) * K + k0 + ahalf * 32;
            uint32_t cb0 = (uint32_t)(ahalf * 64);
#pragma unroll
            for (int q = 0; q < 8; q++) {
                float4 v = *(const float4*)(ap + 4 * q);
                __nv_bfloat162 h0, l0, h1, l1;
                h0.x = __float2bfloat16(v.x);
                l0.x = __float2bfloat16(v.x - __bfloat162float(h0.x));
                h0.y = __float2bfloat16(v.y);
                l0.y = __float2bfloat16(v.y - __bfloat162float(h0.y));
                h1.x = __float2bfloat16(v.z);
                l1.x = __float2bfloat16(v.z - __bfloat162float(h1.x));
                h1.y = __float2bfloat16(v.w);
                l1.y = __float2bfloat16(v.w - __bfloat162float(h1.y));
                uint32_t cb = cb0 + 8 * q;
                uint32_t o = arstore + (cb ^ arswst);
                *(__nv_bfloat162*)(smp + oAh + o)     = h0;
                *(__nv_bfloat162*)(smp + oAh + o + 4) = h1;
                *(__nv_bfloat162*)(smp + oAl + o)     = l0;
                *(__nv_bfloat162*)(smp + oAl + o + 4) = l1;
            }
        }
        // ---- B tile: W(KxN) k0..k0+63, n0..n0+63 -> [n][k] bf16 hi/lo ----
#pragma unroll
        for (int r = 0; r < 8; r++) {
            int linear = r * 256 + tid;            // 0..2047
            int kp = linear >> 6;                  // k pair index 0..31
            int nn = linear & 63;
            int gn = n0 + nn;
            float w0 = 0.f, w1 = 0.f;
            if (gn < N) {
                w0 = W[(size_t)(k0 + 2 * kp) * N + gn];
                w1 = W[(size_t)(k0 + 2 * kp + 1) * N + gn];
            }
            __nv_bfloat162 h, l;
            h.x = __float2bfloat16(w0);
            l.x = __float2bfloat16(w0 - __bfloat162float(h.x));
            h.y = __float2bfloat16(w1);
            l.y = __float2bfloat16(w1 - __bfloat162float(h.y));
            uint32_t o = (uint32_t)nn * 128 + (((uint32_t)(4 * kp)) ^ ((nn & 7) << 4));
            *(__nv_bfloat162*)(smp + oBh + o) = h;
            *(__nv_bfloat162*)(smp + oBl + o) = l;
        }
        __syncthreads();

        // ---- compute: 4 k-steps of 16 ----
#pragma unroll
        for (int kk = 0; kk < 4; kk++) {
            uint32_t cb = ((uint32_t)kk << 5) + qk;
            uint32_t ah[2][4], al[2][4], bh[2][4], bl[2][4];
#pragma unroll
            for (int mt = 0; mt < 2; mt++) {
                uint32_t ad = sb + oAh + aoff[mt] + (cb ^ asw[mt]);
                LDSM_X4(ah[mt][0], ah[mt][1], ah[mt][2], ah[mt][3], ad);
                LDSM_X4(al[mt][0], al[mt][1], al[mt][2], al[mt][3], ad + 16384);
            }
#pragma unroll
            for (int nt = 0; nt < 2; nt++) {
                uint32_t bd = sb + oBh + boff[nt] + (cb ^ bsw[nt]);
                LDSM_X4(bh[nt][0], bh[nt][1], bh[nt][2], bh[nt][3], bd);
                LDSM_X4(bl[nt][0], bl[nt][1], bl[nt][2], bl[nt][3], bd + 8192);
            }
#pragma unroll
            for (int mt = 0; mt < 2; mt++)
#pragma unroll
                for (int nt = 0; nt < 2; nt++)
#pragma unroll
                    for (int u = 0; u < 2; u++) {
                        int nf = nt * 2 + u;
                        MMA4(acc[mt][nf], ah[mt], bh[nt][u], bh[nt][u + 2]);
                        MMA4(acc[mt][nf], ah[mt], bl[nt][u], bl[nt][u + 2]);
                        MMA4(acc[mt][nf], al[mt], bh[nt][u], bh[nt][u + 2]);
                    }
        }
        __syncthreads();
    }

    // ---- epilogue ----
#pragma unroll
    for (int mt = 0; mt < 2; mt++)
#pragma unroll
        for (int nf = 0; nf < 4; nf++) {
            int mrow = m0 + wm * 32 + mt * 16 + (lane >> 2);
            int ncol = n0 + wn * 32 + (nf >> 1) * 16 + (nf & 1) * 8 + 2 * (lane & 3);
            write_c<MODE>(acc[mt][nf][0], mrow,     ncol,     N, bias, out, co, ustr);
            write_c<MODE>(acc[mt][nf][1], mrow,     ncol + 1, N, bias, out, co, ustr);
            write_c<MODE>(acc[mt][nf][2], mrow + 8, ncol,     N, bias, out, co, ustr);
            write_c<MODE>(acc[mt][nf][3], mrow + 8, ncol + 1, N, bias, out, co, ustr);
        }
}

// ---------------------------------------------------------------------------
// SIMT fp32 GEMM (R6) for FC1 / L3 / L4.
// ---------------------------------------------------------------------------
template<int BM, int BN, int TM, int TN, int MODE>
__global__ __launch_bounds__(256)
void gemm_k(const float* __restrict__ A, const float* __restrict__ W,
            const float* __restrict__ bias, float* __restrict__ out,
            int M, int N, int K, int co, long long ustr) {
    __shared__ float As[16][BM + 4];
    __shared__ float Ws[16][BN + 4];
    const int tid = threadIdx.x;
    const int tx = tid & 15, ty = tid >> 4;
    const int m0 = blockIdx.y * BM, n0 = blockIdx.x * BN;

    float acc[TM][TN];
#pragma unroll
    for (int i = 0; i < TM; i++)
#pragma unroll
        for (int j = 0; j < TN; j++) acc[i][j] = 0.0f;

    for (int k0 = 0; k0 < K; k0 += 16) {
#pragma unroll
        for (int r = 0; r < BM / 64; r++) {
            int lid = tid + r * 256;
            int row = lid >> 2;
            int kq = (lid & 3) << 2;
            float4 a = *(const float4*)(A + (size_t)(m0 + row) * K + (k0 + kq));
            As[kq + 0][row] = a.x;
            As[kq + 1][row] = a.y;
            As[kq + 2][row] = a.z;
            As[kq + 3][row] = a.w;
        }
#pragma unroll
        for (int r = 0; r < BN / 64; r++) {
            int lid = tid + r * 256;
            int k = lid / (BN / 4);
            int n4 = (lid % (BN / 4)) * 4;
            int gc = n0 + n4;
            float4 w;
            if (((N & 3) == 0) && gc + 4 <= N) {
                w = *(const float4*)(W + (size_t)(k0 + k) * N + gc);
            } else {
                w.x = (gc + 0 < N) ? W[(size_t)(k0 + k) * N + gc + 0] : 0.f;
                w.y = (gc + 1 < N) ? W[(size_t)(k0 + k) * N + gc + 1] : 0.f;
                w.z = (gc + 2 < N) ? W[(size_t)(k0 + k) * N + gc + 2] : 0.f;
                w.w = (gc + 3 < N) ? W[(size_t)(k0 + k) * N + gc + 3] : 0.f;
            }
            *(float4*)&Ws[k][n4] = w;
        }
        __syncthreads();

#pragma unroll
        for (int k = 0; k < 16; k++) {
            float a[TM], w[TN];
#pragma unroll
            for (int i = 0; i < TM / 4; i++)
                *(float4*)&a[4 * i] = *(const float4*)&As[k][ty * TM + 4 * i];
#pragma unroll
            for (int j = 0; j < TN / 4; j++)
                *(float4*)&w[4 * j] = *(const float4*)&Ws[k][tx * TN + 4 * j];
#pragma unroll
            for (int i = 0; i < TM; i++)
#pragma unroll
                for (int j = 0; j < TN; j++) acc[i][j] += a[i] * w[j];
        }
        __syncthreads();
    }

#pragma unroll
    for (int i = 0; i < TM; i++) {
        int m = m0 + ty * TM + i;
#pragma unroll
        for (int j = 0; j < TN; j++) {
            int n = n0 + tx * TN + j;
            write_c<MODE>(acc[i][j], m, n, N, bias, out, co, ustr);
        }
    }
}

// ---------------------------------------------------------------------------
// Propagation kernels (unchanged from R6)
// ---------------------------------------------------------------------------
__global__ void propV_kernel(float4* __restrict__ V, const float4* __restrict__ U2,
                             int R4, int shU) {
    int v = blockIdx.y;
    int j = blockIdx.x * blockDim.x + threadIdx.x;
    float4 acc = make_float4(0.f, 0.f, 0.f, 0.f);
    int s = g_off[v], t = g_off[v + 1];
    for (int q = s; q < t; q++) {
        float w = g_cw[q];
        float4 x = U2[(size_t)(g_csrc[q] >> shU) * R4 + j];
        acc.x += w * x.x; acc.y += w * x.y; acc.z += w * x.z; acc.w += w * x.w;
    }
    V[(size_t)v * R4 + j] = acc;
}

__global__ void propF_kernel(float4* __restrict__ out, const float4* __restrict__ U0,
                             const float4* __restrict__ U1, const float4* __restrict__ V,
                             const float* __restrict__ bias, int R4, int comask, int shU) {
    int v = blockIdx.y;
    int j = blockIdx.x * blockDim.x + threadIdx.x;
    float4 acc = U0[(size_t)(v >> shU) * R4 + j];
    int s = g_off[v], t = g_off[v + 1];
    for (int q = s; q < t; q++) {
        float w = g_cw[q];
        int src = g_csrc[q];
        float4 a = U1[(size_t)(src >> shU) * R4 + j];
        float4 b = V[(size_t)src * R4 + j];
        acc.x += w * (a.x + 2.f * b.x);
        acc.y += w * (a.y + 2.f * b.y);
        acc.z += w * (a.z + 2.f * b.z);
        acc.w += w * (a.w + 2.f * b.w);
    }
    int c0 = (4 * j) & comask;
    float4 bb = *(const float4*)&bias[c0];
    acc.x += bb.x; acc.y += bb.y; acc.z += bb.z; acc.w += bb.w;
    acc.x = acc.x >= 0.f ? acc.x : LRELU_S * acc.x;
    acc.y = acc.y >= 0.f ? acc.y : LRELU_S * acc.y;
    acc.z = acc.z >= 0.f ? acc.z : LRELU_S * acc.z;
    acc.w = acc.w >= 0.f ? acc.w : LRELU_S * acc.w;
    out[(size_t)v * R4 + j] = acc;
}

__global__ void propF3_kernel(float* __restrict__ out, const float* __restrict__ U0,
                              const float* __restrict__ U1, const float* __restrict__ V,
                              const float* __restrict__ bias) {
    int v = blockIdx.y;
    int p = blockIdx.x * blockDim.x + threadIdx.x;   // < 384
    float acc = U0[(size_t)v * 384 + p];
    int s = g_off[v], t = g_off[v + 1];
    for (int q = s; q < t; q++) {
        size_t o = (size_t)g_csrc[q] * 384 + p;
        acc += g_cw[q] * (U1[o] + 2.f * V[o]);
    }
    out[(size_t)v * 384 + p] = acc + bias[p % 3];
}

__global__ void final_kernel(float* __restrict__ out, const float* __restrict__ h,
                             const void* __restrict__ perm) {
    int i = blockIdx.x * blockDim.x + threadIdx.x;
    const int TOT = 128 * 6890 * 3;
    if (i < TOT) {
        int b = i / (6890 * 3);
        int r = i - b * (6890 * 3);
        int u = r / 3;
        int k = r - u * 3;
        int v = read_idx(perm, u);
        out[i] = h[(size_t)(v * 128 + b) * 3 + k];
    }
}

// ---------------------------------------------------------------------------
extern "C" void kernel_launch(void* const* d_in, const int* in_sizes, int n_in,
                              void* d_out, int out_size) {
    const float* x   = (const float*)d_in[0];
    const float* fw1 = (const float*)d_in[1];
    const float* fb1 = (const float*)d_in[2];
    const float* fw2 = (const float*)d_in[3];
    const float* fb2 = (const float*)d_in[4];
    const float* W[5];
    const float* bb[5];
    for (int i = 0; i < 5; i++) {
        W[i]  = (const float*)d_in[5 + 2 * i];
        bb[i] = (const float*)d_in[6 + 2 * i];
    }
    const void* edges[4];
    for (int i = 0; i < 4; i++) edges[i] = d_in[15 + i];
    const void* perm = d_in[19];
    float* out = (float*)d_out;

    float *T, *OA, *OB, *H1, *WC;
    cudaGetSymbolAddress((void**)&T,  g_T);
    cudaGetSymbolAddress((void**)&OA, g_outA);
    cudaGetSymbolAddress((void**)&OB, g_outB);
    cudaGetSymbolAddress((void**)&H1, g_h1);
    cudaGetSymbolAddress((void**)&WC, g_wcat);

    const int ns[5]   = {864, 1728, 3456, 6912, 6912};
    const int cis[5]  = {128, 128, 64, 32, 16};
    const int cos_[5] = {128, 64, 32, 16, 3};
    const int eidx[5] = {0, 1, 2, 3, 3};
    const int egn[4]  = {864, 1728, 3456, 6912};

    // 0: FC1 (SIMT, tiny)
    gemm_k<128, 128, 8, 8, 1><<<dim3(4, 1), 256>>>(x, fw1, fb1, H1,
                                                   128, 512, 128, 0, 0);
    // 1: FC2 (mma): (128x512)@(512x110592)+b -> OA as (node,batch,ch)
    gemm_mma<2><<<dim3(110592 / 64, 1), 256>>>(H1, fw2, fb2, OA,
                                               128, 110592, 512, 0, 0);
    // 2: combined weights for layer 0
    wprep_kernel<<<(128 * 384 + 255) / 256, 256>>>(W[0], WC, 128, 128);
    // 3: layer-0 ChebConv GEMM (mma) — ncu capture target
    gemm_mma<3><<<dim3(6, 864), 256>>>(OA, WC, nullptr, T,
                                       110592, 384, 128, 128, 14155776LL);
    // 4: dtype sniff
    detect_kernel<<<1, 256>>>((const int*)edges[0], 5184);

    for (int l = 0; l < 5; l++) {
        int n  = ns[l];
        int ci = cis[l];
        int co = cos_[l];
        int N  = 3 * co;
        int ng = (l == 0 || l == 4) ? n : n / 2;   // layers 1-3 un-repeated
        int Mg = ng * 128;
        int shU = (l == 0 || l == 4) ? 0 : 1;
        int R4 = 32 * co;
        long long US = (long long)Mg * co;

        if (l > 0) {
            wprep_kernel<<<(ci * N + 255) / 256, 256>>>(W[l], WC, ci, co);
            if (l <= 2) {   // K = 128/64, mma path
                gemm_mma<3><<<dim3((N + 63) / 64, Mg / 128), 256>>>(
                    OA, WC, nullptr, T, Mg, N, ci, co, US);
            } else {        // K = 32/16, tiny: SIMT
                gemm_k<256, 64, 16, 4, 3><<<dim3((N + 63) / 64, Mg / 256), 256>>>(
                    OA, WC, nullptr, T, Mg, N, ci, co, US);
            }
        }

        if (l < 4) {   // layer 4 reuses layer 3's CSR
            const void* eg = edges[eidx[l]];
            int e = 6 * egn[eidx[l]];
            zero_cnt_kernel<<<(n + 255) / 256, 256>>>(n);
            count_kernel<<<(e + 255) / 256, 256>>>(eg, e);
            dinv_kernel<<<(n + 255) / 256, 256>>>(n);
            scan_kernel<<<1, 1024>>>(n);
            fill_kernel<<<(e + 255) / 256, 256>>>(eg, e);
        }

        propV_kernel<<<dim3(R4 >= 256 ? R4 / 256 : 1, n), R4 < 256 ? R4 : 256>>>(
            (float4*)OB, (const float4*)(T + 2 * US), R4, shU);
        if (l < 4) {
            propF_kernel<<<dim3(R4 / 256, n), 256>>>(
                (float4*)OA, (const float4*)T, (const float4*)(T + US),
                (const float4*)OB, bb[l], R4, co - 1, shU);
        } else {
            propF3_kernel<<<dim3(3, n), 128>>>(OA, T, T + US, OB, bb[4]);
        }
    }

    const int TOT = 128 * 6890 * 3;
    final_kernel<<<(TOT + 255) / 256, 256>>>(out, OA, perm);
}

// round 9
// speedup vs baseline: 5.8097x; 1.1758x over previous
#include <cuda_runtime.h>
#include <cuda_bf16.h>
#include <cstdint>

// ---------------------------------------------------------------------------
// ChebGcnDecoder, commuted form. GEMMs on mma.sync bf16 hi/lo 3-split.
// R9: conversions hoisted OUT of GEMMs (producers emit bf16 hi/lo directly),
// props compute Y = U1 + 2*P*U2 once so the final prop gathers one stream.
// Layout: (node, batch, channel) row-major everywhere.
// ---------------------------------------------------------------------------

#define LRELU_S 0.2f

__device__ float g_T[42467328];            // U0|U1|U2, stride Mg*co
__device__ float g_outA[14155776];         // fp32 layer output (l=3) / final
__device__ float g_Y[14155776];            // Y = U1 + 2*P*U2
__device__ __nv_bfloat16 g_Ah[14155776];   // bf16-hi GEMM input
__device__ __nv_bfloat16 g_Al[14155776];   // bf16-lo GEMM input
__device__ float g_h1[65536];              // FC1 output 128x512
__device__ float g_wc[49152];              // combined weights fp32 (K x N), L4
__device__ __nv_bfloat16 g_wth[49152];     // combined weights bf16-hi (Np x K)
__device__ __nv_bfloat16 g_wtl[49152];     // combined weights bf16-lo (Np x K)
__device__ int   g_cnt[6912];
__device__ float g_dinv[6912];
__device__ int   g_off[6913];
__device__ int   g_cur[6912];
__device__ int   g_csrc[41472];
__device__ float g_cw[41472];
__device__ int   g_is64;

// ---------------------------------------------------------------------------
__device__ __forceinline__ int read_idx(const void* p, int i) {
    if (g_is64) return (int)((const long long*)p)[i];
    return ((const int*)p)[i];
}

__global__ void detect_kernel(const int* w, int nwords) {
    __shared__ int any;
    if (threadIdx.x == 0) any = 0;
    __syncthreads();
    int a = 0;
    for (int i = 1 + 2 * (int)threadIdx.x; i < nwords; i += 2 * blockDim.x) a |= w[i];
    if (a) atomicOr(&any, 1);
    __syncthreads();
    if (threadIdx.x == 0) g_is64 = any ? 0 : 1;
}

__global__ void zero_cnt_kernel(int n) {
    int i = blockIdx.x * blockDim.x + threadIdx.x;
    if (i < n) g_cnt[i] = 0;
}
__global__ void count_kernel(const void* edges, int e) {
    int i = blockIdx.x * blockDim.x + threadIdx.x;
    if (i < e) atomicAdd(&g_cnt[read_idx(edges, e + i)], 1);
}
__global__ void dinv_kernel(int n) {
    int i = blockIdx.x * blockDim.x + threadIdx.x;
    if (i < n) g_dinv[i] = (g_cnt[i] > 0) ? rsqrtf((float)g_cnt[i]) : 0.0f;
}
__global__ void scan_kernel(int n) {
    __shared__ int partial[1024];
    int tid = threadIdx.x;
    int C = (n + 1023) / 1024;
    int start = tid * C;
    int local[8];
    int s = 0;
    for (int i = 0; i < C; i++) {
        int idx = start + i;
        int v = (idx < n) ? g_cnt[idx] : 0;
        local[i] = s;
        s += v;
    }
    partial[tid] = s;
    __syncthreads();
    for (int d = 1; d < 1024; d <<= 1) {
        int t = (tid >= d) ? partial[tid - d] : 0;
        __syncthreads();
        if (tid >= d) partial[tid] += t;
        __syncthreads();
    }
    int base = (tid > 0) ? partial[tid - 1] : 0;
    for (int i = 0; i < C; i++) {
        int idx = start + i;
        if (idx < n) {
            int o = base + local[i];
            g_off[idx] = o;
            g_cur[idx] = o;
        }
    }
    if (tid == 1023) g_off[n] = partial[1023];
}
__global__ void fill_kernel(const void* edges, int e) {
    int i = blockIdx.x * blockDim.x + threadIdx.x;
    if (i < e) {
        int s = read_idx(edges, i);
        int d = read_idx(edges, e + i);
        int p = atomicAdd(&g_cur[d], 1);
        g_csrc[p] = s;
        g_cw[p] = -g_dinv[s] * g_dinv[d];
    }
}

// Combined weights [W0-W2 | W1 | W2]: fp32 (K x N) for the SIMT path, plus
// bf16 hi/lo TRANSPOSED (Np x K, Np = N padded to 64) for the mma path.
__global__ void wprep_kernel(const float* __restrict__ W,
                             float* __restrict__ Wc,
                             __nv_bfloat16* __restrict__ Wth,
                             __nv_bfloat16* __restrict__ Wtl,
                             int ci, int co, int Np) {
    int i = blockIdx.x * blockDim.x + threadIdx.x;
    int N = 3 * co;
    if (i >= Np * ci) return;
    int n = i / ci, k = i - n * ci;
    int cico = ci * co;
    float v = 0.f;
    if (n < N) {
        if (n < co)            v = W[k * co + n] - W[2 * cico + k * co + n];
        else if (n < 2 * co)   v = W[cico + k * co + (n - co)];
        else                   v = W[2 * cico + k * co + (n - 2 * co)];
        Wc[k * N + n] = v;
    }
    __nv_bfloat16 h = __float2bfloat16(v);
    Wth[n * ci + k] = h;
    Wtl[n * ci + k] = __float2bfloat16(v - __bfloat162float(h));
}

// ---------------------------------------------------------------------------
__device__ __forceinline__ uint32_t smem_u32(const void* p) {
    uint32_t a;
    asm("{ .reg .u64 t; cvta.to.shared.u64 t, %1; cvt.u32.u64 %0, t; }"
        : "=r"(a) : "l"(p));
    return a;
}

#define LDSM_X4(r0, r1, r2, r3, a)                                            \
    asm volatile("ldmatrix.sync.aligned.m8n8.x4.shared.b16 {%0,%1,%2,%3}, [%4];" \
        : "=r"(r0), "=r"(r1), "=r"(r2), "=r"(r3) : "r"(a))

#define MMA4(c, a, b0, b1)                                                    \
    asm volatile(                                                             \
        "mma.sync.aligned.m16n8k16.row.col.f32.bf16.bf16.f32 "                \
        "{%0,%1,%2,%3}, {%4,%5,%6,%7}, {%8,%9}, {%0,%1,%2,%3};\n"             \
        : "+f"((c)[0]), "+f"((c)[1]), "+f"((c)[2]), "+f"((c)[3])              \
        : "r"((a)[0]), "r"((a)[1]), "r"((a)[2]), "r"((a)[3]),                 \
          "r"(b0), "r"(b1))

// ---------------------------------------------------------------------------
// bf16-input tensor GEMM: C(MxN) = A(MxK)@Wt^T, A/W pre-split hi/lo.
// Wt is (Np x K) row-major (transposed, zero-padded). BM=128, BN=64, KC chunk.
// Output: split write into U0|U1|U2 (t = n/co) at out + t*ustr (fp32).
// ---------------------------------------------------------------------------
template<int KC>
__global__ __launch_bounds__(256)
void gemm_mmab(const __nv_bfloat16* __restrict__ Ah, const __nv_bfloat16* __restrict__ Al,
               const __nv_bfloat16* __restrict__ Wh, const __nv_bfloat16* __restrict__ Wl,
               float* __restrict__ out, int M, int N, int K, int co, long long ustr) {
    __shared__ __align__(128) uint8_t sm[49152];
    char* smp = (char*)sm;
    const uint32_t sb = smem_u32(sm);
    const uint32_t oAh = 0, oAl = 16384, oBh = 32768, oBl = 40960;

    const int tid = threadIdx.x, lane = tid & 31, warp = tid >> 5;
    const int wm = warp & 3, wn = warp >> 2;
    const int m0 = blockIdx.y * 128, n0 = blockIdx.x * 64;

    float acc[2][4][4];
#pragma unroll
    for (int i = 0; i < 2; i++)
#pragma unroll
        for (int j = 0; j < 4; j++)
#pragma unroll
            for (int q = 0; q < 4; q++) acc[i][j][q] = 0.f;

    const uint32_t lq = lane >> 3, lr = lane & 7;
    const uint32_t qk = (lq >> 1) << 4;
    uint32_t aoff[2], asw[2], boff[2], bsw[2];
#pragma unroll
    for (int mt = 0; mt < 2; mt++) {
        int row = wm * 32 + mt * 16 + ((lq & 1) << 3) + lr;
        aoff[mt] = (uint32_t)row * 128;
        asw[mt] = (uint32_t)((row & 7) << 4);
    }
#pragma unroll
    for (int nt = 0; nt < 2; nt++) {
        int row = wn * 32 + nt * 16 + ((lq & 1) << 3) + lr;
        boff[nt] = (uint32_t)row * 128;
        bsw[nt] = (uint32_t)((row & 7) << 4);
    }

    const int nstages = K / KC;
    for (int s = 0; s < nstages; s++) {
        int k0 = s * KC;
        // ---- A tiles: 128 rows x KC bf16, hi+lo, SW128 ----
        constexpr int RPR = KC / 8;          // uint4 per row
#pragma unroll
        for (int r = 0; r < KC / 16; r++) {
            int idx = r * 256 + tid;
            int row = idx / RPR, c8 = idx % RPR;
            size_t go = (size_t)(m0 + row) * K + k0 + c8 * 8;
            uint4 vH = *(const uint4*)(Ah + go);
            uint4 vL = *(const uint4*)(Al + go);
            uint32_t so = (uint32_t)row * 128 + (((uint32_t)c8 * 16) ^ ((row & 7) << 4));
            *(uint4*)(smp + oAh + so) = vH;
            *(uint4*)(smp + oAl + so) = vL;
        }
        // ---- B tiles: 64 rows x KC bf16 from Wt (Np x K) ----
#pragma unroll
        for (int r = 0; r < KC / 32; r++) {
            int idx = r * 256 + tid;
            int row = idx / RPR, c8 = idx % RPR;
            size_t go = (size_t)(n0 + row) * K + k0 + c8 * 8;
            uint4 vH = *(const uint4*)(Wh + go);
            uint4 vL = *(const uint4*)(Wl + go);
            uint32_t so = (uint32_t)row * 128 + (((uint32_t)c8 * 16) ^ ((row & 7) << 4));
            *(uint4*)(smp + oBh + so) = vH;
            *(uint4*)(smp + oBl + so) = vL;
        }
        __syncthreads();

#pragma unroll
        for (int kk = 0; kk < KC / 16; kk++) {
            uint32_t cb = ((uint32_t)kk << 5) + qk;
            uint32_t ah[2][4], al[2][4], bh[2][4], bl[2][4];
#pragma unroll
            for (int mt = 0; mt < 2; mt++) {
                uint32_t ad = sb + oAh + aoff[mt] + (cb ^ asw[mt]);
                LDSM_X4(ah[mt][0], ah[mt][1], ah[mt][2], ah[mt][3], ad);
                LDSM_X4(al[mt][0], al[mt][1], al[mt][2], al[mt][3], ad + 16384);
            }
#pragma unroll
            for (int nt = 0; nt < 2; nt++) {
                uint32_t bd = sb + oBh + boff[nt] + (cb ^ bsw[nt]);
                LDSM_X4(bh[nt][0], bh[nt][1], bh[nt][2], bh[nt][3], bd);
                LDSM_X4(bl[nt][0], bl[nt][1], bl[nt][2], bl[nt][3], bd + 8192);
            }
#pragma unroll
            for (int mt = 0; mt < 2; mt++)
#pragma unroll
                for (int nt = 0; nt < 2; nt++)
#pragma unroll
                    for (int u = 0; u < 2; u++) {
                        int nf = nt * 2 + u;
                        MMA4(acc[mt][nf], ah[mt], bh[nt][u], bh[nt][u + 2]);
                        MMA4(acc[mt][nf], ah[mt], bl[nt][u], bl[nt][u + 2]);
                        MMA4(acc[mt][nf], al[mt], bh[nt][u], bh[nt][u + 2]);
                    }
        }
        __syncthreads();
    }

#pragma unroll
    for (int mt = 0; mt < 2; mt++)
#pragma unroll
        for (int nf = 0; nf < 4; nf++) {
            int mrow = m0 + wm * 32 + mt * 16 + (lane >> 2);
            int ncol = n0 + wn * 32 + (nf >> 1) * 16 + (nf & 1) * 8 + 2 * (lane & 3);
#pragma unroll
            for (int e = 0; e < 4; e++) {
                int m = mrow + (e >> 1) * 8;
                int n = ncol + (e & 1);
                if (n < N) {
                    int t = n / co;
                    out[(size_t)t * (size_t)ustr + (size_t)m * co + (n - t * co)] =
                        acc[mt][nf][e];
                }
            }
        }
}

// ---------------------------------------------------------------------------
// fp32-input mma GEMM (FC2 only): in-kernel bf16 split of A and W.
// Epilogue: bias, then hi/lo bf16 split written to (node,batch,ch) layout.
// ---------------------------------------------------------------------------
__global__ __launch_bounds__(256)
void gemm_mma_fc2(const float* __restrict__ A, const float* __restrict__ W,
                  const float* __restrict__ bias,
                  __nv_bfloat16* __restrict__ outh, __nv_bfloat16* __restrict__ outl,
                  int M, int N, int K) {
    __shared__ __align__(128) uint8_t sm[49152];
    char* smp = (char*)sm;
    const uint32_t sb = smem_u32(sm);
    const uint32_t oAh = 0, oAl = 16384, oBh = 32768, oBl = 40960;

    const int tid = threadIdx.x, lane = tid & 31, warp = tid >> 5;
    const int wm = warp & 3, wn = warp >> 2;
    const int m0 = blockIdx.y * 128, n0 = blockIdx.x * 64;

    float acc[2][4][4];
#pragma unroll
    for (int i = 0; i < 2; i++)
#pragma unroll
        for (int j = 0; j < 4; j++)
#pragma unroll
            for (int q = 0; q < 4; q++) acc[i][j][q] = 0.f;

    const uint32_t lq = lane >> 3, lr = lane & 7;
    const uint32_t qk = (lq >> 1) << 4;
    uint32_t aoff[2], asw[2], boff[2], bsw[2];
#pragma unroll
    for (int mt = 0; mt < 2; mt++) {
        int row = wm * 32 + mt * 16 + ((lq & 1) << 3) + lr;
        aoff[mt] = (uint32_t)row * 128;
        asw[mt] = (uint32_t)((row & 7) << 4);
    }
#pragma unroll
    for (int nt = 0; nt < 2; nt++) {
        int row = wn * 32 + nt * 16 + ((lq & 1) << 3) + lr;
        boff[nt] = (uint32_t)row * 128;
        bsw[nt] = (uint32_t)((row & 7) << 4);
    }

    const int arow = tid >> 1, ahalf = tid & 1;
    const uint32_t arstore = (uint32_t)arow * 128;
    const uint32_t arswst = (uint32_t)((arow & 7) << 4);

    const int nstages = K >> 6;
    for (int s = 0; s < nstages; s++) {
        int k0 = s << 6;
        {
            const float* ap = A + (size_t)(m0 + arow) * K + k0 + ahalf * 32;
            uint32_t cb0 = (uint32_t)(ahalf * 64);
#pragma unroll
            for (int q = 0; q < 8; q++) {
                float4 v = *(const float4*)(ap + 4 * q);
                __nv_bfloat162 h0, l0, h1, l1;
                h0.x = __float2bfloat16(v.x);
                l0.x = __float2bfloat16(v.x - __bfloat162float(h0.x));
                h0.y = __float2bfloat16(v.y);
                l0.y = __float2bfloat16(v.y - __bfloat162float(h0.y));
                h1.x = __float2bfloat16(v.z);
                l1.x = __float2bfloat16(v.z - __bfloat162float(h1.x));
                h1.y = __float2bfloat16(v.w);
                l1.y = __float2bfloat16(v.w - __bfloat162float(h1.y));
                uint32_t o = arstore + ((cb0 + 8 * q) ^ arswst);
                *(__nv_bfloat162*)(smp + oAh + o)     = h0;
                *(__nv_bfloat162*)(smp + oAh + o + 4) = h1;
                *(__nv_bfloat162*)(smp + oAl + o)     = l0;
                *(__nv_bfloat162*)(smp + oAl + o + 4) = l1;
            }
        }
#pragma unroll
        for (int r = 0; r < 8; r++) {
            int linear = r * 256 + tid;
            int kp = linear >> 6;
            int nn = linear & 63;
            int gn = n0 + nn;
            float w0 = 0.f, w1 = 0.f;
            if (gn < N) {
                w0 = W[(size_t)(k0 + 2 * kp) * N + gn];
                w1 = W[(size_t)(k0 + 2 * kp + 1) * N + gn];
            }
            __nv_bfloat162 h, l;
            h.x = __float2bfloat16(w0);
            l.x = __float2bfloat16(w0 - __bfloat162float(h.x));
            h.y = __float2bfloat16(w1);
            l.y = __float2bfloat16(w1 - __bfloat162float(h.y));
            uint32_t o = (uint32_t)nn * 128 + (((uint32_t)(4 * kp)) ^ ((nn & 7) << 4));
            *(__nv_bfloat162*)(smp + oBh + o) = h;
            *(__nv_bfloat162*)(smp + oBl + o) = l;
        }
        __syncthreads();

#pragma unroll
        for (int kk = 0; kk < 4; kk++) {
            uint32_t cb = ((uint32_t)kk << 5) + qk;
            uint32_t ah[2][4], al[2][4], bh[2][4], bl[2][4];
#pragma unroll
            for (int mt = 0; mt < 2; mt++) {
                uint32_t ad = sb + oAh + aoff[mt] + (cb ^ asw[mt]);
                LDSM_X4(ah[mt][0], ah[mt][1], ah[mt][2], ah[mt][3], ad);
                LDSM_X4(al[mt][0], al[mt][1], al[mt][2], al[mt][3], ad + 16384);
            }
#pragma unroll
            for (int nt = 0; nt < 2; nt++) {
                uint32_t bd = sb + oBh + boff[nt] + (cb ^ bsw[nt]);
                LDSM_X4(bh[nt][0], bh[nt][1], bh[nt][2], bh[nt][3], bd);
                LDSM_X4(bl[nt][0], bl[nt][1], bl[nt][2], bl[nt][3], bd + 8192);
            }
#pragma unroll
            for (int mt = 0; mt < 2; mt++)
#pragma unroll
                for (int nt = 0; nt < 2; nt++)
#pragma unroll
                    for (int u = 0; u < 2; u++) {
                        int nf = nt * 2 + u;
                        MMA4(acc[mt][nf], ah[mt], bh[nt][u], bh[nt][u + 2]);
                        MMA4(acc[mt][nf], ah[mt], bl[nt][u], bl[nt][u + 2]);
                        MMA4(acc[mt][nf], al[mt], bh[nt][u], bh[nt][u + 2]);
                    }
        }
        __syncthreads();
    }

#pragma unroll
    for (int mt = 0; mt < 2; mt++)
#pragma unroll
        for (int nf = 0; nf < 4; nf++) {
            int mrow = m0 + wm * 32 + mt * 16 + (lane >> 2);
            int ncol = n0 + wn * 32 + (nf >> 1) * 16 + (nf & 1) * 8 + 2 * (lane & 3);
#pragma unroll
            for (int e = 0; e < 4; e++) {
                int m = mrow + (e >> 1) * 8;
                int n = ncol + (e & 1);
                if (n < N) {
                    float v = acc[mt][nf][e] + bias[n];
                    __nv_bfloat16 h = __float2bfloat16(v);
                    size_t o = (size_t)((n >> 7) * 128 + m) * 128 + (n & 127);
                    outh[o] = h;
                    outl[o] = __float2bfloat16(v - __bfloat162float(h));
                }
            }
        }
}

// ---------------------------------------------------------------------------
// SIMT fp32 GEMM for FC1 (MODE 1) and L4 (MODE 3).
// ---------------------------------------------------------------------------
template<int BM, int BN, int TM, int TN, int MODE>
__global__ __launch_bounds__(256)
void gemm_k(const float* __restrict__ A, const float* __restrict__ W,
            const float* __restrict__ bias, float* __restrict__ out,
            int M, int N, int K, int co, long long ustr) {
    __shared__ float As[16][BM + 4];
    __shared__ float Ws[16][BN + 4];
    const int tid = threadIdx.x;
    const int tx = tid & 15, ty = tid >> 4;
    const int m0 = blockIdx.y * BM, n0 = blockIdx.x * BN;

    float acc[TM][TN];
#pragma unroll
    for (int i = 0; i < TM; i++)
#pragma unroll
        for (int j = 0; j < TN; j++) acc[i][j] = 0.0f;

    for (int k0 = 0; k0 < K; k0 += 16) {
#pragma unroll
        for (int r = 0; r < BM / 64; r++) {
            int lid = tid + r * 256;
            int row = lid >> 2;
            int kq = (lid & 3) << 2;
            float4 a = *(const float4*)(A + (size_t)(m0 + row) * K + (k0 + kq));
            As[kq + 0][row] = a.x;
            As[kq + 1][row] = a.y;
            As[kq + 2][row] = a.z;
            As[kq + 3][row] = a.w;
        }
#pragma unroll
        for (int r = 0; r < BN / 64; r++) {
            int lid = tid + r * 256;
            int k = lid / (BN / 4);
            int n4 = (lid % (BN / 4)) * 4;
            int gc = n0 + n4;
            float4 w;
            if (((N & 3) == 0) && gc + 4 <= N) {
                w = *(const float4*)(W + (size_t)(k0 + k) * N + gc);
            } else {
                w.x = (gc + 0 < N) ? W[(size_t)(k0 + k) * N + gc + 0] : 0.f;
                w.y = (gc + 1 < N) ? W[(size_t)(k0 + k) * N + gc + 1] : 0.f;
                w.z = (gc + 2 < N) ? W[(size_t)(k0 + k) * N + gc + 2] : 0.f;
                w.w = (gc + 3 < N) ? W[(size_t)(k0 + k) * N + gc + 3] : 0.f;
            }
            *(float4*)&Ws[k][n4] = w;
        }
        __syncthreads();

#pragma unroll
        for (int k = 0; k < 16; k++) {
            float a[TM], w[TN];
#pragma unroll
            for (int i = 0; i < TM / 4; i++)
                *(float4*)&a[4 * i] = *(const float4*)&As[k][ty * TM + 4 * i];
#pragma unroll
            for (int j = 0; j < TN / 4; j++)
                *(float4*)&w[4 * j] = *(const float4*)&Ws[k][tx * TN + 4 * j];
#pragma unroll
            for (int i = 0; i < TM; i++)
#pragma unroll
                for (int j = 0; j < TN; j++) acc[i][j] += a[i] * w[j];
        }
        __syncthreads();
    }

#pragma unroll
    for (int i = 0; i < TM; i++) {
        int m = m0 + ty * TM + i;
#pragma unroll
        for (int j = 0; j < TN; j++) {
            int n = n0 + tx * TN + j;
            if (n >= N) continue;
            float v = acc[i][j];
            if (MODE == 1) {
                v += bias[n];
                v = v > 0.f ? v : 0.f;
                out[(size_t)m * N + n] = v;
            } else {
                int t = n / co;
                out[(size_t)t * (size_t)ustr + (size_t)m * co + (n - t * co)] = v;
            }
        }
    }
}

// ---------------------------------------------------------------------------
// Props with Y-fusion:  Y[v] = U1[v>>shU] + 2 * sum_e w * U2[src>>shU]
//                       out[v] = act( U0[v>>shU] + sum_e w * Y[src] + bias )
// ---------------------------------------------------------------------------
__global__ void propY_kernel(float4* __restrict__ Y, const float4* __restrict__ U1,
                             const float4* __restrict__ U2, int R4, int shU) {
    int v = blockIdx.y;
    int j = blockIdx.x * blockDim.x + threadIdx.x;
    float4 acc = make_float4(0.f, 0.f, 0.f, 0.f);
    int s = g_off[v], t = g_off[v + 1];
    for (int q = s; q < t; q++) {
        float w = g_cw[q];
        float4 x = U2[(size_t)(g_csrc[q] >> shU) * R4 + j];
        acc.x += w * x.x; acc.y += w * x.y; acc.z += w * x.z; acc.w += w * x.w;
    }
    float4 u1 = U1[(size_t)(v >> shU) * R4 + j];
    acc.x = u1.x + 2.f * acc.x;
    acc.y = u1.y + 2.f * acc.y;
    acc.z = u1.z + 2.f * acc.z;
    acc.w = u1.w + 2.f * acc.w;
    Y[(size_t)v * R4 + j] = acc;
}

// OUTF: 0 -> fp32 out; 1 -> bf16 hi/lo split (feeds next mma GEMM)
template<int OUTF>
__global__ void propF_kernel(float* __restrict__ outf,
                             __nv_bfloat16* __restrict__ outh,
                             __nv_bfloat16* __restrict__ outl,
                             const float4* __restrict__ U0, const float4* __restrict__ Y,
                             const float* __restrict__ bias, int R4, int comask, int shU) {
    int v = blockIdx.y;
    int j = blockIdx.x * blockDim.x + threadIdx.x;
    float4 acc = U0[(size_t)(v >> shU) * R4 + j];
    int s = g_off[v], t = g_off[v + 1];
    for (int q = s; q < t; q++) {
        float w = g_cw[q];
        float4 y = Y[(size_t)g_csrc[q] * R4 + j];
        acc.x += w * y.x; acc.y += w * y.y; acc.z += w * y.z; acc.w += w * y.w;
    }
    int c0 = (4 * j) & comask;
    float4 bb = *(const float4*)&bias[c0];
    acc.x += bb.x; acc.y += bb.y; acc.z += bb.z; acc.w += bb.w;
    acc.x = acc.x >= 0.f ? acc.x : LRELU_S * acc.x;
    acc.y = acc.y >= 0.f ? acc.y : LRELU_S * acc.y;
    acc.z = acc.z >= 0.f ? acc.z : LRELU_S * acc.z;
    acc.w = acc.w >= 0.f ? acc.w : LRELU_S * acc.w;
    if (OUTF == 0) {
        ((float4*)outf)[(size_t)v * R4 + j] = acc;
    } else {
        size_t o = (size_t)v * R4 * 4 + 4 * j;
        __nv_bfloat16 h[4], l[4];
        float vv[4] = {acc.x, acc.y, acc.z, acc.w};
#pragma unroll
        for (int e = 0; e < 4; e++) {
            h[e] = __float2bfloat16(vv[e]);
            l[e] = __float2bfloat16(vv[e] - __bfloat162float(h[e]));
        }
        *(uint2*)(outh + o) = *(uint2*)h;
        *(uint2*)(outl + o) = *(uint2*)l;
    }
}

// Last layer: co=3, scalar. out[v*384+p] = U0 + sum w*Y[src] + bias
__global__ void propF3_kernel(float* __restrict__ out, const float* __restrict__ U0,
                              const float* __restrict__ Y,
                              const float* __restrict__ bias) {
    int v = blockIdx.y;
    int p = blockIdx.x * blockDim.x + threadIdx.x;   // < 384
    float acc = U0[(size_t)v * 384 + p];
    int s = g_off[v], t = g_off[v + 1];
    for (int q = s; q < t; q++)
        acc += g_cw[q] * Y[(size_t)g_csrc[q] * 384 + p];
    out[(size_t)v * 384 + p] = acc + bias[p % 3];
}

__global__ void final_kernel(float* __restrict__ out, const float* __restrict__ h,
                             const void* __restrict__ perm) {
    int i = blockIdx.x * blockDim.x + threadIdx.x;
    const int TOT = 128 * 6890 * 3;
    if (i < TOT) {
        int b = i / (6890 * 3);
        int r = i - b * (6890 * 3);
        int u = r / 3;
        int k = r - u * 3;
        int v = read_idx(perm, u);
        out[i] = h[(size_t)(v * 128 + b) * 3 + k];
    }
}

// ---------------------------------------------------------------------------
extern "C" void kernel_launch(void* const* d_in, const int* in_sizes, int n_in,
                              void* d_out, int out_size) {
    const float* x   = (const float*)d_in[0];
    const float* fw1 = (const float*)d_in[1];
    const float* fb1 = (const float*)d_in[2];
    const float* fw2 = (const float*)d_in[3];
    const float* fb2 = (const float*)d_in[4];
    const float* W[5];
    const float* bb[5];
    for (int i = 0; i < 5; i++) {
        W[i]  = (const float*)d_in[5 + 2 * i];
        bb[i] = (const float*)d_in[6 + 2 * i];
    }
    const void* edges[4];
    for (int i = 0; i < 4; i++) edges[i] = d_in[15 + i];
    const void* perm = d_in[19];
    float* out = (float*)d_out;

    float *T, *OA, *YB, *H1, *WC;
    __nv_bfloat16 *AH, *AL, *WTH, *WTL;
    cudaGetSymbolAddress((void**)&T,   g_T);
    cudaGetSymbolAddress((void**)&OA,  g_outA);
    cudaGetSymbolAddress((void**)&YB,  g_Y);
    cudaGetSymbolAddress((void**)&H1,  g_h1);
    cudaGetSymbolAddress((void**)&WC,  g_wc);
    cudaGetSymbolAddress((void**)&AH,  g_Ah);
    cudaGetSymbolAddress((void**)&AL,  g_Al);
    cudaGetSymbolAddress((void**)&WTH, g_wth);
    cudaGetSymbolAddress((void**)&WTL, g_wtl);

    const int ns[5]   = {864, 1728, 3456, 6912, 6912};
    const int cis[5]  = {128, 128, 64, 32, 16};
    const int cos_[5] = {128, 64, 32, 16, 3};
    const int eidx[5] = {0, 1, 2, 3, 3};
    const int egn[4]  = {864, 1728, 3456, 6912};

    // 0: FC1 (SIMT)
    gemm_k<128, 128, 8, 8, 1><<<dim3(4, 1), 256>>>(x, fw1, fb1, H1,
                                                   128, 512, 128, 0, 0);
    // 1: FC2 (mma, fp32-in, bf16-split out into AH/AL as (node,batch,ch))
    gemm_mma_fc2<<<dim3(110592 / 64, 1), 256>>>(H1, fw2, fb2, AH, AL,
                                                128, 110592, 512);
    // 2: combined weights for layer 0 (Np = 384)
    wprep_kernel<<<(384 * 128 + 255) / 256, 256>>>(W[0], WC, WTH, WTL, 128, 128, 384);
    // 3: layer-0 ChebConv GEMM (bf16-in) — ncu capture target
    gemm_mmab<64><<<dim3(6, 864), 256>>>(AH, AL, WTH, WTL, T,
                                         110592, 384, 128, 128, 14155776LL);
    // 4: dtype sniff
    detect_kernel<<<1, 256>>>((const int*)edges[0], 5184);

    for (int l = 0; l < 5; l++) {
        int n  = ns[l];
        int ci = cis[l];
        int co = cos_[l];
        int N  = 3 * co;
        int Np = ((N + 63) / 64) * 64;
        int ng = (l == 0 || l == 4) ? n : n / 2;   // layers 1-3 un-repeated
        int Mg = ng * 128;
        int shU = (l == 0 || l == 4) ? 0 : 1;
        int R4 = 32 * co;
        long long US = (long long)Mg * co;

        if (l > 0) {
            wprep_kernel<<<(Np * ci + 255) / 256, 256>>>(W[l], WC, WTH, WTL,
                                                         ci, co, Np);
            if (l < 4) {   // mma path (K = 64, 32, 32)
                if (ci == 64)
                    gemm_mmab<64><<<dim3(Np / 64, Mg / 128), 256>>>(
                        AH, AL, WTH, WTL, T, Mg, N, ci, co, US);
                else
                    gemm_mmab<32><<<dim3(Np / 64, Mg / 128), 256>>>(
                        AH, AL, WTH, WTL, T, Mg, N, ci, co, US);
            } else {       // L4: K=16, SIMT
                gemm_k<256, 64, 16, 4, 3><<<dim3(1, Mg / 256), 256>>>(
                    OA, WC, nullptr, T, Mg, N, ci, co, US);
            }
        }

        if (l < 4) {   // layer 4 reuses layer 3's CSR
            const void* eg = edges[eidx[l]];
            int e = 6 * egn[eidx[l]];
            zero_cnt_kernel<<<(n + 255) / 256, 256>>>(n);
            count_kernel<<<(e + 255) / 256, 256>>>(eg, e);
            dinv_kernel<<<(n + 255) / 256, 256>>>(n);
            scan_kernel<<<1, 1024>>>(n);
            fill_kernel<<<(e + 255) / 256, 256>>>(eg, e);
        }

        // Y = U1' + 2*P*U2'
        propY_kernel<<<dim3(R4 >= 256 ? R4 / 256 : 1, n), R4 < 256 ? R4 : 256>>>(
            (float4*)YB, (const float4*)(T + US), (const float4*)(T + 2 * US),
            R4, shU);
        // out = act(U0' + P*Y + b)
        if (l < 3) {
            propF_kernel<1><<<dim3(R4 / 256, n), 256>>>(
                nullptr, AH, AL, (const float4*)T, (const float4*)YB,
                bb[l], R4, co - 1, shU);
        } else if (l == 3) {
            propF_kernel<0><<<dim3(R4 / 256, n), 256>>>(
                OA, nullptr, nullptr, (const float4*)T, (const float4*)YB,
                bb[l], R4, co - 1, shU);
        } else {
            propF3_kernel<<<dim3(3, n), 128>>>(OA, T, YB, bb[4]);
        }
    }

    const int TOT = 128 * 6890 * 3;
    final_kernel<<<(TOT + 255) / 256, 256>>>(out, OA, perm);
}

// round 10
// speedup vs baseline: 6.6925x; 1.1520x over previous
#include <cuda_runtime.h>
#include <cuda_bf16.h>
#include <cstdint>

// ---------------------------------------------------------------------------
// ChebGcnDecoder, commuted form. All big GEMMs on mma.sync bf16 hi/lo 3-split
// with pre-split bf16 inputs (no in-loop conversion anywhere). CSR build for
// all 4 graphs fused into 5 launches over concatenated arrays.
// Layout: (node, batch, channel) row-major everywhere.
// ---------------------------------------------------------------------------

#define LRELU_S 0.2f

// Node bases over layers 0..3: [0, 864, 2592, 6048], total 12960.
// Edge bases: [0, 5184, 15552, 36288], total 77760.
__device__ float g_T[42467328];            // U0|U1|U2, stride Mg*co
__device__ float g_outA[14155776];         // fp32 layer output (l=3)
__device__ float g_Y[14155776];            // Y = U1 + 2*P*U2
__device__ __nv_bfloat16 g_Ah[14155776];   // bf16-hi GEMM input (activations)
__device__ __nv_bfloat16 g_Al[14155776];   // bf16-lo
__device__ __nv_bfloat16 g_w2h[56623104];  // fc_w2 transposed+split (N x K)
__device__ __nv_bfloat16 g_w2l[56623104];
__device__ float g_h1[65536];              // FC1 output 128x512 fp32
__device__ __nv_bfloat16 g_h1h[65536];
__device__ __nv_bfloat16 g_h1l[65536];
__device__ float g_wc[49152];              // combined weights fp32 (K x N), L4
__device__ __nv_bfloat16 g_wth[49152];     // combined weights bf16-hi (Np x K)
__device__ __nv_bfloat16 g_wtl[49152];
__device__ int   g_cnt[12960];
__device__ float g_dinv[12960];
__device__ int   g_off[12961];
__device__ int   g_cur[12960];
__device__ int   g_csrc[77760];
__device__ float g_cw[77760];
__device__ int   g_is64;

__constant__ int c_nb[4] = {0, 864, 2592, 6048};
__constant__ int c_eb[4] = {0, 5184, 15552, 36288};
__constant__ int c_nl[4] = {864, 1728, 3456, 6912};

// ---------------------------------------------------------------------------
__device__ __forceinline__ int read_idx(const void* p, int i) {
    if (g_is64) return (int)((const long long*)p)[i];
    return ((const int*)p)[i];
}

__global__ void detect_kernel(const int* w, int nwords) {
    __shared__ int any;
    if (threadIdx.x == 0) any = 0;
    __syncthreads();
    int a = 0;
    for (int i = 1 + 2 * (int)threadIdx.x; i < nwords; i += 2 * blockDim.x) a |= w[i];
    if (a) atomicOr(&any, 1);
    __syncthreads();
    if (threadIdx.x == 0) g_is64 = any ? 0 : 1;
}

// ---- fused CSR build over all 4 graphs ----
__global__ void csr_zero_kernel() {
    int i = blockIdx.x * blockDim.x + threadIdx.x;
    if (i < 12960) g_cnt[i] = 0;
}

__global__ void csr_count_kernel(const void* e0, const void* e1,
                                 const void* e2, const void* e3) {
    int l = blockIdx.y;
    const void* eg = (l == 0) ? e0 : (l == 1) ? e1 : (l == 2) ? e2 : e3;
    int e = 6 * c_nl[l];
    int i = blockIdx.x * blockDim.x + threadIdx.x;
    if (i < e) atomicAdd(&g_cnt[c_nb[l] + read_idx(eg, e + i)], 1);
}

__global__ void csr_dinv_kernel() {
    int i = blockIdx.x * blockDim.x + threadIdx.x;
    if (i < 12960) g_dinv[i] = (g_cnt[i] > 0) ? rsqrtf((float)g_cnt[i]) : 0.0f;
}

__global__ void csr_scan_kernel() {
    __shared__ int partial[1024];
    int l = blockIdx.x;
    int n = c_nl[l], nb = c_nb[l], eb = c_eb[l];
    int tid = threadIdx.x;
    int C = (n + 1023) / 1024;
    int start = tid * C;
    int local[8];
    int s = 0;
    for (int i = 0; i < C; i++) {
        int idx = start + i;
        int v = (idx < n) ? g_cnt[nb + idx] : 0;
        local[i] = s;
        s += v;
    }
    partial[tid] = s;
    __syncthreads();
    for (int d = 1; d < 1024; d <<= 1) {
        int t = (tid >= d) ? partial[tid - d] : 0;
        __syncthreads();
        if (tid >= d) partial[tid] += t;
        __syncthreads();
    }
    int base = (tid > 0) ? partial[tid - 1] : 0;
    for (int i = 0; i < C; i++) {
        int idx = start + i;
        if (idx < n) {
            int o = eb + base + local[i];
            g_off[nb + idx] = o;
            g_cur[nb + idx] = o;
        }
    }
    if (l == 3 && tid == 1023) g_off[12960] = 77760;
}

__global__ void csr_fill_kernel(const void* e0, const void* e1,
                                const void* e2, const void* e3) {
    int l = blockIdx.y;
    const void* eg = (l == 0) ? e0 : (l == 1) ? e1 : (l == 2) ? e2 : e3;
    int e = 6 * c_nl[l];
    int nb = c_nb[l];
    int i = blockIdx.x * blockDim.x + threadIdx.x;
    if (i < e) {
        int s = read_idx(eg, i);
        int d = read_idx(eg, e + i);
        int p = atomicAdd(&g_cur[nb + d], 1);
        g_csrc[p] = s;
        g_cw[p] = -g_dinv[nb + s] * g_dinv[nb + d];
    }
}

// Combined weights [W0-W2 | W1 | W2]: fp32 (K x N) for SIMT L4, bf16 hi/lo
// transposed (Np x K) for the mma path. Factor 2 on P^2 applied in props.
__global__ void wprep_kernel(const float* __restrict__ W,
                             float* __restrict__ Wc,
                             __nv_bfloat16* __restrict__ Wth,
                             __nv_bfloat16* __restrict__ Wtl,
                             int ci, int co, int Np) {
    int i = blockIdx.x * blockDim.x + threadIdx.x;
    int N = 3 * co;
    if (i >= Np * ci) return;
    int n = i / ci, k = i - n * ci;
    int cico = ci * co;
    float v = 0.f;
    if (n < N) {
        if (n < co)            v = W[k * co + n] - W[2 * cico + k * co + n];
        else if (n < 2 * co)   v = W[cico + k * co + (n - co)];
        else                   v = W[2 * cico + k * co + (n - 2 * co)];
        Wc[k * N + n] = v;
    }
    __nv_bfloat16 h = __float2bfloat16(v);
    Wth[n * ci + k] = h;
    Wtl[n * ci + k] = __float2bfloat16(v - __bfloat162float(h));
}

// fc_w2 (K=512 x N=110592) fp32 -> transposed (N x K) bf16 hi/lo.
__global__ void tsplit_kernel(const float* __restrict__ in,
                              __nv_bfloat16* __restrict__ outh,
                              __nv_bfloat16* __restrict__ outl) {
    __shared__ float t[32][33];
    const int N = 110592, K = 512;
    int n0 = blockIdx.x * 32, k0 = blockIdx.y * 32;
    int tx = threadIdx.x, ty = threadIdx.y;
#pragma unroll
    for (int i = 0; i < 4; i++)
        t[ty + 8 * i][tx] = in[(size_t)(k0 + ty + 8 * i) * N + n0 + tx];
    __syncthreads();
#pragma unroll
    for (int i = 0; i < 4; i++) {
        float v = t[tx][ty + 8 * i];
        __nv_bfloat16 h = __float2bfloat16(v);
        size_t o = (size_t)(n0 + ty + 8 * i) * K + k0 + tx;
        outh[o] = h;
        outl[o] = __float2bfloat16(v - __bfloat162float(h));
    }
}

// split FC1 output (128x512) into bf16 hi/lo
__global__ void hsplit_kernel(const float* __restrict__ in,
                              __nv_bfloat16* __restrict__ outh,
                              __nv_bfloat16* __restrict__ outl) {
    int i = blockIdx.x * blockDim.x + threadIdx.x;
    if (i < 65536) {
        float v = in[i];
        __nv_bfloat16 h = __float2bfloat16(v);
        outh[i] = h;
        outl[i] = __float2bfloat16(v - __bfloat162float(h));
    }
}

// ---------------------------------------------------------------------------
__device__ __forceinline__ uint32_t smem_u32(const void* p) {
    uint32_t a;
    asm("{ .reg .u64 t; cvta.to.shared.u64 t, %1; cvt.u32.u64 %0, t; }"
        : "=r"(a) : "l"(p));
    return a;
}

#define LDSM_X4(r0, r1, r2, r3, a)                                            \
    asm volatile("ldmatrix.sync.aligned.m8n8.x4.shared.b16 {%0,%1,%2,%3}, [%4];" \
        : "=r"(r0), "=r"(r1), "=r"(r2), "=r"(r3) : "r"(a))

#define MMA4(c, a, b0, b1)                                                    \
    asm volatile(                                                             \
        "mma.sync.aligned.m16n8k16.row.col.f32.bf16.bf16.f32 "                \
        "{%0,%1,%2,%3}, {%4,%5,%6,%7}, {%8,%9}, {%0,%1,%2,%3};\n"             \
        : "+f"((c)[0]), "+f"((c)[1]), "+f"((c)[2]), "+f"((c)[3])              \
        : "r"((a)[0]), "r"((a)[1]), "r"((a)[2]), "r"((a)[3]),                 \
          "r"(b0), "r"(b1))

// ---------------------------------------------------------------------------
// bf16-input tensor GEMM: C(MxN) = A(MxK)@Wt^T, everything pre-split hi/lo.
// Wt is (Np x K) row-major. BM=128, BN=64, KC chunk. M%128==0, K%KC==0.
// EPI 0: split write into U0|U1|U2 (t = n>>coLog2) at out + t*ustr (fp32).
// EPI 1: FC2: bias add, bf16 hi/lo split write to (node,batch,ch) layout.
// ---------------------------------------------------------------------------
template<int KC, int EPI>
__global__ __launch_bounds__(256)
void gemm_mmab(const __nv_bfloat16* __restrict__ Ah, const __nv_bfloat16* __restrict__ Al,
               const __nv_bfloat16* __restrict__ Wh, const __nv_bfloat16* __restrict__ Wl,
               const float* __restrict__ bias, float* __restrict__ out,
               __nv_bfloat16* __restrict__ outh, __nv_bfloat16* __restrict__ outl,
               int M, int N, int K, int coLog2, long long ustr) {
    __shared__ __align__(128) uint8_t sm[49152];
    char* smp = (char*)sm;
    const uint32_t sb = smem_u32(sm);
    const uint32_t oAh = 0, oAl = 16384, oBh = 32768, oBl = 40960;

    const int tid = threadIdx.x, lane = tid & 31, warp = tid >> 5;
    const int wm = warp & 3, wn = warp >> 2;
    const int m0 = blockIdx.y * 128, n0 = blockIdx.x * 64;

    float acc[2][4][4];
#pragma unroll
    for (int i = 0; i < 2; i++)
#pragma unroll
        for (int j = 0; j < 4; j++)
#pragma unroll
            for (int q = 0; q < 4; q++) acc[i][j][q] = 0.f;

    const uint32_t lq = lane >> 3, lr = lane & 7;
    const uint32_t qk = (lq >> 1) << 4;
    uint32_t aoff[2], asw[2], boff[2], bsw[2];
#pragma unroll
    for (int mt = 0; mt < 2; mt++) {
        int row = wm * 32 + mt * 16 + ((lq & 1) << 3) + lr;
        aoff[mt] = (uint32_t)row * 128;
        asw[mt] = (uint32_t)((row & 7) << 4);
    }
#pragma unroll
    for (int nt = 0; nt < 2; nt++) {
        int row = wn * 32 + nt * 16 + ((lq & 1) << 3) + lr;
        boff[nt] = (uint32_t)row * 128;
        bsw[nt] = (uint32_t)((row & 7) << 4);
    }

    const int nstages = K / KC;
    for (int s = 0; s < nstages; s++) {
        int k0 = s * KC;
        constexpr int RPR = KC / 8;          // uint4 per row
#pragma unroll
        for (int r = 0; r < KC / 16; r++) {
            int idx = r * 256 + tid;
            int row = idx / RPR, c8 = idx % RPR;
            size_t go = (size_t)(m0 + row) * K + k0 + c8 * 8;
            uint4 vH = *(const uint4*)(Ah + go);
            uint4 vL = *(const uint4*)(Al + go);
            uint32_t so = (uint32_t)row * 128 + (((uint32_t)c8 * 16) ^ ((row & 7) << 4));
            *(uint4*)(smp + oAh + so) = vH;
            *(uint4*)(smp + oAl + so) = vL;
        }
#pragma unroll
        for (int r = 0; r < KC / 32; r++) {
            int idx = r * 256 + tid;
            int row = idx / RPR, c8 = idx % RPR;
            size_t go = (size_t)(n0 + row) * K + k0 + c8 * 8;
            uint4 vH = *(const uint4*)(Wh + go);
            uint4 vL = *(const uint4*)(Wl + go);
            uint32_t so = (uint32_t)row * 128 + (((uint32_t)c8 * 16) ^ ((row & 7) << 4));
            *(uint4*)(smp + oBh + so) = vH;
            *(uint4*)(smp + oBl + so) = vL;
        }
        __syncthreads();

#pragma unroll
        for (int kk = 0; kk < KC / 16; kk++) {
            uint32_t cb = ((uint32_t)kk << 5) + qk;
            uint32_t ah[2][4], al[2][4], bh[2][4], bl[2][4];
#pragma unroll
            for (int mt = 0; mt < 2; mt++) {
                uint32_t ad = sb + oAh + aoff[mt] + (cb ^ asw[mt]);
                LDSM_X4(ah[mt][0], ah[mt][1], ah[mt][2], ah[mt][3], ad);
                LDSM_X4(al[mt][0], al[mt][1], al[mt][2], al[mt][3], ad + 16384);
            }
#pragma unroll
            for (int nt = 0; nt < 2; nt++) {
                uint32_t bd = sb + oBh + boff[nt] + (cb ^ bsw[nt]);
                LDSM_X4(bh[nt][0], bh[nt][1], bh[nt][2], bh[nt][3], bd);
                LDSM_X4(bl[nt][0], bl[nt][1], bl[nt][2], bl[nt][3], bd + 8192);
            }
#pragma unroll
            for (int mt = 0; mt < 2; mt++)
#pragma unroll
                for (int nt = 0; nt < 2; nt++)
#pragma unroll
                    for (int u = 0; u < 2; u++) {
                        int nf = nt * 2 + u;
                        MMA4(acc[mt][nf], ah[mt], bh[nt][u], bh[nt][u + 2]);
                        MMA4(acc[mt][nf], ah[mt], bl[nt][u], bl[nt][u + 2]);
                        MMA4(acc[mt][nf], al[mt], bh[nt][u], bh[nt][u + 2]);
                    }
        }
        __syncthreads();
    }

#pragma unroll
    for (int mt = 0; mt < 2; mt++)
#pragma unroll
        for (int nf = 0; nf < 4; nf++) {
            int mrow = m0 + wm * 32 + mt * 16 + (lane >> 2);
            int ncol = n0 + wn * 32 + (nf >> 1) * 16 + (nf & 1) * 8 + 2 * (lane & 3);
#pragma unroll
            for (int e = 0; e < 4; e++) {
                int m = mrow + (e >> 1) * 8;
                int n = ncol + (e & 1);
                if (n >= N) continue;
                if (EPI == 0) {
                    int t = n >> coLog2;
                    int cc = n & ((1 << coLog2) - 1);
                    out[(size_t)t * (size_t)ustr + ((size_t)m << coLog2) + cc] =
                        acc[mt][nf][e];
                } else {
                    float v = acc[mt][nf][e] + bias[n];
                    __nv_bfloat16 h = __float2bfloat16(v);
                    size_t o = (size_t)((n >> 7) * 128 + m) * 128 + (n & 127);
                    outh[o] = h;
                    outl[o] = __float2bfloat16(v - __bfloat162float(h));
                }
            }
        }
}

// ---------------------------------------------------------------------------
// SIMT fp32 GEMM for FC1 (MODE 1) and L4 (MODE 3).
// ---------------------------------------------------------------------------
template<int BM, int BN, int TM, int TN, int MODE>
__global__ __launch_bounds__(256)
void gemm_k(const float* __restrict__ A, const float* __restrict__ W,
            const float* __restrict__ bias, float* __restrict__ out,
            int M, int N, int K, int co, long long ustr) {
    __shared__ float As[16][BM + 4];
    __shared__ float Ws[16][BN + 4];
    const int tid = threadIdx.x;
    const int tx = tid & 15, ty = tid >> 4;
    const int m0 = blockIdx.y * BM, n0 = blockIdx.x * BN;

    float acc[TM][TN];
#pragma unroll
    for (int i = 0; i < TM; i++)
#pragma unroll
        for (int j = 0; j < TN; j++) acc[i][j] = 0.0f;

    for (int k0 = 0; k0 < K; k0 += 16) {
#pragma unroll
        for (int r = 0; r < BM / 64; r++) {
            int lid = tid + r * 256;
            int row = lid >> 2;
            int kq = (lid & 3) << 2;
            float4 a = *(const float4*)(A + (size_t)(m0 + row) * K + (k0 + kq));
            As[kq + 0][row] = a.x;
            As[kq + 1][row] = a.y;
            As[kq + 2][row] = a.z;
            As[kq + 3][row] = a.w;
        }
#pragma unroll
        for (int r = 0; r < BN / 64; r++) {
            int lid = tid + r * 256;
            int k = lid / (BN / 4);
            int n4 = (lid % (BN / 4)) * 4;
            int gc = n0 + n4;
            float4 w;
            if (((N & 3) == 0) && gc + 4 <= N) {
                w = *(const float4*)(W + (size_t)(k0 + k) * N + gc);
            } else {
                w.x = (gc + 0 < N) ? W[(size_t)(k0 + k) * N + gc + 0] : 0.f;
                w.y = (gc + 1 < N) ? W[(size_t)(k0 + k) * N + gc + 1] : 0.f;
                w.z = (gc + 2 < N) ? W[(size_t)(k0 + k) * N + gc + 2] : 0.f;
                w.w = (gc + 3 < N) ? W[(size_t)(k0 + k) * N + gc + 3] : 0.f;
            }
            *(float4*)&Ws[k][n4] = w;
        }
        __syncthreads();

#pragma unroll
        for (int k = 0; k < 16; k++) {
            float a[TM], w[TN];
#pragma unroll
            for (int i = 0; i < TM / 4; i++)
                *(float4*)&a[4 * i] = *(const float4*)&As[k][ty * TM + 4 * i];
#pragma unroll
            for (int j = 0; j < TN / 4; j++)
                *(float4*)&w[4 * j] = *(const float4*)&Ws[k][tx * TN + 4 * j];
#pragma unroll
            for (int i = 0; i < TM; i++)
#pragma unroll
                for (int j = 0; j < TN; j++) acc[i][j] += a[i] * w[j];
        }
        __syncthreads();
    }

#pragma unroll
    for (int i = 0; i < TM; i++) {
        int m = m0 + ty * TM + i;
#pragma unroll
        for (int j = 0; j < TN; j++) {
            int n = n0 + tx * TN + j;
            if (n >= N) continue;
            float v = acc[i][j];
            if (MODE == 1) {
                v += bias[n];
                v = v > 0.f ? v : 0.f;
                out[(size_t)m * N + n] = v;
            } else {
                int t = n / co;
                out[(size_t)t * (size_t)ustr + (size_t)m * co + (n - t * co)] = v;
            }
        }
    }
}

// ---------------------------------------------------------------------------
// Props (CSR slice selected by nb):
//   Y[v] = U1[v>>shU] + 2 * sum_e w * U2[src>>shU]
//   out[v] = act( U0[v>>shU] + sum_e w * Y[src] + bias )
// ---------------------------------------------------------------------------
__global__ void propY_kernel(float4* __restrict__ Y, const float4* __restrict__ U1,
                             const float4* __restrict__ U2, int R4, int shU, int nb) {
    int v = blockIdx.y;
    int j = blockIdx.x * blockDim.x + threadIdx.x;
    float4 acc = make_float4(0.f, 0.f, 0.f, 0.f);
    int s = g_off[nb + v], t = g_off[nb + v + 1];
    for (int q = s; q < t; q++) {
        float w = g_cw[q];
        float4 x = U2[(size_t)(g_csrc[q] >> shU) * R4 + j];
        acc.x += w * x.x; acc.y += w * x.y; acc.z += w * x.z; acc.w += w * x.w;
    }
    float4 u1 = U1[(size_t)(v >> shU) * R4 + j];
    acc.x = u1.x + 2.f * acc.x;
    acc.y = u1.y + 2.f * acc.y;
    acc.z = u1.z + 2.f * acc.z;
    acc.w = u1.w + 2.f * acc.w;
    Y[(size_t)v * R4 + j] = acc;
}

// OUTF: 0 -> fp32 out; 1 -> bf16 hi/lo split (feeds next mma GEMM)
template<int OUTF>
__global__ void propF_kernel(float* __restrict__ outf,
                             __nv_bfloat16* __restrict__ outh,
                             __nv_bfloat16* __restrict__ outl,
                             const float4* __restrict__ U0, const float4* __restrict__ Y,
                             const float* __restrict__ bias, int R4, int comask,
                             int shU, int nb) {
    int v = blockIdx.y;
    int j = blockIdx.x * blockDim.x + threadIdx.x;
    float4 acc = U0[(size_t)(v >> shU) * R4 + j];
    int s = g_off[nb + v], t = g_off[nb + v + 1];
    for (int q = s; q < t; q++) {
        float w = g_cw[q];
        float4 y = Y[(size_t)g_csrc[q] * R4 + j];
        acc.x += w * y.x; acc.y += w * y.y; acc.z += w * y.z; acc.w += w * y.w;
    }
    int c0 = (4 * j) & comask;
    float4 bb = *(const float4*)&bias[c0];
    acc.x += bb.x; acc.y += bb.y; acc.z += bb.z; acc.w += bb.w;
    acc.x = acc.x >= 0.f ? acc.x : LRELU_S * acc.x;
    acc.y = acc.y >= 0.f ? acc.y : LRELU_S * acc.y;
    acc.z = acc.z >= 0.f ? acc.z : LRELU_S * acc.z;
    acc.w = acc.w >= 0.f ? acc.w : LRELU_S * acc.w;
    if (OUTF == 0) {
        ((float4*)outf)[(size_t)v * R4 + j] = acc;
    } else {
        size_t o = (size_t)v * R4 * 4 + 4 * j;
        __nv_bfloat16 h[4], l[4];
        float vv[4] = {acc.x, acc.y, acc.z, acc.w};
#pragma unroll
        for (int e = 0; e < 4; e++) {
            h[e] = __float2bfloat16(vv[e]);
            l[e] = __float2bfloat16(vv[e] - __bfloat162float(h[e]));
        }
        *(uint2*)(outh + o) = *(uint2*)h;
        *(uint2*)(outl + o) = *(uint2*)l;
    }
}

__global__ void propF3_kernel(float* __restrict__ out, const float* __restrict__ U0,
                              const float* __restrict__ Y,
                              const float* __restrict__ bias, int nb) {
    int v = blockIdx.y;
    int p = blockIdx.x * blockDim.x + threadIdx.x;   // < 384
    float acc = U0[(size_t)v * 384 + p];
    int s = g_off[nb + v], t = g_off[nb + v + 1];
    for (int q = s; q < t; q++)
        acc += g_cw[q] * Y[(size_t)g_csrc[q] * 384 + p];
    out[(size_t)v * 384 + p] = acc + bias[p % 3];
}

__global__ void final_kernel(float* __restrict__ out, const float* __restrict__ h,
                             const void* __restrict__ perm) {
    int i = blockIdx.x * blockDim.x + threadIdx.x;
    const int TOT = 128 * 6890 * 3;
    if (i < TOT) {
        int b = i / (6890 * 3);
        int r = i - b * (6890 * 3);
        int u = r / 3;
        int k = r - u * 3;
        int v = read_idx(perm, u);
        out[i] = h[(size_t)(v * 128 + b) * 3 + k];
    }
}

// ---------------------------------------------------------------------------
extern "C" void kernel_launch(void* const* d_in, const int* in_sizes, int n_in,
                              void* d_out, int out_size) {
    const float* x   = (const float*)d_in[0];
    const float* fw1 = (const float*)d_in[1];
    const float* fb1 = (const float*)d_in[2];
    const float* fw2 = (const float*)d_in[3];
    const float* fb2 = (const float*)d_in[4];
    const float* W[5];
    const float* bb[5];
    for (int i = 0; i < 5; i++) {
        W[i]  = (const float*)d_in[5 + 2 * i];
        bb[i] = (const float*)d_in[6 + 2 * i];
    }
    const void* edges[4];
    for (int i = 0; i < 4; i++) edges[i] = d_in[15 + i];
    const void* perm = d_in[19];
    float* out = (float*)d_out;

    float *T, *OA, *YB, *H1, *WC;
    __nv_bfloat16 *AH, *AL, *WTH, *WTL, *W2H, *W2L, *H1H, *H1L;
    cudaGetSymbolAddress((void**)&T,   g_T);
    cudaGetSymbolAddress((void**)&OA,  g_outA);
    cudaGetSymbolAddress((void**)&YB,  g_Y);
    cudaGetSymbolAddress((void**)&H1,  g_h1);
    cudaGetSymbolAddress((void**)&WC,  g_wc);
    cudaGetSymbolAddress((void**)&AH,  g_Ah);
    cudaGetSymbolAddress((void**)&AL,  g_Al);
    cudaGetSymbolAddress((void**)&WTH, g_wth);
    cudaGetSymbolAddress((void**)&WTL, g_wtl);
    cudaGetSymbolAddress((void**)&W2H, g_w2h);
    cudaGetSymbolAddress((void**)&W2L, g_w2l);
    cudaGetSymbolAddress((void**)&H1H, g_h1h);
    cudaGetSymbolAddress((void**)&H1L, g_h1l);

    const int ns[5]   = {864, 1728, 3456, 6912, 6912};
    const int cis[5]  = {128, 128, 64, 32, 16};
    const int cos_[5] = {128, 64, 32, 16, 3};
    const int col2[5] = {7, 6, 5, 4, 0};
    const int nbArr[5] = {0, 864, 2592, 6048, 6048};

    // 0: FC1 (SIMT)
    gemm_k<128, 128, 8, 8, 1><<<dim3(4, 1), 256>>>(x, fw1, fb1, H1,
                                                   128, 512, 128, 0, 0);
    // 1: split FC1 output
    hsplit_kernel<<<256, 256>>>(H1, H1H, H1L);
    // 2: transpose+split fc_w2 -> (N x K) bf16 hi/lo
    tsplit_kernel<<<dim3(110592 / 32, 512 / 32), dim3(32, 8)>>>(fw2, W2H, W2L);
    // 3: FC2 GEMM (pure bf16) — ncu capture target
    gemm_mmab<64, 1><<<dim3(110592 / 64, 1), 256>>>(
        H1H, H1L, W2H, W2L, fb2, nullptr, AH, AL, 128, 110592, 512, 0, 0);
    // 4: combined weights for layer 0
    wprep_kernel<<<(384 * 128 + 255) / 256, 256>>>(W[0], WC, WTH, WTL, 128, 128, 384);
    // 5: layer-0 ChebConv GEMM
    gemm_mmab<64, 0><<<dim3(6, 864), 256>>>(AH, AL, WTH, WTL, nullptr, T,
                                            nullptr, nullptr,
                                            110592, 384, 128, 7, 14155776LL);
    // 6: dtype sniff, then fused CSR build for all 4 graphs
    detect_kernel<<<1, 256>>>((const int*)edges[0], 5184);
    csr_zero_kernel<<<(12960 + 255) / 256, 256>>>();
    csr_count_kernel<<<dim3(162, 4), 256>>>(edges[0], edges[1], edges[2], edges[3]);
    csr_dinv_kernel<<<(12960 + 255) / 256, 256>>>();
    csr_scan_kernel<<<4, 1024>>>();
    csr_fill_kernel<<<dim3(162, 4), 256>>>(edges[0], edges[1], edges[2], edges[3]);

    for (int l = 0; l < 5; l++) {
        int n  = ns[l];
        int ci = cis[l];
        int co = cos_[l];
        int N  = 3 * co;
        int Np = ((N + 63) / 64) * 64;
        int ng = (l == 0 || l == 4) ? n : n / 2;   // layers 1-3 un-repeated
        int Mg = ng * 128;
        int shU = (l == 0 || l == 4) ? 0 : 1;
        int R4 = 32 * co;
        long long US = (long long)Mg * co;
        int nb = nbArr[l];

        if (l > 0) {
            wprep_kernel<<<(Np * ci + 255) / 256, 256>>>(W[l], WC, WTH, WTL,
                                                         ci, co, Np);
            if (l < 4) {   // mma path
                if (ci % 64 == 0)
                    gemm_mmab<64, 0><<<dim3(Np / 64, Mg / 128), 256>>>(
                        AH, AL, WTH, WTL, nullptr, T, nullptr, nullptr,
                        Mg, N, ci, col2[l], US);
                else
                    gemm_mmab<32, 0><<<dim3(Np / 64, Mg / 128), 256>>>(
                        AH, AL, WTH, WTL, nullptr, T, nullptr, nullptr,
                        Mg, N, ci, col2[l], US);
            } else {       // L4: K=16, SIMT
                gemm_k<256, 64, 16, 4, 3><<<dim3(1, Mg / 256), 256>>>(
                    OA, WC, nullptr, T, Mg, N, ci, co, US);
            }
        }

        // Y = U1' + 2*P*U2'
        propY_kernel<<<dim3(R4 >= 256 ? R4 / 256 : 1, n), R4 < 256 ? R4 : 256>>>(
            (float4*)YB, (const float4*)(T + US), (const float4*)(T + 2 * US),
            R4, shU, nb);
        // out = act(U0' + P*Y + b)
        if (l < 3) {
            propF_kernel<1><<<dim3(R4 / 256, n), 256>>>(
                nullptr, AH, AL, (const float4*)T, (const float4*)YB,
                bb[l], R4, co - 1, shU, nb);
        } else if (l == 3) {
            propF_kernel<0><<<dim3(R4 / 256, n), 256>>>(
                OA, nullptr, nullptr, (const float4*)T, (const float4*)YB,
                bb[l], R4, co - 1, shU, nb);
        } else {
            propF3_kernel<<<dim3(3, n), 128>>>(OA, T, YB, bb[4], nb);
        }
    }

    const int TOT = 128 * 6890 * 3;
    final_kernel<<<(TOT + 255) / 256, 256>>>(out, OA, perm);
}

// round 11
// speedup vs baseline: 7.1585x; 1.0696x over previous
#include <cuda_runtime.h>
#include <cuda_bf16.h>
#include <cstdint>

// ---------------------------------------------------------------------------
// ChebGcnDecoder, commuted form. All big GEMMs on mma.sync bf16 hi/lo 3-split
// with pre-split bf16 inputs. R11: cp.async double-buffered GEMM mainloop
// (prefetch stage s+1 while computing stage s). CSR build fused (5 launches).
// Layout: (node, batch, channel) row-major everywhere.
// ---------------------------------------------------------------------------

#define LRELU_S 0.2f

__device__ float g_T[42467328];            // U0|U1|U2, stride Mg*co
__device__ float g_outA[14155776];         // fp32 layer output (l=3)
__device__ float g_Y[14155776];            // Y = U1 + 2*P*U2
__device__ __nv_bfloat16 g_Ah[14155776];   // bf16-hi GEMM input (activations)
__device__ __nv_bfloat16 g_Al[14155776];   // bf16-lo
__device__ __nv_bfloat16 g_w2h[56623104];  // fc_w2 transposed+split (N x K)
__device__ __nv_bfloat16 g_w2l[56623104];
__device__ float g_h1[65536];              // FC1 output 128x512 fp32
__device__ __nv_bfloat16 g_h1h[65536];
__device__ __nv_bfloat16 g_h1l[65536];
__device__ float g_wc[49152];              // combined weights fp32 (K x N), L4
__device__ __nv_bfloat16 g_wth[49152];     // combined weights bf16-hi (Np x K)
__device__ __nv_bfloat16 g_wtl[49152];
__device__ int   g_cnt[12960];
__device__ float g_dinv[12960];
__device__ int   g_off[12961];
__device__ int   g_cur[12960];
__device__ int   g_csrc[77760];
__device__ float g_cw[77760];
__device__ int   g_is64;

__constant__ int c_nb[4] = {0, 864, 2592, 6048};
__constant__ int c_eb[4] = {0, 5184, 15552, 36288};
__constant__ int c_nl[4] = {864, 1728, 3456, 6912};

// ---------------------------------------------------------------------------
__device__ __forceinline__ int read_idx(const void* p, int i) {
    if (g_is64) return (int)((const long long*)p)[i];
    return ((const int*)p)[i];
}

__global__ void detect_kernel(const int* w, int nwords) {
    __shared__ int any;
    if (threadIdx.x == 0) any = 0;
    __syncthreads();
    int a = 0;
    for (int i = 1 + 2 * (int)threadIdx.x; i < nwords; i += 2 * blockDim.x) a |= w[i];
    if (a) atomicOr(&any, 1);
    __syncthreads();
    if (threadIdx.x == 0) g_is64 = any ? 0 : 1;
}

// ---- fused CSR build over all 4 graphs ----
__global__ void csr_zero_kernel() {
    int i = blockIdx.x * blockDim.x + threadIdx.x;
    if (i < 12960) g_cnt[i] = 0;
}

__global__ void csr_count_kernel(const void* e0, const void* e1,
                                 const void* e2, const void* e3) {
    int l = blockIdx.y;
    const void* eg = (l == 0) ? e0 : (l == 1) ? e1 : (l == 2) ? e2 : e3;
    int e = 6 * c_nl[l];
    int i = blockIdx.x * blockDim.x + threadIdx.x;
    if (i < e) atomicAdd(&g_cnt[c_nb[l] + read_idx(eg, e + i)], 1);
}

__global__ void csr_dinv_kernel() {
    int i = blockIdx.x * blockDim.x + threadIdx.x;
    if (i < 12960) g_dinv[i] = (g_cnt[i] > 0) ? rsqrtf((float)g_cnt[i]) : 0.0f;
}

__global__ void csr_scan_kernel() {
    __shared__ int partial[1024];
    int l = blockIdx.x;
    int n = c_nl[l], nb = c_nb[l], eb = c_eb[l];
    int tid = threadIdx.x;
    int C = (n + 1023) / 1024;
    int start = tid * C;
    int local[8];
    int s = 0;
    for (int i = 0; i < C; i++) {
        int idx = start + i;
        int v = (idx < n) ? g_cnt[nb + idx] : 0;
        local[i] = s;
        s += v;
    }
    partial[tid] = s;
    __syncthreads();
    for (int d = 1; d < 1024; d <<= 1) {
        int t = (tid >= d) ? partial[tid - d] : 0;
        __syncthreads();
        if (tid >= d) partial[tid] += t;
        __syncthreads();
    }
    int base = (tid > 0) ? partial[tid - 1] : 0;
    for (int i = 0; i < C; i++) {
        int idx = start + i;
        if (idx < n) {
            int o = eb + base + local[i];
            g_off[nb + idx] = o;
            g_cur[nb + idx] = o;
        }
    }
    if (l == 3 && tid == 1023) g_off[12960] = 77760;
}

__global__ void csr_fill_kernel(const void* e0, const void* e1,
                                const void* e2, const void* e3) {
    int l = blockIdx.y;
    const void* eg = (l == 0) ? e0 : (l == 1) ? e1 : (l == 2) ? e2 : e3;
    int e = 6 * c_nl[l];
    int nb = c_nb[l];
    int i = blockIdx.x * blockDim.x + threadIdx.x;
    if (i < e) {
        int s = read_idx(eg, i);
        int d = read_idx(eg, e + i);
        int p = atomicAdd(&g_cur[nb + d], 1);
        g_csrc[p] = s;
        g_cw[p] = -g_dinv[nb + s] * g_dinv[nb + d];
    }
}

// Combined weights [W0-W2 | W1 | W2]: fp32 (K x N) for SIMT L4, bf16 hi/lo
// transposed (Np x K) for the mma path. Factor 2 on P^2 applied in props.
__global__ void wprep_kernel(const float* __restrict__ W,
                             float* __restrict__ Wc,
                             __nv_bfloat16* __restrict__ Wth,
                             __nv_bfloat16* __restrict__ Wtl,
                             int ci, int co, int Np) {
    int i = blockIdx.x * blockDim.x + threadIdx.x;
    int N = 3 * co;
    if (i >= Np * ci) return;
    int n = i / ci, k = i - n * ci;
    int cico = ci * co;
    float v = 0.f;
    if (n < N) {
        if (n < co)            v = W[k * co + n] - W[2 * cico + k * co + n];
        else if (n < 2 * co)   v = W[cico + k * co + (n - co)];
        else                   v = W[2 * cico + k * co + (n - 2 * co)];
        Wc[k * N + n] = v;
    }
    __nv_bfloat16 h = __float2bfloat16(v);
    Wth[n * ci + k] = h;
    Wtl[n * ci + k] = __float2bfloat16(v - __bfloat162float(h));
}

// fc_w2 (K=512 x N=110592) fp32 -> transposed (N x K) bf16 hi/lo.
__global__ void tsplit_kernel(const float* __restrict__ in,
                              __nv_bfloat16* __restrict__ outh,
                              __nv_bfloat16* __restrict__ outl) {
    __shared__ float t[32][33];
    const int N = 110592, K = 512;
    int n0 = blockIdx.x * 32, k0 = blockIdx.y * 32;
    int tx = threadIdx.x, ty = threadIdx.y;
#pragma unroll
    for (int i = 0; i < 4; i++)
        t[ty + 8 * i][tx] = in[(size_t)(k0 + ty + 8 * i) * N + n0 + tx];
    __syncthreads();
#pragma unroll
    for (int i = 0; i < 4; i++) {
        float v = t[tx][ty + 8 * i];
        __nv_bfloat16 h = __float2bfloat16(v);
        size_t o = (size_t)(n0 + ty + 8 * i) * K + k0 + tx;
        outh[o] = h;
        outl[o] = __float2bfloat16(v - __bfloat162float(h));
    }
}

// split FC1 output (128x512) into bf16 hi/lo
__global__ void hsplit_kernel(const float* __restrict__ in,
                              __nv_bfloat16* __restrict__ outh,
                              __nv_bfloat16* __restrict__ outl) {
    int i = blockIdx.x * blockDim.x + threadIdx.x;
    if (i < 65536) {
        float v = in[i];
        __nv_bfloat16 h = __float2bfloat16(v);
        outh[i] = h;
        outl[i] = __float2bfloat16(v - __bfloat162float(h));
    }
}

// ---------------------------------------------------------------------------
__device__ __forceinline__ uint32_t smem_u32(const void* p) {
    uint32_t a;
    asm("{ .reg .u64 t; cvta.to.shared.u64 t, %1; cvt.u32.u64 %0, t; }"
        : "=r"(a) : "l"(p));
    return a;
}

__device__ __forceinline__ void cp_async16(uint32_t dst, const void* src) {
    asm volatile("cp.async.cg.shared.global [%0], [%1], 16;"
                 :: "r"(dst), "l"(src));
}

#define LDSM_X4(r0, r1, r2, r3, a)                                            \
    asm volatile("ldmatrix.sync.aligned.m8n8.x4.shared.b16 {%0,%1,%2,%3}, [%4];" \
        : "=r"(r0), "=r"(r1), "=r"(r2), "=r"(r3) : "r"(a))

#define MMA4(c, a, b0, b1)                                                    \
    asm volatile(                                                             \
        "mma.sync.aligned.m16n8k16.row.col.f32.bf16.bf16.f32 "                \
        "{%0,%1,%2,%3}, {%4,%5,%6,%7}, {%8,%9}, {%0,%1,%2,%3};\n"             \
        : "+f"((c)[0]), "+f"((c)[1]), "+f"((c)[2]), "+f"((c)[3])              \
        : "r"((a)[0]), "r"((a)[1]), "r"((a)[2]), "r"((a)[3]),                 \
          "r"(b0), "r"(b1))

// ---------------------------------------------------------------------------
// bf16-input tensor GEMM, cp.async double-buffered.
// C(MxN) = A(MxK)@Wt^T. Wt is (Np x K) row-major. BM=128, BN=64, KC chunk.
// Per-buffer SW128 layout (128B row stride): Ah 16K | Al 16K | Bh 8K | Bl 8K.
// EPI 0: split write into U0|U1|U2 (t = n>>coLog2) at out + t*ustr (fp32).
// EPI 1: FC2: bias add, bf16 hi/lo split write to (node,batch,ch) layout.
// ---------------------------------------------------------------------------
#define GBUF 49152

template<int KC, int EPI>
__global__ __launch_bounds__(256)
void gemm_mmab(const __nv_bfloat16* __restrict__ Ah, const __nv_bfloat16* __restrict__ Al,
               const __nv_bfloat16* __restrict__ Wh, const __nv_bfloat16* __restrict__ Wl,
               const float* __restrict__ bias, float* __restrict__ out,
               __nv_bfloat16* __restrict__ outh, __nv_bfloat16* __restrict__ outl,
               int M, int N, int K, int coLog2, long long ustr) {
    extern __shared__ __align__(128) uint8_t smdyn[];
    const uint32_t sb = smem_u32(smdyn);
    const uint32_t oAh = 0, oAl = 16384, oBh = 32768, oBl = 40960;

    const int tid = threadIdx.x, lane = tid & 31, warp = tid >> 5;
    const int wm = warp & 3, wn = warp >> 2;
    const int m0 = blockIdx.y * 128, n0 = blockIdx.x * 64;

    float acc[2][4][4];
#pragma unroll
    for (int i = 0; i < 2; i++)
#pragma unroll
        for (int j = 0; j < 4; j++)
#pragma unroll
            for (int q = 0; q < 4; q++) acc[i][j][q] = 0.f;

    const uint32_t lq = lane >> 3, lr = lane & 7;
    const uint32_t qk = (lq >> 1) << 4;
    uint32_t aoff[2], asw[2], boff[2], bsw[2];
#pragma unroll
    for (int mt = 0; mt < 2; mt++) {
        int row = wm * 32 + mt * 16 + ((lq & 1) << 3) + lr;
        aoff[mt] = (uint32_t)row * 128;
        asw[mt] = (uint32_t)((row & 7) << 4);
    }
#pragma unroll
    for (int nt = 0; nt < 2; nt++) {
        int row = wn * 32 + nt * 16 + ((lq & 1) << 3) + lr;
        boff[nt] = (uint32_t)row * 128;
        bsw[nt] = (uint32_t)((row & 7) << 4);
    }

    constexpr int RPR = KC / 8;              // 16B chunks per row
    const int nstages = K / KC;

    // prefetch helper (as a lambda-free macro-ish block)
#define PREFETCH(S, BUF) do {                                                 \
        int k0_ = (S) * KC;                                                   \
        uint32_t bo_ = sb + (BUF) * GBUF;                                     \
        _Pragma("unroll")                                                     \
        for (int r = 0; r < KC / 16; r++) {                                   \
            int idx = r * 256 + tid;                                          \
            int row = idx / RPR, c8 = idx % RPR;                              \
            size_t go = (size_t)(m0 + row) * K + k0_ + c8 * 8;                \
            uint32_t so = (uint32_t)row * 128 +                               \
                          (((uint32_t)c8 * 16) ^ ((row & 7) << 4));           \
            cp_async16(bo_ + oAh + so, Ah + go);                              \
            cp_async16(bo_ + oAl + so, Al + go);                              \
        }                                                                     \
        _Pragma("unroll")                                                     \
        for (int r = 0; r < KC / 32; r++) {                                   \
            int idx = r * 256 + tid;                                          \
            int row = idx / RPR, c8 = idx % RPR;                              \
            size_t go = (size_t)(n0 + row) * K + k0_ + c8 * 8;                \
            uint32_t so = (uint32_t)row * 128 +                               \
                          (((uint32_t)c8 * 16) ^ ((row & 7) << 4));           \
            cp_async16(bo_ + oBh + so, Wh + go);                              \
            cp_async16(bo_ + oBl + so, Wl + go);                              \
        }                                                                     \
        asm volatile("cp.async.commit_group;" ::: "memory");                  \
    } while (0)

    PREFETCH(0, 0);

    for (int s = 0; s < nstages; s++) {
        int buf = s & 1;
        if (s + 1 < nstages) {
            PREFETCH(s + 1, buf ^ 1);
            asm volatile("cp.async.wait_group 1;" ::: "memory");
        } else {
            asm volatile("cp.async.wait_group 0;" ::: "memory");
        }
        __syncthreads();

        uint32_t bo = sb + buf * GBUF;
#pragma unroll
        for (int kk = 0; kk < KC / 16; kk++) {
            uint32_t cb = ((uint32_t)kk << 5) + qk;
            uint32_t ah[2][4], al[2][4], bh[2][4], bl[2][4];
#pragma unroll
            for (int mt = 0; mt < 2; mt++) {
                uint32_t ad = bo + oAh + aoff[mt] + (cb ^ asw[mt]);
                LDSM_X4(ah[mt][0], ah[mt][1], ah[mt][2], ah[mt][3], ad);
                LDSM_X4(al[mt][0], al[mt][1], al[mt][2], al[mt][3], ad + 16384);
            }
#pragma unroll
            for (int nt = 0; nt < 2; nt++) {
                uint32_t bd = bo + oBh + boff[nt] + (cb ^ bsw[nt]);
                LDSM_X4(bh[nt][0], bh[nt][1], bh[nt][2], bh[nt][3], bd);
                LDSM_X4(bl[nt][0], bl[nt][1], bl[nt][2], bl[nt][3], bd + 8192);
            }
#pragma unroll
            for (int mt = 0; mt < 2; mt++)
#pragma unroll
                for (int nt = 0; nt < 2; nt++)
#pragma unroll
                    for (int u = 0; u < 2; u++) {
                        int nf = nt * 2 + u;
                        MMA4(acc[mt][nf], ah[mt], bh[nt][u], bh[nt][u + 2]);
                        MMA4(acc[mt][nf], ah[mt], bl[nt][u], bl[nt][u + 2]);
                        MMA4(acc[mt][nf], al[mt], bh[nt][u], bh[nt][u + 2]);
                    }
        }
        __syncthreads();
    }
#undef PREFETCH

#pragma unroll
    for (int mt = 0; mt < 2; mt++)
#pragma unroll
        for (int nf = 0; nf < 4; nf++) {
            int mrow = m0 + wm * 32 + mt * 16 + (lane >> 2);
            int ncol = n0 + wn * 32 + (nf >> 1) * 16 + (nf & 1) * 8 + 2 * (lane & 3);
#pragma unroll
            for (int e = 0; e < 4; e++) {
                int m = mrow + (e >> 1) * 8;
                int n = ncol + (e & 1);
                if (n >= N) continue;
                if (EPI == 0) {
                    int t = n >> coLog2;
                    int cc = n & ((1 << coLog2) - 1);
                    out[(size_t)t * (size_t)ustr + ((size_t)m << coLog2) + cc] =
                        acc[mt][nf][e];
                } else {
                    float v = acc[mt][nf][e] + bias[n];
                    __nv_bfloat16 h = __float2bfloat16(v);
                    size_t o = (size_t)((n >> 7) * 128 + m) * 128 + (n & 127);
                    outh[o] = h;
                    outl[o] = __float2bfloat16(v - __bfloat162float(h));
                }
            }
        }
}

// ---------------------------------------------------------------------------
// SIMT fp32 GEMM for FC1 (MODE 1) and L4 (MODE 3).
// ---------------------------------------------------------------------------
template<int BM, int BN, int TM, int TN, int MODE>
__global__ __launch_bounds__(256)
void gemm_k(const float* __restrict__ A, const float* __restrict__ W,
            const float* __restrict__ bias, float* __restrict__ out,
            int M, int N, int K, int co, long long ustr) {
    __shared__ float As[16][BM + 4];
    __shared__ float Ws[16][BN + 4];
    const int tid = threadIdx.x;
    const int tx = tid & 15, ty = tid >> 4;
    const int m0 = blockIdx.y * BM, n0 = blockIdx.x * BN;

    float acc[TM][TN];
#pragma unroll
    for (int i = 0; i < TM; i++)
#pragma unroll
        for (int j = 0; j < TN; j++) acc[i][j] = 0.0f;

    for (int k0 = 0; k0 < K; k0 += 16) {
#pragma unroll
        for (int r = 0; r < BM / 64; r++) {
            int lid = tid + r * 256;
            int row = lid >> 2;
            int kq = (lid & 3) << 2;
            float4 a = *(const float4*)(A + (size_t)(m0 + row) * K + (k0 + kq));
            As[kq + 0][row] = a.x;
            As[kq + 1][row] = a.y;
            As[kq + 2][row] = a.z;
            As[kq + 3][row] = a.w;
        }
#pragma unroll
        for (int r = 0; r < BN / 64; r++) {
            int lid = tid + r * 256;
            int k = lid / (BN / 4);
            int n4 = (lid % (BN / 4)) * 4;
            int gc = n0 + n4;
            float4 w;
            if (((N & 3) == 0) && gc + 4 <= N) {
                w = *(const float4*)(W + (size_t)(k0 + k) * N + gc);
            } else {
                w.x = (gc + 0 < N) ? W[(size_t)(k0 + k) * N + gc + 0] : 0.f;
                w.y = (gc + 1 < N) ? W[(size_t)(k0 + k) * N + gc + 1] : 0.f;
                w.z = (gc + 2 < N) ? W[(size_t)(k0 + k) * N + gc + 2] : 0.f;
                w.w = (gc + 3 < N) ? W[(size_t)(k0 + k) * N + gc + 3] : 0.f;
            }
            *(float4*)&Ws[k][n4] = w;
        }
        __syncthreads();

#pragma unroll
        for (int k = 0; k < 16; k++) {
            float a[TM], w[TN];
#pragma unroll
            for (int i = 0; i < TM / 4; i++)
                *(float4*)&a[4 * i] = *(const float4*)&As[k][ty * TM + 4 * i];
#pragma unroll
            for (int j = 0; j < TN / 4; j++)
                *(float4*)&w[4 * j] = *(const float4*)&Ws[k][tx * TN + 4 * j];
#pragma unroll
            for (int i = 0; i < TM; i++)
#pragma unroll
                for (int j = 0; j < TN; j++) acc[i][j] += a[i] * w[j];
        }
        __syncthreads();
    }

#pragma unroll
    for (int i = 0; i < TM; i++) {
        int m = m0 + ty * TM + i;
#pragma unroll
        for (int j = 0; j < TN; j++) {
            int n = n0 + tx * TN + j;
            if (n >= N) continue;
            float v = acc[i][j];
            if (MODE == 1) {
                v += bias[n];
                v = v > 0.f ? v : 0.f;
                out[(size_t)m * N + n] = v;
            } else {
                int t = n / co;
                out[(size_t)t * (size_t)ustr + (size_t)m * co + (n - t * co)] = v;
            }
        }
    }
}

// ---------------------------------------------------------------------------
// Props (CSR slice selected by nb):
//   Y[v] = U1[v>>shU] + 2 * sum_e w * U2[src>>shU]
//   out[v] = act( U0[v>>shU] + sum_e w * Y[src] + bias )
// ---------------------------------------------------------------------------
__global__ void propY_kernel(float4* __restrict__ Y, const float4* __restrict__ U1,
                             const float4* __restrict__ U2, int R4, int shU, int nb) {
    int v = blockIdx.y;
    int j = blockIdx.x * blockDim.x + threadIdx.x;
    float4 acc = make_float4(0.f, 0.f, 0.f, 0.f);
    int s = g_off[nb + v], t = g_off[nb + v + 1];
    for (int q = s; q < t; q++) {
        float w = g_cw[q];
        float4 x = U2[(size_t)(g_csrc[q] >> shU) * R4 + j];
        acc.x += w * x.x; acc.y += w * x.y; acc.z += w * x.z; acc.w += w * x.w;
    }
    float4 u1 = U1[(size_t)(v >> shU) * R4 + j];
    acc.x = u1.x + 2.f * acc.x;
    acc.y = u1.y + 2.f * acc.y;
    acc.z = u1.z + 2.f * acc.z;
    acc.w = u1.w + 2.f * acc.w;
    Y[(size_t)v * R4 + j] = acc;
}

// OUTF: 0 -> fp32 out; 1 -> bf16 hi/lo split (feeds next mma GEMM)
template<int OUTF>
__global__ void propF_kernel(float* __restrict__ outf,
                             __nv_bfloat16* __restrict__ outh,
                             __nv_bfloat16* __restrict__ outl,
                             const float4* __restrict__ U0, const float4* __restrict__ Y,
                             const float* __restrict__ bias, int R4, int comask,
                             int shU, int nb) {
    int v = blockIdx.y;
    int j = blockIdx.x * blockDim.x + threadIdx.x;
    float4 acc = U0[(size_t)(v >> shU) * R4 + j];
    int s = g_off[nb + v], t = g_off[nb + v + 1];
    for (int q = s; q < t; q++) {
        float w = g_cw[q];
        float4 y = Y[(size_t)g_csrc[q] * R4 + j];
        acc.x += w * y.x; acc.y += w * y.y; acc.z += w * y.z; acc.w += w * y.w;
    }
    int c0 = (4 * j) & comask;
    float4 bb = *(const float4*)&bias[c0];
    acc.x += bb.x; acc.y += bb.y; acc.z += bb.z; acc.w += bb.w;
    acc.x = acc.x >= 0.f ? acc.x : LRELU_S * acc.x;
    acc.y = acc.y >= 0.f ? acc.y : LRELU_S * acc.y;
    acc.z = acc.z >= 0.f ? acc.z : LRELU_S * acc.z;
    acc.w = acc.w >= 0.f ? acc.w : LRELU_S * acc.w;
    if (OUTF == 0) {
        ((float4*)outf)[(size_t)v * R4 + j] = acc;
    } else {
        size_t o = (size_t)v * R4 * 4 + 4 * j;
        __nv_bfloat16 h[4], l[4];
        float vv[4] = {acc.x, acc.y, acc.z, acc.w};
#pragma unroll
        for (int e = 0; e < 4; e++) {
            h[e] = __float2bfloat16(vv[e]);
            l[e] = __float2bfloat16(vv[e] - __bfloat162float(h[e]));
        }
        *(uint2*)(outh + o) = *(uint2*)h;
        *(uint2*)(outl + o) = *(uint2*)l;
    }
}

__global__ void propF3_kernel(float* __restrict__ out, const float* __restrict__ U0,
                              const float* __restrict__ Y,
                              const float* __restrict__ bias, int nb) {
    int v = blockIdx.y;
    int p = blockIdx.x * blockDim.x + threadIdx.x;   // < 384
    float acc = U0[(size_t)v * 384 + p];
    int s = g_off[nb + v], t = g_off[nb + v + 1];
    for (int q = s; q < t; q++)
        acc += g_cw[q] * Y[(size_t)g_csrc[q] * 384 + p];
    out[(size_t)v * 384 + p] = acc + bias[p % 3];
}

__global__ void final_kernel(float* __restrict__ out, const float* __restrict__ h,
                             const void* __restrict__ perm) {
    int i = blockIdx.x * blockDim.x + threadIdx.x;
    const int TOT = 128 * 6890 * 3;
    if (i < TOT) {
        int b = i / (6890 * 3);
        int r = i - b * (6890 * 3);
        int u = r / 3;
        int k = r - u * 3;
        int v = read_idx(perm, u);
        out[i] = h[(size_t)(v * 128 + b) * 3 + k];
    }
}

// ---------------------------------------------------------------------------
extern "C" void kernel_launch(void* const* d_in, const int* in_sizes, int n_in,
                              void* d_out, int out_size) {
    const float* x   = (const float*)d_in[0];
    const float* fw1 = (const float*)d_in[1];
    const float* fb1 = (const float*)d_in[2];
    const float* fw2 = (const float*)d_in[3];
    const float* fb2 = (const float*)d_in[4];
    const float* W[5];
    const float* bb[5];
    for (int i = 0; i < 5; i++) {
        W[i]  = (const float*)d_in[5 + 2 * i];
        bb[i] = (const float*)d_in[6 + 2 * i];
    }
    const void* edges[4];
    for (int i = 0; i < 4; i++) edges[i] = d_in[15 + i];
    const void* perm = d_in[19];
    float* out = (float*)d_out;

    float *T, *OA, *YB, *H1, *WC;
    __nv_bfloat16 *AH, *AL, *WTH, *WTL, *W2H, *W2L, *H1H, *H1L;
    cudaGetSymbolAddress((void**)&T,   g_T);
    cudaGetSymbolAddress((void**)&OA,  g_outA);
    cudaGetSymbolAddress((void**)&YB,  g_Y);
    cudaGetSymbolAddress((void**)&H1,  g_h1);
    cudaGetSymbolAddress((void**)&WC,  g_wc);
    cudaGetSymbolAddress((void**)&AH,  g_Ah);
    cudaGetSymbolAddress((void**)&AL,  g_Al);
    cudaGetSymbolAddress((void**)&WTH, g_wth);
    cudaGetSymbolAddress((void**)&WTL, g_wtl);
    cudaGetSymbolAddress((void**)&W2H, g_w2h);
    cudaGetSymbolAddress((void**)&W2L, g_w2l);
    cudaGetSymbolAddress((void**)&H1H, g_h1h);
    cudaGetSymbolAddress((void**)&H1L, g_h1l);

    const int DSM = 2 * GBUF;   // 96KB double buffer
    cudaFuncSetAttribute(gemm_mmab<64, 0>,
                         cudaFuncAttributeMaxDynamicSharedMemorySize, DSM);
    cudaFuncSetAttribute(gemm_mmab<64, 1>,
                         cudaFuncAttributeMaxDynamicSharedMemorySize, DSM);
    cudaFuncSetAttribute(gemm_mmab<32, 0>,
                         cudaFuncAttributeMaxDynamicSharedMemorySize, DSM);

    const int ns[5]   = {864, 1728, 3456, 6912, 6912};
    const int cis[5]  = {128, 128, 64, 32, 16};
    const int cos_[5] = {128, 64, 32, 16, 3};
    const int col2[5] = {7, 6, 5, 4, 0};
    const int nbArr[5] = {0, 864, 2592, 6048, 6048};

    // 0: FC1 (SIMT)
    gemm_k<128, 128, 8, 8, 1><<<dim3(4, 1), 256>>>(x, fw1, fb1, H1,
                                                   128, 512, 128, 0, 0);
    // 1: split FC1 output
    hsplit_kernel<<<256, 256>>>(H1, H1H, H1L);
    // 2: transpose+split fc_w2 -> (N x K) bf16 hi/lo
    tsplit_kernel<<<dim3(110592 / 32, 512 / 32), dim3(32, 8)>>>(fw2, W2H, W2L);
    // 3: FC2 GEMM (pure bf16, double-buffered) — ncu capture target
    gemm_mmab<64, 1><<<dim3(110592 / 64, 1), 256, DSM>>>(
        H1H, H1L, W2H, W2L, fb2, nullptr, AH, AL, 128, 110592, 512, 0, 0);
    // 4: combined weights for layer 0
    wprep_kernel<<<(384 * 128 + 255) / 256, 256>>>(W[0], WC, WTH, WTL, 128, 128, 384);
    // 5: layer-0 ChebConv GEMM
    gemm_mmab<64, 0><<<dim3(6, 864), 256, DSM>>>(AH, AL, WTH, WTL, nullptr, T,
                                                 nullptr, nullptr,
                                                 110592, 384, 128, 7, 14155776LL);
    // 6: dtype sniff, then fused CSR build for all 4 graphs
    detect_kernel<<<1, 256>>>((const int*)edges[0], 5184);
    csr_zero_kernel<<<(12960 + 255) / 256, 256>>>();
    csr_count_kernel<<<dim3(162, 4), 256>>>(edges[0], edges[1], edges[2], edges[3]);
    csr_dinv_kernel<<<(12960 + 255) / 256, 256>>>();
    csr_scan_kernel<<<4, 1024>>>();
    csr_fill_kernel<<<dim3(162, 4), 256>>>(edges[0], edges[1], edges[2], edges[3]);

    for (int l = 0; l < 5; l++) {
        int n  = ns[l];
        int ci = cis[l];
        int co = cos_[l];
        int N  = 3 * co;
        int Np = ((N + 63) / 64) * 64;
        int ng = (l == 0 || l == 4) ? n : n / 2;   // layers 1-3 un-repeated
        int Mg = ng * 128;
        int shU = (l == 0 || l == 4) ? 0 : 1;
        int R4 = 32 * co;
        long long US = (long long)Mg * co;
        int nb = nbArr[l];

        if (l > 0) {
            wprep_kernel<<<(Np * ci + 255) / 256, 256>>>(W[l], WC, WTH, WTL,
                                                         ci, co, Np);
            if (l < 4) {   // mma path
                if (ci % 64 == 0)
                    gemm_mmab<64, 0><<<dim3(Np / 64, Mg / 128), 256, DSM>>>(
                        AH, AL, WTH, WTL, nullptr, T, nullptr, nullptr,
                        Mg, N, ci, col2[l], US);
                else
                    gemm_mmab<32, 0><<<dim3(Np / 64, Mg / 128), 256, DSM>>>(
                        AH, AL, WTH, WTL, nullptr, T, nullptr, nullptr,
                        Mg, N, ci, col2[l], US);
            } else {       // L4: K=16, SIMT
                gemm_k<256, 64, 16, 4, 3><<<dim3(1, Mg / 256), 256>>>(
                    OA, WC, nullptr, T, Mg, N, ci, co, US);
            }
        }

        // Y = U1' + 2*P*U2'
        propY_kernel<<<dim3(R4 >= 256 ? R4 / 256 : 1, n), R4 < 256 ? R4 : 256>>>(
            (float4*)YB, (const float4*)(T + US), (const float4*)(T + 2 * US),
            R4, shU, nb);
        // out = act(U0' + P*Y + b)
        if (l < 3) {
            propF_kernel<1><<<dim3(R4 / 256, n), 256>>>(
                nullptr, AH, AL, (const float4*)T, (const float4*)YB,
                bb[l], R4, co - 1, shU, nb);
        } else if (l == 3) {
            propF_kernel<0><<<dim3(R4 / 256, n), 256>>>(
                OA, nullptr, nullptr, (const float4*)T, (const float4*)YB,
                bb[l], R4, co - 1, shU, nb);
        } else {
            propF3_kernel<<<dim3(3, n), 128>>>(OA, T, YB, bb[4], nb);
        }
    }

    const int TOT = 128 * 6890 * 3;
    final_kernel<<<(TOT + 255) / 256, 256>>>(out, OA, perm);
}

// round 12
// speedup vs baseline: 7.2295x; 1.0099x over previous
#include <cuda_runtime.h>
#include <cuda_bf16.h>
#include <cstdint>

// ---------------------------------------------------------------------------
// ChebGcnDecoder, commuted form. All big GEMMs on mma.sync bf16 hi/lo 3-split
// with pre-split bf16 inputs, cp.async double-buffered smem, and (R12) a
// two-deep register pipeline: fragment loads for k-step kk+1 issue before the
// MMAs of kk, hiding LDSM latency under MMA issue.
// ---------------------------------------------------------------------------

#define LRELU_S 0.2f

__device__ float g_T[42467328];            // U0|U1|U2, stride Mg*co
__device__ float g_outA[14155776];         // fp32 layer output (l=3)
__device__ float g_Y[14155776];            // Y = U1 + 2*P*U2
__device__ __nv_bfloat16 g_Ah[14155776];   // bf16-hi GEMM input (activations)
__device__ __nv_bfloat16 g_Al[14155776];   // bf16-lo
__device__ __nv_bfloat16 g_w2h[56623104];  // fc_w2 transposed+split (N x K)
__device__ __nv_bfloat16 g_w2l[56623104];
__device__ float g_h1[65536];              // FC1 output 128x512 fp32
__device__ __nv_bfloat16 g_h1h[65536];
__device__ __nv_bfloat16 g_h1l[65536];
__device__ float g_wc[49152];              // combined weights fp32 (K x N), L4
__device__ __nv_bfloat16 g_wth[49152];     // combined weights bf16-hi (Np x K)
__device__ __nv_bfloat16 g_wtl[49152];
__device__ int   g_cnt[12960];
__device__ float g_dinv[12960];
__device__ int   g_off[12961];
__device__ int   g_cur[12960];
__device__ int   g_csrc[77760];
__device__ float g_cw[77760];
__device__ int   g_is64;

__constant__ int c_nb[4] = {0, 864, 2592, 6048};
__constant__ int c_eb[4] = {0, 5184, 15552, 36288};
__constant__ int c_nl[4] = {864, 1728, 3456, 6912};

// ---------------------------------------------------------------------------
__device__ __forceinline__ int read_idx(const void* p, int i) {
    if (g_is64) return (int)((const long long*)p)[i];
    return ((const int*)p)[i];
}

__global__ void detect_kernel(const int* w, int nwords) {
    __shared__ int any;
    if (threadIdx.x == 0) any = 0;
    __syncthreads();
    int a = 0;
    for (int i = 1 + 2 * (int)threadIdx.x; i < nwords; i += 2 * blockDim.x) a |= w[i];
    if (a) atomicOr(&any, 1);
    __syncthreads();
    if (threadIdx.x == 0) g_is64 = any ? 0 : 1;
}

// ---- fused CSR build over all 4 graphs ----
__global__ void csr_zero_kernel() {
    int i = blockIdx.x * blockDim.x + threadIdx.x;
    if (i < 12960) g_cnt[i] = 0;
}

__global__ void csr_count_kernel(const void* e0, const void* e1,
                                 const void* e2, const void* e3) {
    int l = blockIdx.y;
    const void* eg = (l == 0) ? e0 : (l == 1) ? e1 : (l == 2) ? e2 : e3;
    int e = 6 * c_nl[l];
    int i = blockIdx.x * blockDim.x + threadIdx.x;
    if (i < e) atomicAdd(&g_cnt[c_nb[l] + read_idx(eg, e + i)], 1);
}

__global__ void csr_dinv_kernel() {
    int i = blockIdx.x * blockDim.x + threadIdx.x;
    if (i < 12960) g_dinv[i] = (g_cnt[i] > 0) ? rsqrtf((float)g_cnt[i]) : 0.0f;
}

__global__ void csr_scan_kernel() {
    __shared__ int partial[1024];
    int l = blockIdx.x;
    int n = c_nl[l], nb = c_nb[l], eb = c_eb[l];
    int tid = threadIdx.x;
    int C = (n + 1023) / 1024;
    int start = tid * C;
    int local[8];
    int s = 0;
    for (int i = 0; i < C; i++) {
        int idx = start + i;
        int v = (idx < n) ? g_cnt[nb + idx] : 0;
        local[i] = s;
        s += v;
    }
    partial[tid] = s;
    __syncthreads();
    for (int d = 1; d < 1024; d <<= 1) {
        int t = (tid >= d) ? partial[tid - d] : 0;
        __syncthreads();
        if (tid >= d) partial[tid] += t;
        __syncthreads();
    }
    int base = (tid > 0) ? partial[tid - 1] : 0;
    for (int i = 0; i < C; i++) {
        int idx = start + i;
        if (idx < n) {
            int o = eb + base + local[i];
            g_off[nb + idx] = o;
            g_cur[nb + idx] = o;
        }
    }
    if (l == 3 && tid == 1023) g_off[12960] = 77760;
}

__global__ void csr_fill_kernel(const void* e0, const void* e1,
                                const void* e2, const void* e3) {
    int l = blockIdx.y;
    const void* eg = (l == 0) ? e0 : (l == 1) ? e1 : (l == 2) ? e2 : e3;
    int e = 6 * c_nl[l];
    int nb = c_nb[l];
    int i = blockIdx.x * blockDim.x + threadIdx.x;
    if (i < e) {
        int s = read_idx(eg, i);
        int d = read_idx(eg, e + i);
        int p = atomicAdd(&g_cur[nb + d], 1);
        g_csrc[p] = s;
        g_cw[p] = -g_dinv[nb + s] * g_dinv[nb + d];
    }
}

// Combined weights [W0-W2 | W1 | W2]: fp32 (K x N) for SIMT L4, bf16 hi/lo
// transposed (Np x K) for the mma path. Factor 2 on P^2 applied in props.
__global__ void wprep_kernel(const float* __restrict__ W,
                             float* __restrict__ Wc,
                             __nv_bfloat16* __restrict__ Wth,
                             __nv_bfloat16* __restrict__ Wtl,
                             int ci, int co, int Np) {
    int i = blockIdx.x * blockDim.x + threadIdx.x;
    int N = 3 * co;
    if (i >= Np * ci) return;
    int n = i / ci, k = i - n * ci;
    int cico = ci * co;
    float v = 0.f;
    if (n < N) {
        if (n < co)            v = W[k * co + n] - W[2 * cico + k * co + n];
        else if (n < 2 * co)   v = W[cico + k * co + (n - co)];
        else                   v = W[2 * cico + k * co + (n - 2 * co)];
        Wc[k * N + n] = v;
    }
    __nv_bfloat16 h = __float2bfloat16(v);
    Wth[n * ci + k] = h;
    Wtl[n * ci + k] = __float2bfloat16(v - __bfloat162float(h));
}

// fc_w2 (K=512 x N=110592) fp32 -> transposed (N x K) bf16 hi/lo.
__global__ void tsplit_kernel(const float* __restrict__ in,
                              __nv_bfloat16* __restrict__ outh,
                              __nv_bfloat16* __restrict__ outl) {
    __shared__ float t[32][33];
    const int N = 110592, K = 512;
    int n0 = blockIdx.x * 32, k0 = blockIdx.y * 32;
    int tx = threadIdx.x, ty = threadIdx.y;
#pragma unroll
    for (int i = 0; i < 4; i++)
        t[ty + 8 * i][tx] = in[(size_t)(k0 + ty + 8 * i) * N + n0 + tx];
    __syncthreads();
#pragma unroll
    for (int i = 0; i < 4; i++) {
        float v = t[tx][ty + 8 * i];
        __nv_bfloat16 h = __float2bfloat16(v);
        size_t o = (size_t)(n0 + ty + 8 * i) * K + k0 + tx;
        outh[o] = h;
        outl[o] = __float2bfloat16(v - __bfloat162float(h));
    }
}

// split FC1 output (128x512) into bf16 hi/lo
__global__ void hsplit_kernel(const float* __restrict__ in,
                              __nv_bfloat16* __restrict__ outh,
                              __nv_bfloat16* __restrict__ outl) {
    int i = blockIdx.x * blockDim.x + threadIdx.x;
    if (i < 65536) {
        float v = in[i];
        __nv_bfloat16 h = __float2bfloat16(v);
        outh[i] = h;
        outl[i] = __float2bfloat16(v - __bfloat162float(h));
    }
}

// ---------------------------------------------------------------------------
__device__ __forceinline__ uint32_t smem_u32(const void* p) {
    uint32_t a;
    asm("{ .reg .u64 t; cvta.to.shared.u64 t, %1; cvt.u32.u64 %0, t; }"
        : "=r"(a) : "l"(p));
    return a;
}

__device__ __forceinline__ void cp_async16(uint32_t dst, const void* src) {
    asm volatile("cp.async.cg.shared.global [%0], [%1], 16;"
                 :: "r"(dst), "l"(src));
}

#define LDSM_X4(r0, r1, r2, r3, a)                                            \
    asm volatile("ldmatrix.sync.aligned.m8n8.x4.shared.b16 {%0,%1,%2,%3}, [%4];" \
        : "=r"(r0), "=r"(r1), "=r"(r2), "=r"(r3) : "r"(a))

#define MMA4(c, a, b0, b1)                                                    \
    asm volatile(                                                             \
        "mma.sync.aligned.m16n8k16.row.col.f32.bf16.bf16.f32 "                \
        "{%0,%1,%2,%3}, {%4,%5,%6,%7}, {%8,%9}, {%0,%1,%2,%3};\n"             \
        : "+f"((c)[0]), "+f"((c)[1]), "+f"((c)[2]), "+f"((c)[3])              \
        : "r"((a)[0]), "r"((a)[1]), "r"((a)[2]), "r"((a)[3]),                 \
          "r"(b0), "r"(b1))

// ---------------------------------------------------------------------------
// bf16-input tensor GEMM, cp.async double-buffered smem + 2-deep register
// pipeline over k-steps. C(MxN) = A(MxK)@Wt^T. Wt is (Np x K) row-major.
// BM=128, BN=64, KC chunk. Per-buffer SW128 layout: Ah 16K|Al 16K|Bh 8K|Bl 8K.
// EPI 0: split write into U0|U1|U2 (t = n>>coLog2) at out + t*ustr (fp32).
// EPI 1: FC2: bias add, bf16 hi/lo split write to (node,batch,ch) layout.
// ---------------------------------------------------------------------------
#define GBUF 49152

template<int KC, int EPI>
__global__ __launch_bounds__(256)
void gemm_mmab(const __nv_bfloat16* __restrict__ Ah, const __nv_bfloat16* __restrict__ Al,
               const __nv_bfloat16* __restrict__ Wh, const __nv_bfloat16* __restrict__ Wl,
               const float* __restrict__ bias, float* __restrict__ out,
               __nv_bfloat16* __restrict__ outh, __nv_bfloat16* __restrict__ outl,
               int M, int N, int K, int coLog2, long long ustr) {
    extern __shared__ __align__(128) uint8_t smdyn[];
    const uint32_t sb = smem_u32(smdyn);
    const uint32_t oAh = 0, oAl = 16384, oBh = 32768, oBl = 40960;

    const int tid = threadIdx.x, lane = tid & 31, warp = tid >> 5;
    const int wm = warp & 3, wn = warp >> 2;
    const int m0 = blockIdx.y * 128, n0 = blockIdx.x * 64;

    float acc[2][4][4];
#pragma unroll
    for (int i = 0; i < 2; i++)
#pragma unroll
        for (int j = 0; j < 4; j++)
#pragma unroll
            for (int q = 0; q < 4; q++) acc[i][j][q] = 0.f;

    const uint32_t lq = lane >> 3, lr = lane & 7;
    const uint32_t qk = (lq >> 1) << 4;
    uint32_t aoff[2], asw[2], boff[2], bsw[2];
#pragma unroll
    for (int mt = 0; mt < 2; mt++) {
        int row = wm * 32 + mt * 16 + ((lq & 1) << 3) + lr;
        aoff[mt] = (uint32_t)row * 128;
        asw[mt] = (uint32_t)((row & 7) << 4);
    }
#pragma unroll
    for (int nt = 0; nt < 2; nt++) {
        int row = wn * 32 + nt * 16 + ((lq & 1) << 3) + lr;
        boff[nt] = (uint32_t)row * 128;
        bsw[nt] = (uint32_t)((row & 7) << 4);
    }

    constexpr int RPR = KC / 8;              // 16B chunks per row
    const int nstages = K / KC;

#define PREFETCH(S, BUF) do {                                                 \
        int k0_ = (S) * KC;                                                   \
        uint32_t bo_ = sb + (BUF) * GBUF;                                     \
        _Pragma("unroll")                                                     \
        for (int r = 0; r < KC / 16; r++) {                                   \
            int idx = r * 256 + tid;                                          \
            int row = idx / RPR, c8 = idx % RPR;                              \
            size_t go = (size_t)(m0 + row) * K + k0_ + c8 * 8;                \
            uint32_t so = (uint32_t)row * 128 +                               \
                          (((uint32_t)c8 * 16) ^ ((row & 7) << 4));           \
            cp_async16(bo_ + oAh + so, Ah + go);                              \
            cp_async16(bo_ + oAl + so, Al + go);                              \
        }                                                                     \
        _Pragma("unroll")                                                     \
        for (int r = 0; r < KC / 32; r++) {                                   \
            int idx = r * 256 + tid;                                          \
            int row = idx / RPR, c8 = idx % RPR;                              \
            size_t go = (size_t)(n0 + row) * K + k0_ + c8 * 8;                \
            uint32_t so = (uint32_t)row * 128 +                               \
                          (((uint32_t)c8 * 16) ^ ((row & 7) << 4));           \
            cp_async16(bo_ + oBh + so, Wh + go);                              \
            cp_async16(bo_ + oBl + so, Wl + go);                              \
        }                                                                     \
        asm volatile("cp.async.commit_group;" ::: "memory");                  \
    } while (0)

    // fragment banks: [pipeline slot][tile][frag]
    uint32_t ah[2][2][4], al[2][2][4], bh[2][2][4], bl[2][2][4];

#define LOADFRAG(PK, KK, BO) do {                                             \
        uint32_t cb_ = ((uint32_t)(KK) << 5) + qk;                            \
        _Pragma("unroll")                                                     \
        for (int mt = 0; mt < 2; mt++) {                                      \
            uint32_t ad = (BO) + oAh + aoff[mt] + (cb_ ^ asw[mt]);            \
            LDSM_X4(ah[PK][mt][0], ah[PK][mt][1], ah[PK][mt][2], ah[PK][mt][3], ad); \
            LDSM_X4(al[PK][mt][0], al[PK][mt][1], al[PK][mt][2], al[PK][mt][3], ad + 16384); \
        }                                                                     \
        _Pragma("unroll")                                                     \
        for (int nt = 0; nt < 2; nt++) {                                      \
            uint32_t bd = (BO) + oBh + boff[nt] + (cb_ ^ bsw[nt]);            \
            LDSM_X4(bh[PK][nt][0], bh[PK][nt][1], bh[PK][nt][2], bh[PK][nt][3], bd); \
            LDSM_X4(bl[PK][nt][0], bl[PK][nt][1], bl[PK][nt][2], bl[PK][nt][3], bd + 8192); \
        }                                                                     \
    } while (0)

    PREFETCH(0, 0);

    for (int s = 0; s < nstages; s++) {
        int buf = s & 1;
        if (s + 1 < nstages) {
            PREFETCH(s + 1, buf ^ 1);
            asm volatile("cp.async.wait_group 1;" ::: "memory");
        } else {
            asm volatile("cp.async.wait_group 0;" ::: "memory");
        }
        __syncthreads();

        uint32_t bo = sb + buf * GBUF;
        LOADFRAG(0, 0, bo);
#pragma unroll
        for (int kk = 0; kk < KC / 16; kk++) {
            int pk = kk & 1;
            if (kk + 1 < KC / 16) LOADFRAG(pk ^ 1, kk + 1, bo);
#pragma unroll
            for (int mt = 0; mt < 2; mt++)
#pragma unroll
                for (int nt = 0; nt < 2; nt++)
#pragma unroll
                    for (int u = 0; u < 2; u++) {
                        int nf = nt * 2 + u;
                        MMA4(acc[mt][nf], ah[pk][mt], bh[pk][nt][u], bh[pk][nt][u + 2]);
                        MMA4(acc[mt][nf], ah[pk][mt], bl[pk][nt][u], bl[pk][nt][u + 2]);
                        MMA4(acc[mt][nf], al[pk][mt], bh[pk][nt][u], bh[pk][nt][u + 2]);
                    }
        }
        __syncthreads();
    }
#undef PREFETCH
#undef LOADFRAG

#pragma unroll
    for (int mt = 0; mt < 2; mt++)
#pragma unroll
        for (int nf = 0; nf < 4; nf++) {
            int mrow = m0 + wm * 32 + mt * 16 + (lane >> 2);
            int ncol = n0 + wn * 32 + (nf >> 1) * 16 + (nf & 1) * 8 + 2 * (lane & 3);
#pragma unroll
            for (int e = 0; e < 4; e++) {
                int m = mrow + (e >> 1) * 8;
                int n = ncol + (e & 1);
                if (n >= N) continue;
                if (EPI == 0) {
                    int t = n >> coLog2;
                    int cc = n & ((1 << coLog2) - 1);
                    out[(size_t)t * (size_t)ustr + ((size_t)m << coLog2) + cc] =
                        acc[mt][nf][e];
                } else {
                    float v = acc[mt][nf][e] + bias[n];
                    __nv_bfloat16 h = __float2bfloat16(v);
                    size_t o = (size_t)((n >> 7) * 128 + m) * 128 + (n & 127);
                    outh[o] = h;
                    outl[o] = __float2bfloat16(v - __bfloat162float(h));
                }
            }
        }
}

// ---------------------------------------------------------------------------
// SIMT fp32 GEMM for FC1 (MODE 1) and L4 (MODE 3).
// ---------------------------------------------------------------------------
template<int BM, int BN, int TM, int TN, int MODE>
__global__ __launch_bounds__(256)
void gemm_k(const float* __restrict__ A, const float* __restrict__ W,
            const float* __restrict__ bias, float* __restrict__ out,
            int M, int N, int K, int co, long long ustr) {
    __shared__ float As[16][BM + 4];
    __shared__ float Ws[16][BN + 4];
    const int tid = threadIdx.x;
    const int tx = tid & 15, ty = tid >> 4;
    const int m0 = blockIdx.y * BM, n0 = blockIdx.x * BN;

    float acc[TM][TN];
#pragma unroll
    for (int i = 0; i < TM; i++)
#pragma unroll
        for (int j = 0; j < TN; j++) acc[i][j] = 0.0f;

    for (int k0 = 0; k0 < K; k0 += 16) {
#pragma unroll
        for (int r = 0; r < BM / 64; r++) {
            int lid = tid + r * 256;
            int row = lid >> 2;
            int kq = (lid & 3) << 2;
            float4 a = *(const float4*)(A + (size_t)(m0 + row) * K + (k0 + kq));
            As[kq + 0][row] = a.x;
            As[kq + 1][row] = a.y;
            As[kq + 2][row] = a.z;
            As[kq + 3][row] = a.w;
        }
#pragma unroll
        for (int r = 0; r < BN / 64; r++) {
            int lid = tid + r * 256;
            int k = lid / (BN / 4);
            int n4 = (lid % (BN / 4)) * 4;
            int gc = n0 + n4;
            float4 w;
            if (((N & 3) == 0) && gc + 4 <= N) {
                w = *(const float4*)(W + (size_t)(k0 + k) * N + gc);
            } else {
                w.x = (gc + 0 < N) ? W[(size_t)(k0 + k) * N + gc + 0] : 0.f;
                w.y = (gc + 1 < N) ? W[(size_t)(k0 + k) * N + gc + 1] : 0.f;
                w.z = (gc + 2 < N) ? W[(size_t)(k0 + k) * N + gc + 2] : 0.f;
                w.w = (gc + 3 < N) ? W[(size_t)(k0 + k) * N + gc + 3] : 0.f;
            }
            *(float4*)&Ws[k][n4] = w;
        }
        __syncthreads();

#pragma unroll
        for (int k = 0; k < 16; k++) {
            float a[TM], w[TN];
#pragma unroll
            for (int i = 0; i < TM / 4; i++)
                *(float4*)&a[4 * i] = *(const float4*)&As[k][ty * TM + 4 * i];
#pragma unroll
            for (int j = 0; j < TN / 4; j++)
                *(float4*)&w[4 * j] = *(const float4*)&Ws[k][tx * TN + 4 * j];
#pragma unroll
            for (int i = 0; i < TM; i++)
#pragma unroll
                for (int j = 0; j < TN; j++) acc[i][j] += a[i] * w[j];
        }
        __syncthreads();
    }

#pragma unroll
    for (int i = 0; i < TM; i++) {
        int m = m0 + ty * TM + i;
#pragma unroll
        for (int j = 0; j < TN; j++) {
            int n = n0 + tx * TN + j;
            if (n >= N) continue;
            float v = acc[i][j];
            if (MODE == 1) {
                v += bias[n];
                v = v > 0.f ? v : 0.f;
                out[(size_t)m * N + n] = v;
            } else {
                int t = n / co;
                out[(size_t)t * (size_t)ustr + (size_t)m * co + (n - t * co)] = v;
            }
        }
    }
}

// ---------------------------------------------------------------------------
// Props (CSR slice selected by nb):
//   Y[v] = U1[v>>shU] + 2 * sum_e w * U2[src>>shU]
//   out[v] = act( U0[v>>shU] + sum_e w * Y[src] + bias )
// ---------------------------------------------------------------------------
__global__ void propY_kernel(float4* __restrict__ Y, const float4* __restrict__ U1,
                             const float4* __restrict__ U2, int R4, int shU, int nb) {
    int v = blockIdx.y;
    int j = blockIdx.x * blockDim.x + threadIdx.x;
    float4 acc = make_float4(0.f, 0.f, 0.f, 0.f);
    int s = g_off[nb + v], t = g_off[nb + v + 1];
    for (int q = s; q < t; q++) {
        float w = g_cw[q];
        float4 x = U2[(size_t)(g_csrc[q] >> shU) * R4 + j];
        acc.x += w * x.x; acc.y += w * x.y; acc.z += w * x.z; acc.w += w * x.w;
    }
    float4 u1 = U1[(size_t)(v >> shU) * R4 + j];
    acc.x = u1.x + 2.f * acc.x;
    acc.y = u1.y + 2.f * acc.y;
    acc.z = u1.z + 2.f * acc.z;
    acc.w = u1.w + 2.f * acc.w;
    Y[(size_t)v * R4 + j] = acc;
}

// OUTF: 0 -> fp32 out; 1 -> bf16 hi/lo split (feeds next mma GEMM)
template<int OUTF>
__global__ void propF_kernel(float* __restrict__ outf,
                             __nv_bfloat16* __restrict__ outh,
                             __nv_bfloat16* __restrict__ outl,
                             const float4* __restrict__ U0, const float4* __restrict__ Y,
                             const float* __restrict__ bias, int R4, int comask,
                             int shU, int nb) {
    int v = blockIdx.y;
    int j = blockIdx.x * blockDim.x + threadIdx.x;
    float4 acc = U0[(size_t)(v >> shU) * R4 + j];
    int s = g_off[nb + v], t = g_off[nb + v + 1];
    for (int q = s; q < t; q++) {
        float w = g_cw[q];
        float4 y = Y[(size_t)g_csrc[q] * R4 + j];
        acc.x += w * y.x; acc.y += w * y.y; acc.z += w * y.z; acc.w += w * y.w;
    }
    int c0 = (4 * j) & comask;
    float4 bb = *(const float4*)&bias[c0];
    acc.x += bb.x; acc.y += bb.y; acc.z += bb.z; acc.w += bb.w;
    acc.x = acc.x >= 0.f ? acc.x : LRELU_S * acc.x;
    acc.y = acc.y >= 0.f ? acc.y : LRELU_S * acc.y;
    acc.z = acc.z >= 0.f ? acc.z : LRELU_S * acc.z;
    acc.w = acc.w >= 0.f ? acc.w : LRELU_S * acc.w;
    if (OUTF == 0) {
        ((float4*)outf)[(size_t)v * R4 + j] = acc;
    } else {
        size_t o = (size_t)v * R4 * 4 + 4 * j;
        __nv_bfloat16 h[4], l[4];
        float vv[4] = {acc.x, acc.y, acc.z, acc.w};
#pragma unroll
        for (int e = 0; e < 4; e++) {
            h[e] = __float2bfloat16(vv[e]);
            l[e] = __float2bfloat16(vv[e] - __bfloat162float(h[e]));
        }
        *(uint2*)(outh + o) = *(uint2*)h;
        *(uint2*)(outl + o) = *(uint2*)l;
    }
}

__global__ void propF3_kernel(float* __restrict__ out, const float* __restrict__ U0,
                              const float* __restrict__ Y,
                              const float* __restrict__ bias, int nb) {
    int v = blockIdx.y;
    int p = blockIdx.x * blockDim.x + threadIdx.x;   // < 384
    float acc = U0[(size_t)v * 384 + p];
    int s = g_off[nb + v], t = g_off[nb + v + 1];
    for (int q = s; q < t; q++)
        acc += g_cw[q] * Y[(size_t)g_csrc[q] * 384 + p];
    out[(size_t)v * 384 + p] = acc + bias[p % 3];
}

__global__ void final_kernel(float* __restrict__ out, const float* __restrict__ h,
                             const void* __restrict__ perm) {
    int i = blockIdx.x * blockDim.x + threadIdx.x;
    const int TOT = 128 * 6890 * 3;
    if (i < TOT) {
        int b = i / (6890 * 3);
        int r = i - b * (6890 * 3);
        int u = r / 3;
        int k = r - u * 3;
        int v = read_idx(perm, u);
        out[i] = h[(size_t)(v * 128 + b) * 3 + k];
    }
}

// ---------------------------------------------------------------------------
extern "C" void kernel_launch(void* const* d_in, const int* in_sizes, int n_in,
                              void* d_out, int out_size) {
    const float* x   = (const float*)d_in[0];
    const float* fw1 = (const float*)d_in[1];
    const float* fb1 = (const float*)d_in[2];
    const float* fw2 = (const float*)d_in[3];
    const float* fb2 = (const float*)d_in[4];
    const float* W[5];
    const float* bb[5];
    for (int i = 0; i < 5; i++) {
        W[i]  = (const float*)d_in[5 + 2 * i];
        bb[i] = (const float*)d_in[6 + 2 * i];
    }
    const void* edges[4];
    for (int i = 0; i < 4; i++) edges[i] = d_in[15 + i];
    const void* perm = d_in[19];
    float* out = (float*)d_out;

    float *T, *OA, *YB, *H1, *WC;
    __nv_bfloat16 *AH, *AL, *WTH, *WTL, *W2H, *W2L, *H1H, *H1L;
    cudaGetSymbolAddress((void**)&T,   g_T);
    cudaGetSymbolAddress((void**)&OA,  g_outA);
    cudaGetSymbolAddress((void**)&YB,  g_Y);
    cudaGetSymbolAddress((void**)&H1,  g_h1);
    cudaGetSymbolAddress((void**)&WC,  g_wc);
    cudaGetSymbolAddress((void**)&AH,  g_Ah);
    cudaGetSymbolAddress((void**)&AL,  g_Al);
    cudaGetSymbolAddress((void**)&WTH, g_wth);
    cudaGetSymbolAddress((void**)&WTL, g_wtl);
    cudaGetSymbolAddress((void**)&W2H, g_w2h);
    cudaGetSymbolAddress((void**)&W2L, g_w2l);
    cudaGetSymbolAddress((void**)&H1H, g_h1h);
    cudaGetSymbolAddress((void**)&H1L, g_h1l);

    const int DSM = 2 * GBUF;   // 96KB double buffer
    cudaFuncSetAttribute(gemm_mmab<64, 0>,
                         cudaFuncAttributeMaxDynamicSharedMemorySize, DSM);
    cudaFuncSetAttribute(gemm_mmab<64, 1>,
                         cudaFuncAttributeMaxDynamicSharedMemorySize, DSM);
    cudaFuncSetAttribute(gemm_mmab<32, 0>,
                         cudaFuncAttributeMaxDynamicSharedMemorySize, DSM);

    const int ns[5]   = {864, 1728, 3456, 6912, 6912};
    const int cis[5]  = {128, 128, 64, 32, 16};
    const int cos_[5] = {128, 64, 32, 16, 3};
    const int col2[5] = {7, 6, 5, 4, 0};
    const int nbArr[5] = {0, 864, 2592, 6048, 6048};

    // 0: FC1 (SIMT)
    gemm_k<128, 128, 8, 8, 1><<<dim3(4, 1), 256>>>(x, fw1, fb1, H1,
                                                   128, 512, 128, 0, 0);
    // 1: split FC1 output
    hsplit_kernel<<<256, 256>>>(H1, H1H, H1L);
    // 2: transpose+split fc_w2 -> (N x K) bf16 hi/lo
    tsplit_kernel<<<dim3(110592 / 32, 512 / 32), dim3(32, 8)>>>(fw2, W2H, W2L);
    // 3: FC2 GEMM (pure bf16, double-buffered, reg-pipelined) — ncu target
    gemm_mmab<64, 1><<<dim3(110592 / 64, 1), 256, DSM>>>(
        H1H, H1L, W2H, W2L, fb2, nullptr, AH, AL, 128, 110592, 512, 0, 0);
    // 4: combined weights for layer 0
    wprep_kernel<<<(384 * 128 + 255) / 256, 256>>>(W[0], WC, WTH, WTL, 128, 128, 384);
    // 5: layer-0 ChebConv GEMM
    gemm_mmab<64, 0><<<dim3(6, 864), 256, DSM>>>(AH, AL, WTH, WTL, nullptr, T,
                                                 nullptr, nullptr,
                                                 110592, 384, 128, 7, 14155776LL);
    // 6: dtype sniff, then fused CSR build for all 4 graphs
    detect_kernel<<<1, 256>>>((const int*)edges[0], 5184);
    csr_zero_kernel<<<(12960 + 255) / 256, 256>>>();
    csr_count_kernel<<<dim3(162, 4), 256>>>(edges[0], edges[1], edges[2], edges[3]);
    csr_dinv_kernel<<<(12960 + 255) / 256, 256>>>();
    csr_scan_kernel<<<4, 1024>>>();
    csr_fill_kernel<<<dim3(162, 4), 256>>>(edges[0], edges[1], edges[2], edges[3]);

    for (int l = 0; l < 5; l++) {
        int n  = ns[l];
        int ci = cis[l];
        int co = cos_[l];
        int N  = 3 * co;
        int Np = ((N + 63) / 64) * 64;
        int ng = (l == 0 || l == 4) ? n : n / 2;   // layers 1-3 un-repeated
        int Mg = ng * 128;
        int shU = (l == 0 || l == 4) ? 0 : 1;
        int R4 = 32 * co;
        long long US = (long long)Mg * co;
        int nb = nbArr[l];

        if (l > 0) {
            wprep_kernel<<<(Np * ci + 255) / 256, 256>>>(W[l], WC, WTH, WTL,
                                                         ci, co, Np);
            if (l < 4) {   // mma path
                if (ci % 64 == 0)
                    gemm_mmab<64, 0><<<dim3(Np / 64, Mg / 128), 256, DSM>>>(
                        AH, AL, WTH, WTL, nullptr, T, nullptr, nullptr,
                        Mg, N, ci, col2[l], US);
                else
                    gemm_mmab<32, 0><<<dim3(Np / 64, Mg / 128), 256, DSM>>>(
                        AH, AL, WTH, WTL, nullptr, T, nullptr, nullptr,
                        Mg, N, ci, col2[l], US);
            } else {       // L4: K=16, SIMT
                gemm_k<256, 64, 16, 4, 3><<<dim3(1, Mg / 256), 256>>>(
                    OA, WC, nullptr, T, Mg, N, ci, co, US);
            }
        }

        // Y = U1' + 2*P*U2'
        propY_kernel<<<dim3(R4 >= 256 ? R4 / 256 : 1, n), R4 < 256 ? R4 : 256>>>(
            (float4*)YB, (const float4*)(T + US), (const float4*)(T + 2 * US),
            R4, shU, nb);
        // out = act(U0' + P*Y + b)
        if (l < 3) {
            propF_kernel<1><<<dim3(R4 / 256, n), 256>>>(
                nullptr, AH, AL, (const float4*)T, (const float4*)YB,
                bb[l], R4, co - 1, shU, nb);
        } else if (l == 3) {
            propF_kernel<0><<<dim3(R4 / 256, n), 256>>>(
                OA, nullptr, nullptr, (const float4*)T, (const float4*)YB,
                bb[l], R4, co - 1, shU, nb);
        } else {
            propF3_kernel<<<dim3(3, n), 128>>>(OA, T, YB, bb[4], nb);
        }
    }

    const int TOT = 128 * 6890 * 3;
    final_kernel<<<(TOT + 255) / 256, 256>>>(out, OA, perm);
}